// round 1
// baseline (speedup 1.0000x reference)
#include <cuda_runtime.h>

// ---------------------------------------------------------------------------
// BigramModel forward: 3-layer transformer, D=64, H=8, HD=8, DF=256, V=65
// B=4096, T=128 -> NTOK = 524288 tokens.
// Output assumed: logits [NTOK*65] (fp32) followed by scalar loss.
// ---------------------------------------------------------------------------

#define NTOK (4096 * 128)
#define TSEQ 128
#define DMODEL 64
#define NVOCAB 65
#define NHEAD 8
#define DFF 256
#define NLAYER 3

// Scratch (device globals: allocation-free per harness rules)
__device__ float g_x[(size_t)NTOK * DMODEL];
__device__ float g_xn[(size_t)NTOK * DMODEL];
__device__ float g_q[(size_t)NTOK * DMODEL];
__device__ float g_k[(size_t)NTOK * DMODEL];
__device__ float g_v[(size_t)NTOK * DMODEL];
__device__ float g_h1[(size_t)NTOK * DFF];
__device__ float g_logits[(size_t)NTOK * NVOCAB];
__device__ float g_tokloss[NTOK];

// ---------------------------------------------------------------------------
// Embedding: x[n] = tok_emb[idx[n]] + pos_emb[n % T]
// ---------------------------------------------------------------------------
__global__ void embed_kernel(const int* __restrict__ idx,
                             const float4* __restrict__ te,
                             const float4* __restrict__ pe,
                             float4* __restrict__ x) {
    long i = (long)blockIdx.x * blockDim.x + threadIdx.x;
    if (i >= (long)NTOK * 16) return;
    long tok = i >> 4;
    int d4 = (int)(i & 15);
    int id = idx[tok];
    int t = (int)(tok & (TSEQ - 1));
    float4 a = te[(long)id * 16 + d4];
    float4 p = pe[(long)t * 16 + d4];
    float4 r;
    r.x = a.x + p.x; r.y = a.y + p.y; r.z = a.z + p.z; r.w = a.w + p.w;
    x[i] = r;
}

// ---------------------------------------------------------------------------
// LayerNorm over D=64: one token per warp (lane holds 2 elements)
// ---------------------------------------------------------------------------
__global__ void ln_kernel(const float* __restrict__ x,
                          const float* __restrict__ g,
                          const float* __restrict__ b,
                          float* __restrict__ out) {
    long tok = ((long)blockIdx.x * blockDim.x + threadIdx.x) >> 5;
    int lane = threadIdx.x & 31;
    const float* row = x + tok * DMODEL;
    float a0 = row[lane];
    float a1 = row[lane + 32];
    float s = a0 + a1;
#pragma unroll
    for (int o = 16; o; o >>= 1) s += __shfl_xor_sync(0xffffffffu, s, o);
    float mu = s * (1.0f / 64.0f);
    float d0 = a0 - mu, d1 = a1 - mu;
    float vs = d0 * d0 + d1 * d1;
#pragma unroll
    for (int o = 16; o; o >>= 1) vs += __shfl_xor_sync(0xffffffffu, vs, o);
    float inv = rsqrtf(vs * (1.0f / 64.0f) + 1e-5f);
    out[tok * DMODEL + lane]      = d0 * inv * g[lane]      + b[lane];
    out[tok * DMODEL + lane + 32] = d1 * inv * g[lane + 32] + b[lane + 32];
}

// ---------------------------------------------------------------------------
// GEMM: out[M,NCOLS] = A[M,KDIM] @ W[KDIM,NCOLS] (+bias)(relu)(+res)
// Block tile 128x64, 256 threads, 8x4 register tile.
// A-tile stored transposed in smem with XOR swizzle (conflict-free both ways).
// ---------------------------------------------------------------------------
template <int KDIM, int NCOLS, bool RELU, bool RES>
__global__ __launch_bounds__(256) void gemm_kernel(
    const float* __restrict__ A, const float* __restrict__ W,
    const float* __restrict__ bias, const float* __restrict__ res,
    float* __restrict__ out) {
    __shared__ float4 As[64][32];   // As[k][m4-swizzled] : 32 KB
    __shared__ float4 Ws[64][16];   // Ws[k][n4]          : 16 KB
    float* Af = reinterpret_cast<float*>(As);

    const int tid = threadIdx.x;
    const int tx = tid & 15;        // output col group (4 cols)
    const int ty = tid >> 4;        // output row group
    const long row0 = (long)blockIdx.x * 128;
    const int col0 = blockIdx.y * 64;

    float acc[8][4];
#pragma unroll
    for (int i = 0; i < 8; i++)
#pragma unroll
        for (int j = 0; j < 4; j++) acc[i][j] = 0.0f;

    const int am = tid & 15;          // A-load: row within 16-row group
    const int ak = (tid >> 4) * 4;    // A-load: k offset (float4)
    const int wk = tid >> 4;          // W-load: k row
    const int wn = tid & 15;          // W-load: n4 group

    for (int kc = 0; kc < KDIM; kc += 64) {
        // ---- load A tile, transpose into swizzled smem -------------------
#pragma unroll
        for (int i = 0; i < 8; i++) {
            int mm = am + i * 16;
            const float4 av =
                *reinterpret_cast<const float4*>(A + (row0 + mm) * KDIM + kc + ak);
            int m4 = mm >> 2, mi = mm & 3;
            float vals[4] = {av.x, av.y, av.z, av.w};
#pragma unroll
            for (int j = 0; j < 4; j++) {
                int kq = ak + j;
                Af[(size_t)kq * 128 + ((m4 ^ (kq & 31)) << 2) + mi] = vals[j];
            }
        }
        // ---- load W tile -------------------------------------------------
#pragma unroll
        for (int i = 0; i < 4; i++) {
            int kr = wk + i * 16;
            Ws[kr][wn] = *reinterpret_cast<const float4*>(
                W + (long)(kc + kr) * NCOLS + col0 + wn * 4);
        }
        __syncthreads();

        // ---- compute -------------------------------------------------------
#pragma unroll 8
        for (int k = 0; k < 64; k++) {
            const float4 a0 = As[k][(ty) ^ (k & 31)];
            const float4 a1 = As[k][(ty + 16) ^ (k & 31)];
            const float4 bw = Ws[k][tx];
            const float av[8] = {a0.x, a0.y, a0.z, a0.w, a1.x, a1.y, a1.z, a1.w};
            const float bv[4] = {bw.x, bw.y, bw.z, bw.w};
#pragma unroll
            for (int i = 0; i < 8; i++)
#pragma unroll
                for (int j = 0; j < 4; j++) acc[i][j] += av[i] * bv[j];
        }
        __syncthreads();
    }

    // ---- epilogue -----------------------------------------------------------
    float bb[4] = {0.f, 0.f, 0.f, 0.f};
    if (bias) {
#pragma unroll
        for (int j = 0; j < 4; j++) bb[j] = bias[col0 + tx * 4 + j];
    }
#pragma unroll
    for (int i = 0; i < 8; i++) {
        long r = row0 + ((i < 4) ? (ty * 4 + i) : (64 + ty * 4 + (i - 4)));
        float4 o;
        float ov[4];
#pragma unroll
        for (int j = 0; j < 4; j++) {
            float vv = acc[i][j] + bb[j];
            if (RELU) vv = fmaxf(vv, 0.0f);
            ov[j] = vv;
        }
        if (RES) {
            const float4 rv = *reinterpret_cast<const float4*>(
                res + r * NCOLS + col0 + tx * 4);
            ov[0] += rv.x; ov[1] += rv.y; ov[2] += rv.z; ov[3] += rv.w;
        }
        o.x = ov[0]; o.y = ov[1]; o.z = ov[2]; o.w = ov[3];
        *reinterpret_cast<float4*>(out + r * NCOLS + col0 + tx * 4) = o;
    }
}

// ---------------------------------------------------------------------------
// Attention: one block per (batch, head); 128 threads, one query row each.
// Causal mask + softmax (2-pass: max, then exp-sum + weighted V accumulate).
// ---------------------------------------------------------------------------
__global__ __launch_bounds__(128) void attn_kernel(
    const float* __restrict__ q, const float* __restrict__ k,
    const float* __restrict__ v, float* __restrict__ out) {
    __shared__ float4 ks[128][2];
    __shared__ float4 vs[128][2];
    int bh = blockIdx.x;
    int b = bh >> 3, h = bh & 7;
    int t = threadIdx.x;
    long base = ((long)b * TSEQ) * DMODEL + h * 8;
    long roff = base + (long)t * DMODEL;

    ks[t][0] = *reinterpret_cast<const float4*>(k + roff);
    ks[t][1] = *reinterpret_cast<const float4*>(k + roff + 4);
    vs[t][0] = *reinterpret_cast<const float4*>(v + roff);
    vs[t][1] = *reinterpret_cast<const float4*>(v + roff + 4);
    float4 q0 = *reinterpret_cast<const float4*>(q + roff);
    float4 q1 = *reinterpret_cast<const float4*>(q + roff + 4);
    const float scale = 0.35355339059327373f;  // 1/sqrt(8)
    q0.x *= scale; q0.y *= scale; q0.z *= scale; q0.w *= scale;
    q1.x *= scale; q1.y *= scale; q1.z *= scale; q1.w *= scale;
    __syncthreads();

    float m = -1e30f;
    for (int j = 0; j <= t; j++) {
        float4 k0 = ks[j][0], k1 = ks[j][1];
        float s = q0.x * k0.x + q0.y * k0.y + q0.z * k0.z + q0.w * k0.w +
                  q1.x * k1.x + q1.y * k1.y + q1.z * k1.z + q1.w * k1.w;
        m = fmaxf(m, s);
    }
    float l = 0.0f;
    float4 a0 = {0.f, 0.f, 0.f, 0.f}, a1 = {0.f, 0.f, 0.f, 0.f};
    for (int j = 0; j <= t; j++) {
        float4 k0 = ks[j][0], k1 = ks[j][1];
        float s = q0.x * k0.x + q0.y * k0.y + q0.z * k0.z + q0.w * k0.w +
                  q1.x * k1.x + q1.y * k1.y + q1.z * k1.z + q1.w * k1.w;
        float p = __expf(s - m);
        l += p;
        float4 v0 = vs[j][0], v1 = vs[j][1];
        a0.x += p * v0.x; a0.y += p * v0.y; a0.z += p * v0.z; a0.w += p * v0.w;
        a1.x += p * v1.x; a1.y += p * v1.y; a1.z += p * v1.z; a1.w += p * v1.w;
    }
    float inv = 1.0f / l;
    a0.x *= inv; a0.y *= inv; a0.z *= inv; a0.w *= inv;
    a1.x *= inv; a1.y *= inv; a1.z *= inv; a1.w *= inv;
    *reinterpret_cast<float4*>(out + roff) = a0;
    *reinterpret_cast<float4*>(out + roff + 4) = a1;
}

// ---------------------------------------------------------------------------
// LM head: logits[n,v] = xn[n] . lm_w[:,v] + lm_b[v]
// 520 threads = 8 groups x 65 lanes; weight column held in registers.
// tid = grp*65 + v  ->  logit writes are fully contiguous across the block.
// ---------------------------------------------------------------------------
__global__ __launch_bounds__(520) void lmhead_kernel(
    const float* __restrict__ xn, const float* __restrict__ w,
    const float* __restrict__ bv, float* __restrict__ logits) {
    __shared__ float ws[64 * 65];
    __shared__ float xs[32][64];
    int tid = threadIdx.x;
    long tok0 = (long)blockIdx.x * 32;
    for (int i = tid; i < 64 * 65; i += 520) ws[i] = w[i];
    for (int i = tid; i < 32 * 64; i += 520) xs[i >> 6][i & 63] = xn[tok0 * 64 + i];
    __syncthreads();

    int grp = tid / 65;
    int vv = tid - grp * 65;
    float wr[64];
#pragma unroll
    for (int d = 0; d < 64; d++) wr[d] = ws[d * 65 + vv];
    float bb = bv[vv];
    float acc[4] = {bb, bb, bb, bb};
#pragma unroll
    for (int d4 = 0; d4 < 16; d4++) {
        float4 xv[4];
#pragma unroll
        for (int u = 0; u < 4; u++)
            xv[u] = *reinterpret_cast<const float4*>(&xs[grp + 8 * u][d4 * 4]);
#pragma unroll
        for (int u = 0; u < 4; u++) {
            acc[u] += xv[u].x * wr[d4 * 4 + 0];
            acc[u] += xv[u].y * wr[d4 * 4 + 1];
            acc[u] += xv[u].z * wr[d4 * 4 + 2];
            acc[u] += xv[u].w * wr[d4 * 4 + 3];
        }
    }
#pragma unroll
    for (int u = 0; u < 4; u++)
        logits[(tok0 + grp + 8 * u) * NVOCAB + vv] = acc[u];
}

// ---------------------------------------------------------------------------
// Per-token cross-entropy; one warp per token (65 logits)
// ---------------------------------------------------------------------------
__global__ void loss_kernel(const float* __restrict__ logits,
                            const int* __restrict__ tgt,
                            float* __restrict__ tokloss) {
    long wid = ((long)blockIdx.x * blockDim.x + threadIdx.x) >> 5;
    int lane = threadIdx.x & 31;
    if (wid >= NTOK) return;
    const float* row = logits + wid * NVOCAB;
    float v0 = row[lane];
    float v1 = row[lane + 32];
    float v2 = (lane == 0) ? row[64] : -1e30f;
    float mx = fmaxf(fmaxf(v0, v1), v2);
#pragma unroll
    for (int o = 16; o; o >>= 1) mx = fmaxf(mx, __shfl_xor_sync(0xffffffffu, mx, o));
    float se = expf(v0 - mx) + expf(v1 - mx) + expf(v2 - mx);
#pragma unroll
    for (int o = 16; o; o >>= 1) se += __shfl_xor_sync(0xffffffffu, se, o);
    if (lane == 0) {
        int tg = tgt[wid];
        tokloss[wid] = -(row[tg] - mx - logf(se));
    }
}

// Deterministic fixed-tree mean reduction (single block)
__global__ void reduce_loss_kernel(const float* __restrict__ tokloss,
                                   float* __restrict__ out) {
    __shared__ double sm[1024];
    double s = 0.0;
    for (int i = threadIdx.x; i < NTOK; i += 1024) s += (double)tokloss[i];
    sm[threadIdx.x] = s;
    __syncthreads();
    for (int o = 512; o; o >>= 1) {
        if (threadIdx.x < o) sm[threadIdx.x] += sm[threadIdx.x + o];
        __syncthreads();
    }
    if (threadIdx.x == 0) out[0] = (float)(sm[0] / (double)NTOK);
}

// ---------------------------------------------------------------------------
extern "C" void kernel_launch(void* const* d_in, const int* in_sizes, int n_in,
                              void* d_out, int out_size) {
    const float* tok_emb = (const float*)d_in[0];
    const float* pos_emb = (const float*)d_in[1];
    const float* ln1_g   = (const float*)d_in[2];
    const float* ln1_b   = (const float*)d_in[3];
    const float* wq      = (const float*)d_in[4];
    const float* wk      = (const float*)d_in[5];
    const float* wv      = (const float*)d_in[6];
    const float* wo      = (const float*)d_in[7];
    const float* bo      = (const float*)d_in[8];
    const float* ln2_g   = (const float*)d_in[9];
    const float* ln2_b   = (const float*)d_in[10];
    const float* w1      = (const float*)d_in[11];
    const float* b1      = (const float*)d_in[12];
    const float* w2      = (const float*)d_in[13];
    const float* b2      = (const float*)d_in[14];
    const float* lnf_g   = (const float*)d_in[15];
    const float* lnf_b   = (const float*)d_in[16];
    const float* lm_w    = (const float*)d_in[17];
    const float* lm_b    = (const float*)d_in[18];
    const int*   idx     = (const int*)d_in[19];
    const int*   targets = (const int*)d_in[20];

    float *x, *xn, *q, *k, *v, *h1, *lg, *tl;
    cudaGetSymbolAddress((void**)&x,  g_x);
    cudaGetSymbolAddress((void**)&xn, g_xn);
    cudaGetSymbolAddress((void**)&q,  g_q);
    cudaGetSymbolAddress((void**)&k,  g_k);
    cudaGetSymbolAddress((void**)&v,  g_v);
    cudaGetSymbolAddress((void**)&h1, g_h1);
    cudaGetSymbolAddress((void**)&lg, g_logits);
    cudaGetSymbolAddress((void**)&tl, g_tokloss);

    float* outp = (float*)d_out;
    const long LSZ = (long)NTOK * NVOCAB;
    float* logits = ((long)out_size >= LSZ) ? outp : lg;
    float* lossp;
    if ((long)out_size >= LSZ + 1)      lossp = outp + LSZ;
    else if (out_size == 1)             lossp = outp;
    else                                lossp = tl;  // discarded

    embed_kernel<<<(NTOK * 16) / 256, 256>>>(
        idx, (const float4*)tok_emb, (const float4*)pos_emb, (float4*)x);

    const dim3 g1(NTOK / 128, 1);
    for (int l = 0; l < NLAYER; l++) {
        ln_kernel<<<NTOK / 8, 256>>>(x, ln1_g + l * 64, ln1_b + l * 64, xn);
        gemm_kernel<64, 64, false, false><<<g1, 256>>>(xn, wq + (long)l * 4096, nullptr, nullptr, q);
        gemm_kernel<64, 64, false, false><<<g1, 256>>>(xn, wk + (long)l * 4096, nullptr, nullptr, k);
        gemm_kernel<64, 64, false, false><<<g1, 256>>>(xn, wv + (long)l * 4096, nullptr, nullptr, v);
        attn_kernel<<<4096 * NHEAD, 128>>>(q, k, v, xn);
        gemm_kernel<64, 64, false, true><<<g1, 256>>>(xn, wo + (long)l * 4096, bo + l * 64, x, x);
        ln_kernel<<<NTOK / 8, 256>>>(x, ln2_g + l * 64, ln2_b + l * 64, xn);
        gemm_kernel<64, 256, true, false><<<dim3(NTOK / 128, 4), 256>>>(
            xn, w1 + (long)l * 64 * 256, b1 + l * 256, nullptr, h1);
        gemm_kernel<256, 64, false, true><<<g1, 256>>>(
            h1, w2 + (long)l * 256 * 64, b2 + l * 64, x, x);
    }
    ln_kernel<<<NTOK / 8, 256>>>(x, lnf_g, lnf_b, xn);
    lmhead_kernel<<<NTOK / 32, 520>>>(xn, lm_w, lm_b, logits);
    loss_kernel<<<NTOK / 8, 256>>>(logits, targets, tl);
    reduce_loss_kernel<<<1, 1024>>>(tl, lossp);
}

// round 2
// speedup vs baseline: 1.0197x; 1.0197x over previous
#include <cuda_runtime.h>

// ---------------------------------------------------------------------------
// 3-layer transformer forward. B=4096, T=128, D=64, H=8, HD=8, DF=256, V=65.
// Round 2: fused LN+QKV, fused attention+Wo+residual, fused LN+W1+ReLU,
// W2 with resident weights, fused LNf+lm_head+loss.
// ---------------------------------------------------------------------------

#define NTOK (4096 * 128)
#define TSEQ 128
#define DMODEL 64
#define NVOCAB 65
#define NHEAD 8
#define DFF 256
#define NLAYER 3

__device__ float g_x[(size_t)NTOK * DMODEL];
__device__ float g_q[(size_t)NTOK * DMODEL];
__device__ float g_k[(size_t)NTOK * DMODEL];
__device__ float g_v[(size_t)NTOK * DMODEL];
__device__ float g_h1[(size_t)NTOK * DFF];
__device__ float g_logits[(size_t)NTOK * NVOCAB];
__device__ float g_tokloss[NTOK];

// ---------------------------------------------------------------------------
// Embedding
// ---------------------------------------------------------------------------
__global__ void embed_kernel(const int* __restrict__ idx,
                             const float4* __restrict__ te,
                             const float4* __restrict__ pe,
                             float4* __restrict__ x) {
    long i = (long)blockIdx.x * blockDim.x + threadIdx.x;
    if (i >= (long)NTOK * 16) return;
    long tok = i >> 4;
    int d4 = (int)(i & 15);
    int id = idx[tok];
    int t = (int)(tok & (TSEQ - 1));
    float4 a = te[(long)id * 16 + d4];
    float4 p = pe[(long)t * 16 + d4];
    float4 r;
    r.x = a.x + p.x; r.y = a.y + p.y; r.z = a.z + p.z; r.w = a.w + p.w;
    x[i] = r;
}

// LN one row (64 elems) with a full warp; lane holds elems lane, lane+32.
// Returns the two normalized outputs.
__device__ __forceinline__ void warp_ln(const float* __restrict__ rowp, int lane,
                                        float gg0, float gg1, float bb0, float bb1,
                                        float& o0, float& o1) {
    float a0 = rowp[lane];
    float a1 = rowp[lane + 32];
    float s = a0 + a1;
#pragma unroll
    for (int o = 16; o; o >>= 1) s += __shfl_xor_sync(0xffffffffu, s, o);
    float mu = s * (1.0f / 64.0f);
    float d0 = a0 - mu, d1 = a1 - mu;
    float vs = d0 * d0 + d1 * d1;
#pragma unroll
    for (int o = 16; o; o >>= 1) vs += __shfl_xor_sync(0xffffffffu, vs, o);
    float inv = rsqrtf(vs * (1.0f / 64.0f) + 1e-5f);
    o0 = d0 * inv * gg0 + bb0;
    o1 = d1 * inv * gg1 + bb1;
}

// ---------------------------------------------------------------------------
// Fused LN1 + QKV: per block 128 tokens -> q,k,v [128,64] each.
// 512 threads. smem: xn^T swizzled (32KB) + Wqkv (36KB) = 68KB dynamic.
// Thread (ty,tx): rows ty*4..+3, cols tx*4..+3 in each of q,k,v. acc 4x12.
// ---------------------------------------------------------------------------
__global__ __launch_bounds__(512) void lnqkv_kernel(
    const float* __restrict__ x, const float* __restrict__ lng,
    const float* __restrict__ lnb,
    const float* __restrict__ wq, const float* __restrict__ wk,
    const float* __restrict__ wv,
    float* __restrict__ q, float* __restrict__ k, float* __restrict__ v) {
    extern __shared__ float smem[];
    float* Af = smem;                         // 8192 floats = As[64][32] f4
    float4* As4 = (float4*)smem;
    float4* Ws4 = (float4*)(smem + 8192);     // 3072 f4 = Ws[64][48]

    const int tid = threadIdx.x;
    const long row0 = (long)blockIdx.x * 128;

    // stage weights: slots 0..15=q, 16..31=k, 32..47=v per k-row
    {
        const float4* wsrc0 = (const float4*)wq;
        const float4* wsrc1 = (const float4*)wk;
        const float4* wsrc2 = (const float4*)wv;
#pragma unroll
        for (int i = 0; i < 6; i++) {
            int f = tid + i * 512;            // 0..3071
            int kk = f / 48, slot = f % 48;
            const float4* src = (slot < 16) ? wsrc0 : (slot < 32) ? wsrc1 : wsrc2;
            Ws4[f] = src[kk * 16 + (slot & 15)];
        }
    }
    // LN: 16 warps x 8 rows, store transposed+swizzled
    {
        int warp = tid >> 5, lane = tid & 31;
        float gg0 = lng[lane], gg1 = lng[lane + 32];
        float bb0 = lnb[lane], bb1 = lnb[lane + 32];
        for (int r = warp; r < 128; r += 16) {
            float o0, o1;
            warp_ln(x + (row0 + r) * 64, lane, gg0, gg1, bb0, bb1, o0, o1);
            int m4 = r >> 2, mi = r & 3;
            Af[lane * 128 + ((m4 ^ (lane & 31)) << 2) + mi] = o0;
            int k2 = lane + 32;
            Af[k2 * 128 + ((m4 ^ (k2 & 31)) << 2) + mi] = o1;
        }
    }
    __syncthreads();

    const int ty = tid >> 4;   // 0..31 : rows ty*4..+3
    const int tx = tid & 15;   // cols tx*4..+3 in each buffer
    float acc[4][12];
#pragma unroll
    for (int i = 0; i < 4; i++)
#pragma unroll
        for (int j = 0; j < 12; j++) acc[i][j] = 0.0f;

#pragma unroll 4
    for (int kk = 0; kk < 64; kk++) {
        float4 a  = As4[kk * 32 + (ty ^ (kk & 31))];
        float4 b0 = Ws4[kk * 48 + tx];
        float4 b1 = Ws4[kk * 48 + tx + 16];
        float4 b2 = Ws4[kk * 48 + tx + 32];
        float av[4] = {a.x, a.y, a.z, a.w};
        float bv[12] = {b0.x, b0.y, b0.z, b0.w, b1.x, b1.y, b1.z, b1.w,
                        b2.x, b2.y, b2.z, b2.w};
#pragma unroll
        for (int i = 0; i < 4; i++)
#pragma unroll
            for (int j = 0; j < 12; j++) acc[i][j] += av[i] * bv[j];
    }

    float* outs[3] = {q, k, v};
#pragma unroll
    for (int s = 0; s < 3; s++) {
#pragma unroll
        for (int i = 0; i < 4; i++) {
            float4 o;
            o.x = acc[i][s * 4 + 0]; o.y = acc[i][s * 4 + 1];
            o.z = acc[i][s * 4 + 2]; o.w = acc[i][s * 4 + 3];
            *reinterpret_cast<float4*>(outs[s] + (row0 + ty * 4 + i) * 64 + tx * 4) = o;
        }
    }
}

// ---------------------------------------------------------------------------
// Fused attention + Wo + bias + residual. One block per batch (128 tokens,
// all 8 heads), 256 threads. Thread = (head h, lane g) handles queries
// t = g+32i, i=0..3 with branchless softmax (exp without max: |scores|<<1).
// smem: K 32KB + V 32KB + Wo 16KB + attn_out 128x65 f = ~112.3KB dynamic.
// ---------------------------------------------------------------------------
__global__ __launch_bounds__(256) void attnwo_kernel(
    const float* __restrict__ q, const float* __restrict__ k,
    const float* __restrict__ v, const float* __restrict__ wo,
    const float* __restrict__ bo, float* __restrict__ x) {
    extern __shared__ float smem[];
    float4* ks4 = (float4*)smem;          // [128*16]
    float4* vs4 = ks4 + 2048;             // [128*16]
    float4* wo4 = vs4 + 2048;             // [64*16]
    float* ao = (float*)(wo4 + 1024);     // [128][65]

    const int tid = threadIdx.x;
    const long base = (long)blockIdx.x * 128 * 64;

    // stage K,V (coalesced: thread pair covers one 256B row)
    {
        int row = tid >> 1, half = (tid & 1) * 8;
        const float4* kg = (const float4*)(k + base) + row * 16 + half;
        const float4* vg = (const float4*)(v + base) + row * 16 + half;
        float4* kd = ks4 + row * 16 + half;
        float4* vd = vs4 + row * 16 + half;
#pragma unroll
        for (int i = 0; i < 8; i++) { kd[i] = kg[i]; vd[i] = vg[i]; }
    }
    {
        const float4* wg = (const float4*)wo;
#pragma unroll
        for (int i = 0; i < 4; i++) wo4[tid + i * 256] = wg[tid + i * 256];
    }

    const int h = tid >> 5, g = tid & 31;
    const float scale = 0.35355339059327373f;  // 1/sqrt(8)
    float4 q0[4], q1[4];
#pragma unroll
    for (int i = 0; i < 4; i++) {
        int t = g + 32 * i;
        const float4* qg = (const float4*)(q + base + (long)t * 64 + h * 8);
        float4 a = qg[0], bq = qg[1];
        a.x *= scale; a.y *= scale; a.z *= scale; a.w *= scale;
        bq.x *= scale; bq.y *= scale; bq.z *= scale; bq.w *= scale;
        q0[i] = a; q1[i] = bq;
    }
    float acc[4][8];
    float l[4] = {0.f, 0.f, 0.f, 0.f};
#pragma unroll
    for (int i = 0; i < 4; i++)
#pragma unroll
        for (int d = 0; d < 8; d++) acc[i][d] = 0.0f;

    __syncthreads();

    const float4* kp = ks4 + h * 2;
    const float4* vp = vs4 + h * 2;
#pragma unroll 2
    for (int j = 0; j < 128; j++) {
        float4 k0 = kp[j * 16], k1 = kp[j * 16 + 1];
        float4 v0 = vp[j * 16], v1 = vp[j * 16 + 1];
#pragma unroll
        for (int i = 0; i < 4; i++) {
            float s = q0[i].x * k0.x + q0[i].y * k0.y + q0[i].z * k0.z +
                      q0[i].w * k0.w + q1[i].x * k1.x + q1[i].y * k1.y +
                      q1[i].z * k1.z + q1[i].w * k1.w;
            float p = (j <= g + 32 * i) ? __expf(s) : 0.0f;
            l[i] += p;
            acc[i][0] += p * v0.x; acc[i][1] += p * v0.y;
            acc[i][2] += p * v0.z; acc[i][3] += p * v0.w;
            acc[i][4] += p * v1.x; acc[i][5] += p * v1.y;
            acc[i][6] += p * v1.z; acc[i][7] += p * v1.w;
        }
    }
#pragma unroll
    for (int i = 0; i < 4; i++) {
        float inv = 1.0f / l[i];
        int t = g + 32 * i;
        float* aop = ao + t * 65 + h * 8;
#pragma unroll
        for (int d = 0; d < 8; d++) aop[d] = acc[i][d] * inv;
    }
    __syncthreads();

    // Wo GEMM + bias + residual, in-place on x. 256 thr: 8 rows x 4 cols each.
    const int ty = tid >> 4, tx = tid & 15;
    float oacc[8][4];
#pragma unroll
    for (int i = 0; i < 8; i++)
#pragma unroll
        for (int j = 0; j < 4; j++) oacc[i][j] = 0.0f;
#pragma unroll 4
    for (int kk = 0; kk < 64; kk++) {
        float4 bw = wo4[kk * 16 + tx];
#pragma unroll
        for (int i = 0; i < 8; i++) {
            float a = ao[(ty * 8 + i) * 65 + kk];
            oacc[i][0] += a * bw.x; oacc[i][1] += a * bw.y;
            oacc[i][2] += a * bw.z; oacc[i][3] += a * bw.w;
        }
    }
    float4 bb = ((const float4*)bo)[tx];
#pragma unroll
    for (int i = 0; i < 8; i++) {
        float4* xp = (float4*)(x + base + (long)(ty * 8 + i) * 64) + tx;
        float4 rv = *xp;
        float4 o;
        o.x = oacc[i][0] + bb.x + rv.x;
        o.y = oacc[i][1] + bb.y + rv.y;
        o.z = oacc[i][2] + bb.z + rv.z;
        o.w = oacc[i][3] + bb.w + rv.w;
        *xp = o;
    }
}

// ---------------------------------------------------------------------------
// Fused LN2 + W1 + bias + ReLU: 128 tokens x 256 outputs, 512 threads.
// smem: xn^T swizzled 32KB + W1 64KB = 96KB dynamic. acc 8x8.
// ---------------------------------------------------------------------------
__global__ __launch_bounds__(512) void lnffn1_kernel(
    const float* __restrict__ x, const float* __restrict__ lng,
    const float* __restrict__ lnb, const float* __restrict__ w1,
    const float* __restrict__ b1, float* __restrict__ h1) {
    extern __shared__ float smem[];
    float* Af = smem;                       // 8192 floats
    float4* As4 = (float4*)smem;
    float4* Ws4 = (float4*)(smem + 8192);   // 4096 f4 = W1[64][64 f4]

    const int tid = threadIdx.x;
    const long row0 = (long)blockIdx.x * 128;

#pragma unroll
    for (int i = 0; i < 8; i++) Ws4[tid + i * 512] = ((const float4*)w1)[tid + i * 512];
    {
        int warp = tid >> 5, lane = tid & 31;
        float gg0 = lng[lane], gg1 = lng[lane + 32];
        float bb0 = lnb[lane], bb1 = lnb[lane + 32];
        for (int r = warp; r < 128; r += 16) {
            float o0, o1;
            warp_ln(x + (row0 + r) * 64, lane, gg0, gg1, bb0, bb1, o0, o1);
            int m4 = r >> 2, mi = r & 3;
            Af[lane * 128 + ((m4 ^ (lane & 31)) << 2) + mi] = o0;
            int k2 = lane + 32;
            Af[k2 * 128 + ((m4 ^ (k2 & 31)) << 2) + mi] = o1;
        }
    }
    __syncthreads();

    const int ty = tid >> 5;   // warp id: rows ty*8..+7 (A broadcast in warp)
    const int tx = tid & 31;   // cols tx*4..+3 and 128+tx*4..+3
    float acc[8][8];
#pragma unroll
    for (int i = 0; i < 8; i++)
#pragma unroll
        for (int j = 0; j < 8; j++) acc[i][j] = 0.0f;

#pragma unroll 4
    for (int kk = 0; kk < 64; kk++) {
        float4 a0 = As4[kk * 32 + ((ty * 2) ^ (kk & 31))];
        float4 a1 = As4[kk * 32 + ((ty * 2 + 1) ^ (kk & 31))];
        float4 b0 = Ws4[kk * 64 + tx];
        float4 b1 = Ws4[kk * 64 + tx + 32];
        float av[8] = {a0.x, a0.y, a0.z, a0.w, a1.x, a1.y, a1.z, a1.w};
        float bv[8] = {b0.x, b0.y, b0.z, b0.w, b1.x, b1.y, b1.z, b1.w};
#pragma unroll
        for (int i = 0; i < 8; i++)
#pragma unroll
            for (int j = 0; j < 8; j++) acc[i][j] += av[i] * bv[j];
    }

    float4 bia0 = ((const float4*)b1)[tx];
    float4 bia1 = ((const float4*)b1)[tx + 32];
#pragma unroll
    for (int i = 0; i < 8; i++) {
        long r = row0 + ty * 8 + i;
        float4 o0, o1;
        o0.x = fmaxf(acc[i][0] + bia0.x, 0.f);
        o0.y = fmaxf(acc[i][1] + bia0.y, 0.f);
        o0.z = fmaxf(acc[i][2] + bia0.z, 0.f);
        o0.w = fmaxf(acc[i][3] + bia0.w, 0.f);
        o1.x = fmaxf(acc[i][4] + bia1.x, 0.f);
        o1.y = fmaxf(acc[i][5] + bia1.y, 0.f);
        o1.z = fmaxf(acc[i][6] + bia1.z, 0.f);
        o1.w = fmaxf(acc[i][7] + bia1.w, 0.f);
        *reinterpret_cast<float4*>(h1 + r * 256 + tx * 4) = o0;
        *reinterpret_cast<float4*>(h1 + r * 256 + 128 + tx * 4) = o1;
    }
}

// ---------------------------------------------------------------------------
// W2 + bias + residual: K=256, out 64. W2 fully resident (64KB), A staged in
// 64-wide chunks (32KB swizzled). 512 threads, acc 4x4.
// ---------------------------------------------------------------------------
__global__ __launch_bounds__(512) void ffn2_kernel(
    const float* __restrict__ h1, const float* __restrict__ w2,
    const float* __restrict__ b2, float* __restrict__ x) {
    extern __shared__ float smem[];
    float* Af = smem;                       // 8192 floats
    float4* As4 = (float4*)smem;
    float4* Ws4 = (float4*)(smem + 8192);   // 4096 f4 = W2[256][16 f4]

    const int tid = threadIdx.x;
    const long row0 = (long)blockIdx.x * 128;

#pragma unroll
    for (int i = 0; i < 8; i++) Ws4[tid + i * 512] = ((const float4*)w2)[tid + i * 512];

    const int ty = tid >> 4;   // 0..31: rows ty*4..+3
    const int tx = tid & 15;   // cols tx*4..+3
    float acc[4][4];
#pragma unroll
    for (int i = 0; i < 4; i++)
#pragma unroll
        for (int j = 0; j < 4; j++) acc[i][j] = 0.0f;

    const int arow = tid >> 2;            // 0..127
    const int alane = tid & 3;            // coalesced: col f4 = jj*4 + alane

    for (int kc = 0; kc < 256; kc += 64) {
        __syncthreads();
#pragma unroll
        for (int jj = 0; jj < 4; jj++) {
            int f4c = jj * 4 + alane;     // 0..15 within chunk
            float4 av = ((const float4*)(h1 + (row0 + arow) * 256 + kc))[f4c];
            int m4 = arow >> 2, mi = arow & 3;
            int kq = f4c * 4;
            float vals[4] = {av.x, av.y, av.z, av.w};
#pragma unroll
            for (int c = 0; c < 4; c++) {
                int kqq = kq + c;
                Af[kqq * 128 + ((m4 ^ (kqq & 31)) << 2) + mi] = vals[c];
            }
        }
        __syncthreads();
#pragma unroll 4
        for (int kk = 0; kk < 64; kk++) {
            float4 a = As4[kk * 32 + (ty ^ (kk & 31))];
            float4 bw = Ws4[(kc + kk) * 16 + tx];
            float av[4] = {a.x, a.y, a.z, a.w};
#pragma unroll
            for (int i = 0; i < 4; i++) {
                acc[i][0] += av[i] * bw.x; acc[i][1] += av[i] * bw.y;
                acc[i][2] += av[i] * bw.z; acc[i][3] += av[i] * bw.w;
            }
        }
    }

    float4 bb = ((const float4*)b2)[tx];
#pragma unroll
    for (int i = 0; i < 4; i++) {
        float4* xp = (float4*)(x + (row0 + ty * 4 + i) * 64) + tx;
        float4 rv = *xp;
        float4 o;
        o.x = acc[i][0] + bb.x + rv.x;
        o.y = acc[i][1] + bb.y + rv.y;
        o.z = acc[i][2] + bb.z + rv.z;
        o.w = acc[i][3] + bb.w + rv.w;
        *xp = o;
    }
}

// ---------------------------------------------------------------------------
// Fused LNf + LM head + per-token loss. Block = 32 tokens, 520 threads.
// ---------------------------------------------------------------------------
__global__ __launch_bounds__(520) void lmhead_kernel(
    const float* __restrict__ x, const float* __restrict__ lng,
    const float* __restrict__ lnb, const float* __restrict__ w,
    const float* __restrict__ bv, const int* __restrict__ tgt,
    float* __restrict__ logits, float* __restrict__ tokloss) {
    __shared__ float ws[64 * 65];
    __shared__ float xs[32][64];
    __shared__ float ls[32][65];
    int tid = threadIdx.x;
    long tok0 = (long)blockIdx.x * 32;
    for (int i = tid; i < 64 * 65; i += 520) ws[i] = w[i];
    if (tid < 512) {
        int warp = tid >> 5, lane = tid & 31;
        float gg0 = lng[lane], gg1 = lng[lane + 32];
        float bb0 = lnb[lane], bb1 = lnb[lane + 32];
#pragma unroll
        for (int rr = 0; rr < 2; rr++) {
            int r = warp * 2 + rr;
            float o0, o1;
            warp_ln(x + (tok0 + r) * 64, lane, gg0, gg1, bb0, bb1, o0, o1);
            xs[r][lane] = o0;
            xs[r][lane + 32] = o1;
        }
    }
    __syncthreads();

    int grp = tid / 65;
    int vv = tid - grp * 65;
    float wr[64];
#pragma unroll
    for (int d = 0; d < 64; d++) wr[d] = ws[d * 65 + vv];
    float bb = bv[vv];
    float acc[4] = {bb, bb, bb, bb};
#pragma unroll
    for (int d4 = 0; d4 < 16; d4++) {
        float4 xv[4];
#pragma unroll
        for (int u = 0; u < 4; u++)
            xv[u] = *reinterpret_cast<const float4*>(&xs[grp + 8 * u][d4 * 4]);
#pragma unroll
        for (int u = 0; u < 4; u++) {
            acc[u] += xv[u].x * wr[d4 * 4 + 0];
            acc[u] += xv[u].y * wr[d4 * 4 + 1];
            acc[u] += xv[u].z * wr[d4 * 4 + 2];
            acc[u] += xv[u].w * wr[d4 * 4 + 3];
        }
    }
#pragma unroll
    for (int u = 0; u < 4; u++) {
        logits[(tok0 + grp + 8 * u) * NVOCAB + vv] = acc[u];
        ls[grp + 8 * u][vv] = acc[u];
    }
    __syncthreads();

    if (tid < 512) {
        int warp = tid >> 5, lane = tid & 31;
#pragma unroll
        for (int rr = 0; rr < 2; rr++) {
            int t = warp * 2 + rr;
            float v0 = ls[t][lane];
            float v1 = ls[t][lane + 32];
            float v2 = (lane == 0) ? ls[t][64] : -1e30f;
            float mx = fmaxf(fmaxf(v0, v1), v2);
#pragma unroll
            for (int o = 16; o; o >>= 1)
                mx = fmaxf(mx, __shfl_xor_sync(0xffffffffu, mx, o));
            float se = expf(v0 - mx) + expf(v1 - mx) + expf(v2 - mx);
#pragma unroll
            for (int o = 16; o; o >>= 1) se += __shfl_xor_sync(0xffffffffu, se, o);
            if (lane == 0) {
                int tg = tgt[tok0 + t];
                tokloss[tok0 + t] = -(ls[t][tg] - mx - logf(se));
            }
        }
    }
}

// Deterministic fixed-tree mean reduction
__global__ void reduce_loss_kernel(const float* __restrict__ tokloss,
                                   float* __restrict__ out) {
    __shared__ double sm[1024];
    double s = 0.0;
    for (int i = threadIdx.x; i < NTOK; i += 1024) s += (double)tokloss[i];
    sm[threadIdx.x] = s;
    __syncthreads();
    for (int o = 512; o; o >>= 1) {
        if (threadIdx.x < o) sm[threadIdx.x] += sm[threadIdx.x + o];
        __syncthreads();
    }
    if (threadIdx.x == 0) out[0] = (float)(sm[0] / (double)NTOK);
}

// ---------------------------------------------------------------------------
extern "C" void kernel_launch(void* const* d_in, const int* in_sizes, int n_in,
                              void* d_out, int out_size) {
    const float* tok_emb = (const float*)d_in[0];
    const float* pos_emb = (const float*)d_in[1];
    const float* ln1_g   = (const float*)d_in[2];
    const float* ln1_b   = (const float*)d_in[3];
    const float* wq      = (const float*)d_in[4];
    const float* wk      = (const float*)d_in[5];
    const float* wv      = (const float*)d_in[6];
    const float* wo      = (const float*)d_in[7];
    const float* bo      = (const float*)d_in[8];
    const float* ln2_g   = (const float*)d_in[9];
    const float* ln2_b   = (const float*)d_in[10];
    const float* w1      = (const float*)d_in[11];
    const float* b1      = (const float*)d_in[12];
    const float* w2      = (const float*)d_in[13];
    const float* b2      = (const float*)d_in[14];
    const float* lnf_g   = (const float*)d_in[15];
    const float* lnf_b   = (const float*)d_in[16];
    const float* lm_w    = (const float*)d_in[17];
    const float* lm_b    = (const float*)d_in[18];
    const int*   idx     = (const int*)d_in[19];
    const int*   targets = (const int*)d_in[20];

    float *x, *q, *k, *v, *h1, *lg, *tl;
    cudaGetSymbolAddress((void**)&x,  g_x);
    cudaGetSymbolAddress((void**)&q,  g_q);
    cudaGetSymbolAddress((void**)&k,  g_k);
    cudaGetSymbolAddress((void**)&v,  g_v);
    cudaGetSymbolAddress((void**)&h1, g_h1);
    cudaGetSymbolAddress((void**)&lg, g_logits);
    cudaGetSymbolAddress((void**)&tl, g_tokloss);

    float* outp = (float*)d_out;
    const long LSZ = (long)NTOK * NVOCAB;
    float* logits = ((long)out_size >= LSZ) ? outp : lg;
    float* lossp;
    if ((long)out_size >= LSZ + 1)      lossp = outp + LSZ;
    else if (out_size == 1)             lossp = outp;
    else                                lossp = tl;

    const int LNQKV_SMEM = (8192 + 3072 * 4) * 4;           // 68 KB
    const int ATTN_SMEM  = (2048 + 2048 + 1024) * 16 + 128 * 65 * 4;  // ~112.3 KB
    const int FFN_SMEM   = (8192 + 4096 * 4) * 4;           // 96 KB
    cudaFuncSetAttribute(lnqkv_kernel, cudaFuncAttributeMaxDynamicSharedMemorySize, LNQKV_SMEM);
    cudaFuncSetAttribute(attnwo_kernel, cudaFuncAttributeMaxDynamicSharedMemorySize, ATTN_SMEM);
    cudaFuncSetAttribute(lnffn1_kernel, cudaFuncAttributeMaxDynamicSharedMemorySize, FFN_SMEM);
    cudaFuncSetAttribute(ffn2_kernel,  cudaFuncAttributeMaxDynamicSharedMemorySize, FFN_SMEM);

    embed_kernel<<<(NTOK * 16) / 256, 256>>>(
        idx, (const float4*)tok_emb, (const float4*)pos_emb, (float4*)x);

    for (int l = 0; l < NLAYER; l++) {
        lnqkv_kernel<<<NTOK / 128, 512, LNQKV_SMEM>>>(
            x, ln1_g + l * 64, ln1_b + l * 64,
            wq + (long)l * 4096, wk + (long)l * 4096, wv + (long)l * 4096,
            q, k, v);
        attnwo_kernel<<<4096, 256, ATTN_SMEM>>>(
            q, k, v, wo + (long)l * 4096, bo + l * 64, x);
        lnffn1_kernel<<<NTOK / 128, 512, FFN_SMEM>>>(
            x, ln2_g + l * 64, ln2_b + l * 64,
            w1 + (long)l * 64 * 256, b1 + l * 256, h1);
        ffn2_kernel<<<NTOK / 128, 512, FFN_SMEM>>>(
            h1, w2 + (long)l * 256 * 64, b2 + l * 64, x);
    }
    lmhead_kernel<<<NTOK / 32, 520>>>(x, lnf_g, lnf_b, lm_w, lm_b, targets,
                                      logits, tl);
    reduce_loss_kernel<<<1, 1024>>>(tl, lossp);
}

// round 3
// speedup vs baseline: 1.3441x; 1.3181x over previous
#include <cuda_runtime.h>
#include <cstdint>

// ---------------------------------------------------------------------------
// 3-layer transformer forward. B=4096, T=128, D=64, H=8, HD=8, DF=256, V=65.
// Round 3: TF32 tensor-core (mma.sync.m16n8k8) GEMMs for QKV / FFN1 / FFN2.
// ---------------------------------------------------------------------------

#define NTOK (4096 * 128)
#define TSEQ 128
#define DMODEL 64
#define NVOCAB 65
#define NHEAD 8
#define DFF 256
#define NLAYER 3

__device__ float g_x[(size_t)NTOK * DMODEL];
__device__ float g_q[(size_t)NTOK * DMODEL];
__device__ float g_k[(size_t)NTOK * DMODEL];
__device__ float g_v[(size_t)NTOK * DMODEL];
__device__ float g_h1[(size_t)NTOK * DFF];
__device__ float g_logits[(size_t)NTOK * NVOCAB];
__device__ float g_tokloss[NTOK];

// ---------------------------------------------------------------------------
__device__ __forceinline__ unsigned f2tf(float f) {
    unsigned r;
    asm("cvt.rna.tf32.f32 %0, %1;" : "=r"(r) : "f"(f));
    return r;
}

__device__ __forceinline__ void mma_tf32(float* c, const unsigned* a,
                                         const unsigned* b) {
    asm volatile(
        "mma.sync.aligned.m16n8k8.row.col.f32.tf32.tf32.f32 "
        "{%0,%1,%2,%3},{%4,%5,%6,%7},{%8,%9},{%0,%1,%2,%3};"
        : "+f"(c[0]), "+f"(c[1]), "+f"(c[2]), "+f"(c[3])
        : "r"(a[0]), "r"(a[1]), "r"(a[2]), "r"(a[3]), "r"(b[0]), "r"(b[1]));
}

// LN one row (64 elems) with a full warp; lane holds elems lane, lane+32.
__device__ __forceinline__ void warp_ln(const float* __restrict__ rowp, int lane,
                                        float gg0, float gg1, float bb0, float bb1,
                                        float& o0, float& o1) {
    float a0 = rowp[lane];
    float a1 = rowp[lane + 32];
    float s = a0 + a1;
#pragma unroll
    for (int o = 16; o; o >>= 1) s += __shfl_xor_sync(0xffffffffu, s, o);
    float mu = s * (1.0f / 64.0f);
    float d0 = a0 - mu, d1 = a1 - mu;
    float vs = d0 * d0 + d1 * d1;
#pragma unroll
    for (int o = 16; o; o >>= 1) vs += __shfl_xor_sync(0xffffffffu, vs, o);
    float inv = rsqrtf(vs * (1.0f / 64.0f) + 1e-5f);
    o0 = d0 * inv * gg0 + bb0;
    o1 = d1 * inv * gg1 + bb1;
}

// ---------------------------------------------------------------------------
// Embedding
// ---------------------------------------------------------------------------
__global__ void embed_kernel(const int* __restrict__ idx,
                             const float4* __restrict__ te,
                             const float4* __restrict__ pe,
                             float4* __restrict__ x) {
    long i = (long)blockIdx.x * blockDim.x + threadIdx.x;
    if (i >= (long)NTOK * 16) return;
    long tok = i >> 4;
    int d4 = (int)(i & 15);
    int id = idx[tok];
    int t = (int)(tok & (TSEQ - 1));
    float4 a = te[(long)id * 16 + d4];
    float4 p = pe[(long)t * 16 + d4];
    float4 r;
    r.x = a.x + p.x; r.y = a.y + p.y; r.z = a.z + p.z; r.w = a.w + p.w;
    x[i] = r;
}

// ---------------------------------------------------------------------------
// Fused LN1 + QKV via TF32 MMA. Block: 128 tokens, 512 threads (16 warps,
// 4M x 4N). Warp tile 32x48. smem: As[128][68] + Bs[192][68] tf32.
// ---------------------------------------------------------------------------
__global__ __launch_bounds__(512) void lnqkv_tc(
    const float* __restrict__ x, const float* __restrict__ lng,
    const float* __restrict__ lnb,
    const float* __restrict__ wq, const float* __restrict__ wk,
    const float* __restrict__ wv,
    float* __restrict__ q, float* __restrict__ k, float* __restrict__ v) {
    extern __shared__ unsigned sm[];
    unsigned* As = sm;              // [128][68]
    unsigned* Bs = sm + 128 * 68;   // [192][68]  (Wt: row n, col k)
    const int tid = threadIdx.x;
    const long row0 = (long)blockIdx.x * 128;

    // stage weights transposed + tf32
    {
        const float* wsrc[3] = {wq, wk, wv};
#pragma unroll
        for (int s = 0; s < 3; s++) {
            const float* W = wsrc[s];
#pragma unroll
            for (int j = 0; j < 8; j++) {
                int e = tid + j * 512;      // 0..4095
                int kk = e >> 6, n = e & 63;
                Bs[(s * 64 + n) * 68 + kk] = f2tf(W[e]);
            }
        }
    }
    // LN -> As (row-major, tf32)
    {
        int warp = tid >> 5, lane = tid & 31;
        float gg0 = lng[lane], gg1 = lng[lane + 32];
        float bb0 = lnb[lane], bb1 = lnb[lane + 32];
        for (int r = warp; r < 128; r += 16) {
            float o0, o1;
            warp_ln(x + (row0 + r) * 64, lane, gg0, gg1, bb0, bb1, o0, o1);
            As[r * 68 + lane] = f2tf(o0);
            As[r * 68 + lane + 32] = f2tf(o1);
        }
    }
    __syncthreads();

    const int wid = tid >> 5, lane = tid & 31;
    const int wm = wid >> 2, wn = wid & 3;
    const int m0 = wm * 32, n0 = wn * 48;
    const int lr = lane >> 2, lc = lane & 3;

    float acc[2][6][4];
#pragma unroll
    for (int mi = 0; mi < 2; mi++)
#pragma unroll
        for (int ni = 0; ni < 6; ni++)
#pragma unroll
            for (int e = 0; e < 4; e++) acc[mi][ni][e] = 0.0f;

#pragma unroll
    for (int k0 = 0; k0 < 64; k0 += 8) {
        unsigned a[2][4];
#pragma unroll
        for (int mi = 0; mi < 2; mi++) {
            int rb = m0 + mi * 16 + lr;
            a[mi][0] = As[rb * 68 + k0 + lc];
            a[mi][1] = As[(rb + 8) * 68 + k0 + lc];
            a[mi][2] = As[rb * 68 + k0 + lc + 4];
            a[mi][3] = As[(rb + 8) * 68 + k0 + lc + 4];
        }
#pragma unroll
        for (int ni = 0; ni < 6; ni++) {
            int nb = n0 + ni * 8 + lr;
            unsigned b[2];
            b[0] = Bs[nb * 68 + k0 + lc];
            b[1] = Bs[nb * 68 + k0 + lc + 4];
#pragma unroll
            for (int mi = 0; mi < 2; mi++) mma_tf32(acc[mi][ni], a[mi], b);
        }
    }

    float* bufs[3] = {q, k, v};
#pragma unroll
    for (int ni = 0; ni < 6; ni++) {
        int cg = n0 + ni * 8;
        float* out = bufs[cg >> 6];
        int col = (cg & 63) + 2 * lc;
#pragma unroll
        for (int mi = 0; mi < 2; mi++) {
            long r = row0 + m0 + mi * 16 + lr;
            *(float2*)(out + r * 64 + col) =
                make_float2(acc[mi][ni][0], acc[mi][ni][1]);
            *(float2*)(out + (r + 8) * 64 + col) =
                make_float2(acc[mi][ni][2], acc[mi][ni][3]);
        }
    }
}

// ---------------------------------------------------------------------------
// Fused LN2 + W1 + bias + ReLU via TF32 MMA. Block 128x256, 512 thr, warp
// tile 32x64. smem: As[128][68] + Bs[256][68].
// ---------------------------------------------------------------------------
__global__ __launch_bounds__(512) void lnffn1_tc(
    const float* __restrict__ x, const float* __restrict__ lng,
    const float* __restrict__ lnb, const float* __restrict__ w1,
    const float* __restrict__ b1, float* __restrict__ h1) {
    extern __shared__ unsigned sm[];
    unsigned* As = sm;              // [128][68]
    unsigned* Bs = sm + 128 * 68;   // [256][68]
    const int tid = threadIdx.x;
    const long row0 = (long)blockIdx.x * 128;

#pragma unroll
    for (int j = 0; j < 32; j++) {
        int e = tid + j * 512;          // 0..16383
        int kk = e >> 8, n = e & 255;
        Bs[n * 68 + kk] = f2tf(w1[e]);
    }
    {
        int warp = tid >> 5, lane = tid & 31;
        float gg0 = lng[lane], gg1 = lng[lane + 32];
        float bb0 = lnb[lane], bb1 = lnb[lane + 32];
        for (int r = warp; r < 128; r += 16) {
            float o0, o1;
            warp_ln(x + (row0 + r) * 64, lane, gg0, gg1, bb0, bb1, o0, o1);
            As[r * 68 + lane] = f2tf(o0);
            As[r * 68 + lane + 32] = f2tf(o1);
        }
    }
    __syncthreads();

    const int wid = tid >> 5, lane = tid & 31;
    const int wm = wid >> 2, wn = wid & 3;
    const int m0 = wm * 32, n0 = wn * 64;
    const int lr = lane >> 2, lc = lane & 3;

    float acc[2][8][4];
#pragma unroll
    for (int mi = 0; mi < 2; mi++)
#pragma unroll
        for (int ni = 0; ni < 8; ni++)
#pragma unroll
            for (int e = 0; e < 4; e++) acc[mi][ni][e] = 0.0f;

#pragma unroll
    for (int k0 = 0; k0 < 64; k0 += 8) {
        unsigned a[2][4];
#pragma unroll
        for (int mi = 0; mi < 2; mi++) {
            int rb = m0 + mi * 16 + lr;
            a[mi][0] = As[rb * 68 + k0 + lc];
            a[mi][1] = As[(rb + 8) * 68 + k0 + lc];
            a[mi][2] = As[rb * 68 + k0 + lc + 4];
            a[mi][3] = As[(rb + 8) * 68 + k0 + lc + 4];
        }
#pragma unroll
        for (int ni = 0; ni < 8; ni++) {
            int nb = n0 + ni * 8 + lr;
            unsigned b[2];
            b[0] = Bs[nb * 68 + k0 + lc];
            b[1] = Bs[nb * 68 + k0 + lc + 4];
#pragma unroll
            for (int mi = 0; mi < 2; mi++) mma_tf32(acc[mi][ni], a[mi], b);
        }
    }

#pragma unroll
    for (int ni = 0; ni < 8; ni++) {
        int col = n0 + ni * 8 + 2 * lc;
        float2 bb = *(const float2*)(b1 + col);
#pragma unroll
        for (int mi = 0; mi < 2; mi++) {
            long r = row0 + m0 + mi * 16 + lr;
            float2 o0, o1;
            o0.x = fmaxf(acc[mi][ni][0] + bb.x, 0.0f);
            o0.y = fmaxf(acc[mi][ni][1] + bb.y, 0.0f);
            o1.x = fmaxf(acc[mi][ni][2] + bb.x, 0.0f);
            o1.y = fmaxf(acc[mi][ni][3] + bb.y, 0.0f);
            *(float2*)(h1 + r * 256 + col) = o0;
            *(float2*)(h1 + (r + 8) * 256 + col) = o1;
        }
    }
}

// ---------------------------------------------------------------------------
// W2 + bias + residual via TF32 MMA. Block 128x64, K=256 in 4 chunks.
// 512 thr, warp tile 32x16. smem: As[128][68] + Bs[64][260].
// ---------------------------------------------------------------------------
__global__ __launch_bounds__(512) void ffn2_tc(
    const float* __restrict__ h1, const float* __restrict__ w2,
    const float* __restrict__ b2, float* __restrict__ x) {
    extern __shared__ unsigned sm[];
    unsigned* As = sm;              // [128][68]
    unsigned* Bs = sm + 128 * 68;   // [64][260]
    const int tid = threadIdx.x;
    const long row0 = (long)blockIdx.x * 128;

#pragma unroll
    for (int j = 0; j < 32; j++) {
        int e = tid + j * 512;          // 0..16383
        int kk = e >> 6, n = e & 63;
        Bs[n * 260 + kk] = f2tf(w2[e]);
    }

    const int wid = tid >> 5, lane = tid & 31;
    const int wm = wid >> 2, wn = wid & 3;
    const int m0 = wm * 32, n0 = wn * 16;
    const int lr = lane >> 2, lc = lane & 3;

    float acc[2][2][4];
#pragma unroll
    for (int mi = 0; mi < 2; mi++)
#pragma unroll
        for (int ni = 0; ni < 2; ni++)
#pragma unroll
            for (int e = 0; e < 4; e++) acc[mi][ni][e] = 0.0f;

    for (int kc = 0; kc < 256; kc += 64) {
        __syncthreads();
        {
            int r = tid >> 2;
            const float4* src = (const float4*)(h1 + (row0 + r) * 256 + kc);
#pragma unroll
            for (int i = 0; i < 4; i++) {
                int f4 = (tid & 3) + 4 * i;
                float4 val = src[f4];
                unsigned* d = &As[r * 68 + f4 * 4];
                d[0] = f2tf(val.x); d[1] = f2tf(val.y);
                d[2] = f2tf(val.z); d[3] = f2tf(val.w);
            }
        }
        __syncthreads();
#pragma unroll
        for (int k0 = 0; k0 < 64; k0 += 8) {
            unsigned a[2][4];
#pragma unroll
            for (int mi = 0; mi < 2; mi++) {
                int rb = m0 + mi * 16 + lr;
                a[mi][0] = As[rb * 68 + k0 + lc];
                a[mi][1] = As[(rb + 8) * 68 + k0 + lc];
                a[mi][2] = As[rb * 68 + k0 + lc + 4];
                a[mi][3] = As[(rb + 8) * 68 + k0 + lc + 4];
            }
#pragma unroll
            for (int ni = 0; ni < 2; ni++) {
                int nb = n0 + ni * 8 + lr;
                unsigned b[2];
                b[0] = Bs[nb * 260 + kc + k0 + lc];
                b[1] = Bs[nb * 260 + kc + k0 + lc + 4];
#pragma unroll
                for (int mi = 0; mi < 2; mi++) mma_tf32(acc[mi][ni], a[mi], b);
            }
        }
    }

#pragma unroll
    for (int ni = 0; ni < 2; ni++) {
        int col = n0 + ni * 8 + 2 * lc;
        float2 bb = *(const float2*)(b2 + col);
#pragma unroll
        for (int mi = 0; mi < 2; mi++) {
            long r = row0 + m0 + mi * 16 + lr;
            float2* p0 = (float2*)(x + r * 64 + col);
            float2* p1 = (float2*)(x + (r + 8) * 64 + col);
            float2 r0 = *p0, r1 = *p1;
            r0.x += acc[mi][ni][0] + bb.x;
            r0.y += acc[mi][ni][1] + bb.y;
            r1.x += acc[mi][ni][2] + bb.x;
            r1.y += acc[mi][ni][3] + bb.y;
            *p0 = r0;
            *p1 = r1;
        }
    }
}

// ---------------------------------------------------------------------------
// Fused attention + Wo + bias + residual (fp32, unchanged from R2).
// ---------------------------------------------------------------------------
__global__ __launch_bounds__(256) void attnwo_kernel(
    const float* __restrict__ q, const float* __restrict__ k,
    const float* __restrict__ v, const float* __restrict__ wo,
    const float* __restrict__ bo, float* __restrict__ x) {
    extern __shared__ float smem[];
    float4* ks4 = (float4*)smem;          // [128*16]
    float4* vs4 = ks4 + 2048;             // [128*16]
    float4* wo4 = vs4 + 2048;             // [64*16]
    float* ao = (float*)(wo4 + 1024);     // [128][65]

    const int tid = threadIdx.x;
    const long base = (long)blockIdx.x * 128 * 64;

    {
        int row = tid >> 1, half = (tid & 1) * 8;
        const float4* kg = (const float4*)(k + base) + row * 16 + half;
        const float4* vg = (const float4*)(v + base) + row * 16 + half;
        float4* kd = ks4 + row * 16 + half;
        float4* vd = vs4 + row * 16 + half;
#pragma unroll
        for (int i = 0; i < 8; i++) { kd[i] = kg[i]; vd[i] = vg[i]; }
    }
    {
        const float4* wg = (const float4*)wo;
#pragma unroll
        for (int i = 0; i < 4; i++) wo4[tid + i * 256] = wg[tid + i * 256];
    }

    const int h = tid >> 5, g = tid & 31;
    const float scale = 0.35355339059327373f;
    float4 q0[4], q1[4];
#pragma unroll
    for (int i = 0; i < 4; i++) {
        int t = g + 32 * i;
        const float4* qg = (const float4*)(q + base + (long)t * 64 + h * 8);
        float4 a = qg[0], bq = qg[1];
        a.x *= scale; a.y *= scale; a.z *= scale; a.w *= scale;
        bq.x *= scale; bq.y *= scale; bq.z *= scale; bq.w *= scale;
        q0[i] = a; q1[i] = bq;
    }
    float acc[4][8];
    float l[4] = {0.f, 0.f, 0.f, 0.f};
#pragma unroll
    for (int i = 0; i < 4; i++)
#pragma unroll
        for (int d = 0; d < 8; d++) acc[i][d] = 0.0f;

    __syncthreads();

    const float4* kp = ks4 + h * 2;
    const float4* vp = vs4 + h * 2;
#pragma unroll 2
    for (int j = 0; j < 128; j++) {
        float4 k0 = kp[j * 16], k1 = kp[j * 16 + 1];
        float4 v0 = vp[j * 16], v1 = vp[j * 16 + 1];
#pragma unroll
        for (int i = 0; i < 4; i++) {
            float s = q0[i].x * k0.x + q0[i].y * k0.y + q0[i].z * k0.z +
                      q0[i].w * k0.w + q1[i].x * k1.x + q1[i].y * k1.y +
                      q1[i].z * k1.z + q1[i].w * k1.w;
            float p = (j <= g + 32 * i) ? __expf(s) : 0.0f;
            l[i] += p;
            acc[i][0] += p * v0.x; acc[i][1] += p * v0.y;
            acc[i][2] += p * v0.z; acc[i][3] += p * v0.w;
            acc[i][4] += p * v1.x; acc[i][5] += p * v1.y;
            acc[i][6] += p * v1.z; acc[i][7] += p * v1.w;
        }
    }
#pragma unroll
    for (int i = 0; i < 4; i++) {
        float inv = 1.0f / l[i];
        int t = g + 32 * i;
        float* aop = ao + t * 65 + h * 8;
#pragma unroll
        for (int d = 0; d < 8; d++) aop[d] = acc[i][d] * inv;
    }
    __syncthreads();

    const int ty = tid >> 4, tx = tid & 15;
    float oacc[8][4];
#pragma unroll
    for (int i = 0; i < 8; i++)
#pragma unroll
        for (int j = 0; j < 4; j++) oacc[i][j] = 0.0f;
#pragma unroll 4
    for (int kk = 0; kk < 64; kk++) {
        float4 bw = wo4[kk * 16 + tx];
#pragma unroll
        for (int i = 0; i < 8; i++) {
            float a = ao[(ty * 8 + i) * 65 + kk];
            oacc[i][0] += a * bw.x; oacc[i][1] += a * bw.y;
            oacc[i][2] += a * bw.z; oacc[i][3] += a * bw.w;
        }
    }
    float4 bb = ((const float4*)bo)[tx];
#pragma unroll
    for (int i = 0; i < 8; i++) {
        float4* xp = (float4*)(x + base + (long)(ty * 8 + i) * 64) + tx;
        float4 rv = *xp;
        float4 o;
        o.x = oacc[i][0] + bb.x + rv.x;
        o.y = oacc[i][1] + bb.y + rv.y;
        o.z = oacc[i][2] + bb.z + rv.z;
        o.w = oacc[i][3] + bb.w + rv.w;
        *xp = o;
    }
}

// ---------------------------------------------------------------------------
// Fused LNf + LM head + per-token loss (unchanged).
// ---------------------------------------------------------------------------
__global__ __launch_bounds__(520) void lmhead_kernel(
    const float* __restrict__ x, const float* __restrict__ lng,
    const float* __restrict__ lnb, const float* __restrict__ w,
    const float* __restrict__ bv, const int* __restrict__ tgt,
    float* __restrict__ logits, float* __restrict__ tokloss) {
    __shared__ float ws[64 * 65];
    __shared__ float xs[32][64];
    __shared__ float ls[32][65];
    int tid = threadIdx.x;
    long tok0 = (long)blockIdx.x * 32;
    for (int i = tid; i < 64 * 65; i += 520) ws[i] = w[i];
    if (tid < 512) {
        int warp = tid >> 5, lane = tid & 31;
        float gg0 = lng[lane], gg1 = lng[lane + 32];
        float bb0 = lnb[lane], bb1 = lnb[lane + 32];
#pragma unroll
        for (int rr = 0; rr < 2; rr++) {
            int r = warp * 2 + rr;
            float o0, o1;
            warp_ln(x + (tok0 + r) * 64, lane, gg0, gg1, bb0, bb1, o0, o1);
            xs[r][lane] = o0;
            xs[r][lane + 32] = o1;
        }
    }
    __syncthreads();

    int grp = tid / 65;
    int vv = tid - grp * 65;
    float wr[64];
#pragma unroll
    for (int d = 0; d < 64; d++) wr[d] = ws[d * 65 + vv];
    float bb = bv[vv];
    float acc[4] = {bb, bb, bb, bb};
#pragma unroll
    for (int d4 = 0; d4 < 16; d4++) {
        float4 xv[4];
#pragma unroll
        for (int u = 0; u < 4; u++)
            xv[u] = *reinterpret_cast<const float4*>(&xs[grp + 8 * u][d4 * 4]);
#pragma unroll
        for (int u = 0; u < 4; u++) {
            acc[u] += xv[u].x * wr[d4 * 4 + 0];
            acc[u] += xv[u].y * wr[d4 * 4 + 1];
            acc[u] += xv[u].z * wr[d4 * 4 + 2];
            acc[u] += xv[u].w * wr[d4 * 4 + 3];
        }
    }
#pragma unroll
    for (int u = 0; u < 4; u++) {
        logits[(tok0 + grp + 8 * u) * NVOCAB + vv] = acc[u];
        ls[grp + 8 * u][vv] = acc[u];
    }
    __syncthreads();

    if (tid < 512) {
        int warp = tid >> 5, lane = tid & 31;
#pragma unroll
        for (int rr = 0; rr < 2; rr++) {
            int t = warp * 2 + rr;
            float v0 = ls[t][lane];
            float v1 = ls[t][lane + 32];
            float v2 = (lane == 0) ? ls[t][64] : -1e30f;
            float mx = fmaxf(fmaxf(v0, v1), v2);
#pragma unroll
            for (int o = 16; o; o >>= 1)
                mx = fmaxf(mx, __shfl_xor_sync(0xffffffffu, mx, o));
            float se = expf(v0 - mx) + expf(v1 - mx) + expf(v2 - mx);
#pragma unroll
            for (int o = 16; o; o >>= 1) se += __shfl_xor_sync(0xffffffffu, se, o);
            if (lane == 0) {
                int tg = tgt[tok0 + t];
                tokloss[tok0 + t] = -(ls[t][tg] - mx - logf(se));
            }
        }
    }
}

__global__ void reduce_loss_kernel(const float* __restrict__ tokloss,
                                   float* __restrict__ out) {
    __shared__ double sm[1024];
    double s = 0.0;
    for (int i = threadIdx.x; i < NTOK; i += 1024) s += (double)tokloss[i];
    sm[threadIdx.x] = s;
    __syncthreads();
    for (int o = 512; o; o >>= 1) {
        if (threadIdx.x < o) sm[threadIdx.x] += sm[threadIdx.x + o];
        __syncthreads();
    }
    if (threadIdx.x == 0) out[0] = (float)(sm[0] / (double)NTOK);
}

// ---------------------------------------------------------------------------
extern "C" void kernel_launch(void* const* d_in, const int* in_sizes, int n_in,
                              void* d_out, int out_size) {
    const float* tok_emb = (const float*)d_in[0];
    const float* pos_emb = (const float*)d_in[1];
    const float* ln1_g   = (const float*)d_in[2];
    const float* ln1_b   = (const float*)d_in[3];
    const float* wq      = (const float*)d_in[4];
    const float* wk      = (const float*)d_in[5];
    const float* wv      = (const float*)d_in[6];
    const float* wo      = (const float*)d_in[7];
    const float* bo      = (const float*)d_in[8];
    const float* ln2_g   = (const float*)d_in[9];
    const float* ln2_b   = (const float*)d_in[10];
    const float* w1      = (const float*)d_in[11];
    const float* b1      = (const float*)d_in[12];
    const float* w2      = (const float*)d_in[13];
    const float* b2      = (const float*)d_in[14];
    const float* lnf_g   = (const float*)d_in[15];
    const float* lnf_b   = (const float*)d_in[16];
    const float* lm_w    = (const float*)d_in[17];
    const float* lm_b    = (const float*)d_in[18];
    const int*   idx     = (const int*)d_in[19];
    const int*   targets = (const int*)d_in[20];

    float *x, *q, *k, *v, *h1, *lg, *tl;
    cudaGetSymbolAddress((void**)&x,  g_x);
    cudaGetSymbolAddress((void**)&q,  g_q);
    cudaGetSymbolAddress((void**)&k,  g_k);
    cudaGetSymbolAddress((void**)&v,  g_v);
    cudaGetSymbolAddress((void**)&h1, g_h1);
    cudaGetSymbolAddress((void**)&lg, g_logits);
    cudaGetSymbolAddress((void**)&tl, g_tokloss);

    float* outp = (float*)d_out;
    const long LSZ = (long)NTOK * NVOCAB;
    float* logits = ((long)out_size >= LSZ) ? outp : lg;
    float* lossp;
    if ((long)out_size >= LSZ + 1)      lossp = outp + LSZ;
    else if (out_size == 1)             lossp = outp;
    else                                lossp = tl;

    const int LNQKV_SMEM = (128 + 192) * 68 * 4;                      // 87040
    const int FFN1_SMEM  = (128 + 256) * 68 * 4;                      // 104448
    const int FFN2_SMEM  = 128 * 68 * 4 + 64 * 260 * 4;               // 101376
    const int ATTN_SMEM  = (2048 + 2048 + 1024) * 16 + 128 * 65 * 4;  // 115200
    cudaFuncSetAttribute(lnqkv_tc,  cudaFuncAttributeMaxDynamicSharedMemorySize, LNQKV_SMEM);
    cudaFuncSetAttribute(lnffn1_tc, cudaFuncAttributeMaxDynamicSharedMemorySize, FFN1_SMEM);
    cudaFuncSetAttribute(ffn2_tc,   cudaFuncAttributeMaxDynamicSharedMemorySize, FFN2_SMEM);
    cudaFuncSetAttribute(attnwo_kernel, cudaFuncAttributeMaxDynamicSharedMemorySize, ATTN_SMEM);

    embed_kernel<<<(NTOK * 16) / 256, 256>>>(
        idx, (const float4*)tok_emb, (const float4*)pos_emb, (float4*)x);

    for (int l = 0; l < NLAYER; l++) {
        lnqkv_tc<<<NTOK / 128, 512, LNQKV_SMEM>>>(
            x, ln1_g + l * 64, ln1_b + l * 64,
            wq + (long)l * 4096, wk + (long)l * 4096, wv + (long)l * 4096,
            q, k, v);
        attnwo_kernel<<<4096, 256, ATTN_SMEM>>>(
            q, k, v, wo + (long)l * 4096, bo + l * 64, x);
        lnffn1_tc<<<NTOK / 128, 512, FFN1_SMEM>>>(
            x, ln2_g + l * 64, ln2_b + l * 64,
            w1 + (long)l * 64 * 256, b1 + l * 256, h1);
        ffn2_tc<<<NTOK / 128, 512, FFN2_SMEM>>>(
            h1, w2 + (long)l * 256 * 64, b2 + l * 64, x);
    }
    lmhead_kernel<<<NTOK / 32, 520>>>(x, lnf_g, lnf_b, lm_w, lm_b, targets,
                                      logits, tl);
    reduce_loss_kernel<<<1, 1024>>>(tl, lossp);
}

// round 4
// speedup vs baseline: 1.5486x; 1.1521x over previous
#include <cuda_runtime.h>
#include <cstdint>

// ---------------------------------------------------------------------------
// 3-layer transformer forward. B=4096, T=128, D=64, H=8, HD=8, DF=256, V=65.
// Round 4: two mega-kernels per layer; q/k/v and h1 never touch DRAM.
// ---------------------------------------------------------------------------

#define NTOK (4096 * 128)
#define TSEQ 128
#define DMODEL 64
#define NVOCAB 65
#define NHEAD 8
#define DFF 256
#define NLAYER 3

__device__ float g_x[(size_t)NTOK * DMODEL];
__device__ float g_logits[(size_t)NTOK * NVOCAB];
__device__ float g_tokloss[NTOK];

// ---------------------------------------------------------------------------
__device__ __forceinline__ unsigned f2tf(float f) {
    unsigned r;
    asm("cvt.rna.tf32.f32 %0, %1;" : "=r"(r) : "f"(f));
    return r;
}

__device__ __forceinline__ void mma_tf32(float* c, const unsigned* a,
                                         const unsigned* b) {
    asm volatile(
        "mma.sync.aligned.m16n8k8.row.col.f32.tf32.tf32.f32 "
        "{%0,%1,%2,%3},{%4,%5,%6,%7},{%8,%9},{%0,%1,%2,%3};"
        : "+f"(c[0]), "+f"(c[1]), "+f"(c[2]), "+f"(c[3])
        : "r"(a[0]), "r"(a[1]), "r"(a[2]), "r"(a[3]), "r"(b[0]), "r"(b[1]));
}

__device__ __forceinline__ void warp_ln(const float* __restrict__ rowp, int lane,
                                        float gg0, float gg1, float bb0, float bb1,
                                        float& o0, float& o1) {
    float a0 = rowp[lane];
    float a1 = rowp[lane + 32];
    float s = a0 + a1;
#pragma unroll
    for (int o = 16; o; o >>= 1) s += __shfl_xor_sync(0xffffffffu, s, o);
    float mu = s * (1.0f / 64.0f);
    float d0 = a0 - mu, d1 = a1 - mu;
    float vs = d0 * d0 + d1 * d1;
#pragma unroll
    for (int o = 16; o; o >>= 1) vs += __shfl_xor_sync(0xffffffffu, vs, o);
    float inv = rsqrtf(vs * (1.0f / 64.0f) + 1e-5f);
    o0 = d0 * inv * gg0 + bb0;
    o1 = d1 * inv * gg1 + bb1;
}

// ---------------------------------------------------------------------------
__global__ void embed_kernel(const int* __restrict__ idx,
                             const float4* __restrict__ te,
                             const float4* __restrict__ pe,
                             float4* __restrict__ x) {
    long i = (long)blockIdx.x * blockDim.x + threadIdx.x;
    if (i >= (long)NTOK * 16) return;
    long tok = i >> 4;
    int d4 = (int)(i & 15);
    int id = idx[tok];
    int t = (int)(tok & (TSEQ - 1));
    float4 a = te[(long)id * 16 + d4];
    float4 p = pe[(long)t * 16 + d4];
    float4 r;
    r.x = a.x + p.x; r.y = a.y + p.y; r.z = a.z + p.z; r.w = a.w + p.w;
    x[i] = r;
}

// ---------------------------------------------------------------------------
// Mega-kernel 1: LN1 + QKV (TF32 MMA) + attention + Wo + residual.
// One block = one batch (128 tokens, all heads). 512 threads.
// smem: As[128][68]u | Bs[192][68]u | qs/ks/vs[128][68]f  = 191488 B.
// As reused as ao[128][65]f, Bs reused as Wo[64][64]f for the epilogue.
// ---------------------------------------------------------------------------
__global__ __launch_bounds__(512) void layer_attn(
    const float* __restrict__ x, const float* __restrict__ lng,
    const float* __restrict__ lnb,
    const float* __restrict__ wq, const float* __restrict__ wk,
    const float* __restrict__ wv, const float* __restrict__ wo,
    const float* __restrict__ bo, float* __restrict__ xo) {
    extern __shared__ unsigned sm[];
    unsigned* As = sm;                       // [128][68]
    unsigned* Bs = sm + 128 * 68;            // [192][68]
    float* qs = (float*)(sm + 128 * 68 + 192 * 68);  // [128][68]
    float* ks = qs + 128 * 68;
    float* vs = ks + 128 * 68;

    const int tid = threadIdx.x;
    const long row0 = (long)blockIdx.x * 128;
    const long base = row0 * 64;

    // ---- stage Wqkv (transposed, tf32) + LN1 -> As ------------------------
    {
        const float* wsrc[3] = {wq, wk, wv};
#pragma unroll
        for (int s = 0; s < 3; s++) {
            const float* W = wsrc[s];
#pragma unroll
            for (int j = 0; j < 8; j++) {
                int e = tid + j * 512;
                int kk = e >> 6, n = e & 63;
                Bs[(s * 64 + n) * 68 + kk] = f2tf(W[e]);
            }
        }
    }
    {
        int warp = tid >> 5, lane = tid & 31;
        float gg0 = lng[lane], gg1 = lng[lane + 32];
        float bb0 = lnb[lane], bb1 = lnb[lane + 32];
        for (int r = warp; r < 128; r += 16) {
            float o0, o1;
            warp_ln(x + (row0 + r) * 64, lane, gg0, gg1, bb0, bb1, o0, o1);
            As[r * 68 + lane] = f2tf(o0);
            As[r * 68 + lane + 32] = f2tf(o1);
        }
    }
    __syncthreads();

    // ---- QKV MMA (128x192x64) -> qs/ks/vs smem ----------------------------
    const int wid = tid >> 5, lane = tid & 31;
    {
        const int wm = wid >> 2, wn = wid & 3;
        const int m0 = wm * 32, n0 = wn * 48;
        const int lr = lane >> 2, lc = lane & 3;
        float acc[2][6][4];
#pragma unroll
        for (int mi = 0; mi < 2; mi++)
#pragma unroll
            for (int ni = 0; ni < 6; ni++)
#pragma unroll
                for (int e = 0; e < 4; e++) acc[mi][ni][e] = 0.0f;
#pragma unroll
        for (int k0 = 0; k0 < 64; k0 += 8) {
            unsigned a[2][4];
#pragma unroll
            for (int mi = 0; mi < 2; mi++) {
                int rb = m0 + mi * 16 + lr;
                a[mi][0] = As[rb * 68 + k0 + lc];
                a[mi][1] = As[(rb + 8) * 68 + k0 + lc];
                a[mi][2] = As[rb * 68 + k0 + lc + 4];
                a[mi][3] = As[(rb + 8) * 68 + k0 + lc + 4];
            }
#pragma unroll
            for (int ni = 0; ni < 6; ni++) {
                int nb = n0 + ni * 8 + lr;
                unsigned b[2];
                b[0] = Bs[nb * 68 + k0 + lc];
                b[1] = Bs[nb * 68 + k0 + lc + 4];
#pragma unroll
                for (int mi = 0; mi < 2; mi++) mma_tf32(acc[mi][ni], a[mi], b);
            }
        }
        float* bufs[3] = {qs, ks, vs};
#pragma unroll
        for (int ni = 0; ni < 6; ni++) {
            int cg = n0 + ni * 8;
            float* buf = bufs[cg >> 6];
            int col = (cg & 63) + 2 * lc;
#pragma unroll
            for (int mi = 0; mi < 2; mi++) {
                int r = m0 + mi * 16 + lr;
                *(float2*)(buf + r * 68 + col) =
                    make_float2(acc[mi][ni][0], acc[mi][ni][1]);
                *(float2*)(buf + (r + 8) * 68 + col) =
                    make_float2(acc[mi][ni][2], acc[mi][ni][3]);
            }
        }
    }
    __syncthreads();

    // ---- attention: 512 thr, thread = (half, head, lane); 2 queries -------
    float* ao = (float*)As;            // [128][65]
    float* wos = (float*)Bs;           // [64][64]
#pragma unroll
    for (int j = 0; j < 8; j++) wos[tid + j * 512] = wo[tid + j * 512];
    {
        const int h = (tid >> 5) & 7, g = tid & 31, half = tid >> 8;
        const float scale = 0.35355339059327373f;
        float4 q0[2], q1[2];
        int tq[2];
#pragma unroll
        for (int i = 0; i < 2; i++) {
            tq[i] = g + 32 * (half * 2 + i);
            const float4* qp = (const float4*)(qs + tq[i] * 68 + h * 8);
            float4 a = qp[0], b = qp[1];
            a.x *= scale; a.y *= scale; a.z *= scale; a.w *= scale;
            b.x *= scale; b.y *= scale; b.z *= scale; b.w *= scale;
            q0[i] = a; q1[i] = b;
        }
        float acc[2][8], l[2] = {0.f, 0.f};
#pragma unroll
        for (int i = 0; i < 2; i++)
#pragma unroll
            for (int d = 0; d < 8; d++) acc[i][d] = 0.0f;

        const float4* kp = (const float4*)(ks + h * 8);
        const float4* vp = (const float4*)(vs + h * 8);
#pragma unroll 4
        for (int j = 0; j < 128; j++) {
            float4 k0 = kp[j * 17], k1 = kp[j * 17 + 1];
            float4 v0 = vp[j * 17], v1 = vp[j * 17 + 1];
#pragma unroll
            for (int i = 0; i < 2; i++) {
                float s = q0[i].x * k0.x + q0[i].y * k0.y + q0[i].z * k0.z +
                          q0[i].w * k0.w + q1[i].x * k1.x + q1[i].y * k1.y +
                          q1[i].z * k1.z + q1[i].w * k1.w;
                float p = (j <= tq[i]) ? __expf(s) : 0.0f;
                l[i] += p;
                acc[i][0] += p * v0.x; acc[i][1] += p * v0.y;
                acc[i][2] += p * v0.z; acc[i][3] += p * v0.w;
                acc[i][4] += p * v1.x; acc[i][5] += p * v1.y;
                acc[i][6] += p * v1.z; acc[i][7] += p * v1.w;
            }
        }
        __syncthreads();   // As free (MMA done); safe to write ao
#pragma unroll
        for (int i = 0; i < 2; i++) {
            float inv = 1.0f / l[i];
            float* aop = ao + tq[i] * 65 + h * 8;
#pragma unroll
            for (int d = 0; d < 8; d++) aop[d] = acc[i][d] * inv;
        }
    }
    __syncthreads();

    // ---- Wo GEMM + bias + residual ----------------------------------------
    {
        const int ty = tid >> 4, tx = tid & 15;  // 4 rows x 4 cols per thread
        const float4* wo4 = (const float4*)wos;
        float oacc[4][4];
#pragma unroll
        for (int i = 0; i < 4; i++)
#pragma unroll
            for (int j = 0; j < 4; j++) oacc[i][j] = 0.0f;
#pragma unroll 4
        for (int kk = 0; kk < 64; kk++) {
            float4 bw = wo4[kk * 16 + tx];
#pragma unroll
            for (int i = 0; i < 4; i++) {
                float a = ao[(ty * 4 + i) * 65 + kk];
                oacc[i][0] += a * bw.x; oacc[i][1] += a * bw.y;
                oacc[i][2] += a * bw.z; oacc[i][3] += a * bw.w;
            }
        }
        float4 bb = ((const float4*)bo)[tx];
#pragma unroll
        for (int i = 0; i < 4; i++) {
            float4* xp = (float4*)(xo + base + (long)(ty * 4 + i) * 64) + tx;
            float4 rv = *xp;
            rv.x += oacc[i][0] + bb.x;
            rv.y += oacc[i][1] + bb.y;
            rv.z += oacc[i][2] + bb.z;
            rv.w += oacc[i][3] + bb.w;
            *xp = rv;
        }
    }
}

// ---------------------------------------------------------------------------
// Mega-kernel 2: LN2 + W1 + bias + ReLU + W2 + bias + residual.
// Block = 128 tokens, 512 threads. h1 stays in registers; W2 GEMM consumes
// it via 4 smem-staged k-chunks (reusing the As region).
// smem: As[128][68]u | W1s[256][68]u | W2s[64][260]u = 171008 B.
// ---------------------------------------------------------------------------
__global__ __launch_bounds__(512) void layer_ffn(
    const float* __restrict__ x, const float* __restrict__ lng,
    const float* __restrict__ lnb, const float* __restrict__ w1,
    const float* __restrict__ b1, const float* __restrict__ w2,
    const float* __restrict__ b2, float* __restrict__ xo) {
    extern __shared__ unsigned sm[];
    unsigned* As = sm;                  // [128][68]
    unsigned* W1s = sm + 128 * 68;      // [256][68]
    unsigned* W2s = W1s + 256 * 68;     // [64][260]

    const int tid = threadIdx.x;
    const long row0 = (long)blockIdx.x * 128;

#pragma unroll
    for (int j = 0; j < 32; j++) {
        int e = tid + j * 512;
        W1s[(e & 255) * 68 + (e >> 8)] = f2tf(w1[e]);
    }
#pragma unroll
    for (int j = 0; j < 32; j++) {
        int e = tid + j * 512;
        W2s[(e & 63) * 260 + (e >> 6)] = f2tf(w2[e]);
    }
    {
        int warp = tid >> 5, lane = tid & 31;
        float gg0 = lng[lane], gg1 = lng[lane + 32];
        float bb0 = lnb[lane], bb1 = lnb[lane + 32];
        for (int r = warp; r < 128; r += 16) {
            float o0, o1;
            warp_ln(x + (row0 + r) * 64, lane, gg0, gg1, bb0, bb1, o0, o1);
            As[r * 68 + lane] = f2tf(o0);
            As[r * 68 + lane + 32] = f2tf(o1);
        }
    }
    __syncthreads();

    const int wid = tid >> 5, lane = tid & 31;
    const int wm = wid >> 2, wn = wid & 3;
    const int m0 = wm * 32;
    const int lr = lane >> 2, lc = lane & 3;

    // ---- GEMM1: h1 = LN2(x) @ W1, warp tile 32x64 -------------------------
    const int n0 = wn * 64;
    float acc[2][8][4];
#pragma unroll
    for (int mi = 0; mi < 2; mi++)
#pragma unroll
        for (int ni = 0; ni < 8; ni++)
#pragma unroll
            for (int e = 0; e < 4; e++) acc[mi][ni][e] = 0.0f;
#pragma unroll
    for (int k0 = 0; k0 < 64; k0 += 8) {
        unsigned a[2][4];
#pragma unroll
        for (int mi = 0; mi < 2; mi++) {
            int rb = m0 + mi * 16 + lr;
            a[mi][0] = As[rb * 68 + k0 + lc];
            a[mi][1] = As[(rb + 8) * 68 + k0 + lc];
            a[mi][2] = As[rb * 68 + k0 + lc + 4];
            a[mi][3] = As[(rb + 8) * 68 + k0 + lc + 4];
        }
#pragma unroll
        for (int ni = 0; ni < 8; ni++) {
            int nb = n0 + ni * 8 + lr;
            unsigned b[2];
            b[0] = W1s[nb * 68 + k0 + lc];
            b[1] = W1s[nb * 68 + k0 + lc + 4];
#pragma unroll
            for (int mi = 0; mi < 2; mi++) mma_tf32(acc[mi][ni], a[mi], b);
        }
    }

    // ---- GEMM2: out = relu(h1+b1) @ W2, staged k-chunks --------------------
    const int n02 = wn * 16;
    float acc2[2][2][4];
#pragma unroll
    for (int mi = 0; mi < 2; mi++)
#pragma unroll
        for (int ni = 0; ni < 2; ni++)
#pragma unroll
            for (int e = 0; e < 4; e++) acc2[mi][ni][e] = 0.0f;

#pragma unroll
    for (int kc = 0; kc < 4; kc++) {
        __syncthreads();
        if (wn == kc) {
#pragma unroll
            for (int ni = 0; ni < 8; ni++) {
                int coll = ni * 8 + 2 * lc;
                float2 bb = *(const float2*)(b1 + n0 + coll);
#pragma unroll
                for (int mi = 0; mi < 2; mi++) {
                    int r = m0 + mi * 16 + lr;
                    As[r * 68 + coll]       = f2tf(fmaxf(acc[mi][ni][0] + bb.x, 0.f));
                    As[r * 68 + coll + 1]   = f2tf(fmaxf(acc[mi][ni][1] + bb.y, 0.f));
                    As[(r + 8) * 68 + coll]     = f2tf(fmaxf(acc[mi][ni][2] + bb.x, 0.f));
                    As[(r + 8) * 68 + coll + 1] = f2tf(fmaxf(acc[mi][ni][3] + bb.y, 0.f));
                }
            }
        }
        __syncthreads();
#pragma unroll
        for (int k0 = 0; k0 < 64; k0 += 8) {
            unsigned a[2][4];
#pragma unroll
            for (int mi = 0; mi < 2; mi++) {
                int rb = m0 + mi * 16 + lr;
                a[mi][0] = As[rb * 68 + k0 + lc];
                a[mi][1] = As[(rb + 8) * 68 + k0 + lc];
                a[mi][2] = As[rb * 68 + k0 + lc + 4];
                a[mi][3] = As[(rb + 8) * 68 + k0 + lc + 4];
            }
#pragma unroll
            for (int ni = 0; ni < 2; ni++) {
                int nb = n02 + ni * 8 + lr;
                unsigned b[2];
                b[0] = W2s[nb * 260 + kc * 64 + k0 + lc];
                b[1] = W2s[nb * 260 + kc * 64 + k0 + lc + 4];
#pragma unroll
                for (int mi = 0; mi < 2; mi++) mma_tf32(acc2[mi][ni], a[mi], b);
            }
        }
    }

#pragma unroll
    for (int ni = 0; ni < 2; ni++) {
        int col = n02 + ni * 8 + 2 * lc;
        float2 bb = *(const float2*)(b2 + col);
#pragma unroll
        for (int mi = 0; mi < 2; mi++) {
            long r = row0 + m0 + mi * 16 + lr;
            float2* p0 = (float2*)(xo + r * 64 + col);
            float2* p1 = (float2*)(xo + (r + 8) * 64 + col);
            float2 r0 = *p0, r1 = *p1;
            r0.x += acc2[mi][ni][0] + bb.x;
            r0.y += acc2[mi][ni][1] + bb.y;
            r1.x += acc2[mi][ni][2] + bb.x;
            r1.y += acc2[mi][ni][3] + bb.y;
            *p0 = r0;
            *p1 = r1;
        }
    }
}

// ---------------------------------------------------------------------------
// Fused LNf + LM head + per-token loss (unchanged).
// ---------------------------------------------------------------------------
__global__ __launch_bounds__(520) void lmhead_kernel(
    const float* __restrict__ x, const float* __restrict__ lng,
    const float* __restrict__ lnb, const float* __restrict__ w,
    const float* __restrict__ bv, const int* __restrict__ tgt,
    float* __restrict__ logits, float* __restrict__ tokloss) {
    __shared__ float ws[64 * 65];
    __shared__ float xs[32][64];
    __shared__ float ls[32][65];
    int tid = threadIdx.x;
    long tok0 = (long)blockIdx.x * 32;
    for (int i = tid; i < 64 * 65; i += 520) ws[i] = w[i];
    if (tid < 512) {
        int warp = tid >> 5, lane = tid & 31;
        float gg0 = lng[lane], gg1 = lng[lane + 32];
        float bb0 = lnb[lane], bb1 = lnb[lane + 32];
#pragma unroll
        for (int rr = 0; rr < 2; rr++) {
            int r = warp * 2 + rr;
            float o0, o1;
            warp_ln(x + (tok0 + r) * 64, lane, gg0, gg1, bb0, bb1, o0, o1);
            xs[r][lane] = o0;
            xs[r][lane + 32] = o1;
        }
    }
    __syncthreads();

    int grp = tid / 65;
    int vv = tid - grp * 65;
    float wr[64];
#pragma unroll
    for (int d = 0; d < 64; d++) wr[d] = ws[d * 65 + vv];
    float bb = bv[vv];
    float acc[4] = {bb, bb, bb, bb};
#pragma unroll
    for (int d4 = 0; d4 < 16; d4++) {
        float4 xv[4];
#pragma unroll
        for (int u = 0; u < 4; u++)
            xv[u] = *reinterpret_cast<const float4*>(&xs[grp + 8 * u][d4 * 4]);
#pragma unroll
        for (int u = 0; u < 4; u++) {
            acc[u] += xv[u].x * wr[d4 * 4 + 0];
            acc[u] += xv[u].y * wr[d4 * 4 + 1];
            acc[u] += xv[u].z * wr[d4 * 4 + 2];
            acc[u] += xv[u].w * wr[d4 * 4 + 3];
        }
    }
#pragma unroll
    for (int u = 0; u < 4; u++) {
        logits[(tok0 + grp + 8 * u) * NVOCAB + vv] = acc[u];
        ls[grp + 8 * u][vv] = acc[u];
    }
    __syncthreads();

    if (tid < 512) {
        int warp = tid >> 5, lane = tid & 31;
#pragma unroll
        for (int rr = 0; rr < 2; rr++) {
            int t = warp * 2 + rr;
            float v0 = ls[t][lane];
            float v1 = ls[t][lane + 32];
            float v2 = (lane == 0) ? ls[t][64] : -1e30f;
            float mx = fmaxf(fmaxf(v0, v1), v2);
#pragma unroll
            for (int o = 16; o; o >>= 1)
                mx = fmaxf(mx, __shfl_xor_sync(0xffffffffu, mx, o));
            float se = expf(v0 - mx) + expf(v1 - mx) + expf(v2 - mx);
#pragma unroll
            for (int o = 16; o; o >>= 1) se += __shfl_xor_sync(0xffffffffu, se, o);
            if (lane == 0) {
                int tg = tgt[tok0 + t];
                tokloss[tok0 + t] = -(ls[t][tg] - mx - logf(se));
            }
        }
    }
}

__global__ void reduce_loss_kernel(const float* __restrict__ tokloss,
                                   float* __restrict__ out) {
    __shared__ double sm[1024];
    double s = 0.0;
    for (int i = threadIdx.x; i < NTOK; i += 1024) s += (double)tokloss[i];
    sm[threadIdx.x] = s;
    __syncthreads();
    for (int o = 512; o; o >>= 1) {
        if (threadIdx.x < o) sm[threadIdx.x] += sm[threadIdx.x + o];
        __syncthreads();
    }
    if (threadIdx.x == 0) out[0] = (float)(sm[0] / (double)NTOK);
}

// ---------------------------------------------------------------------------
extern "C" void kernel_launch(void* const* d_in, const int* in_sizes, int n_in,
                              void* d_out, int out_size) {
    const float* tok_emb = (const float*)d_in[0];
    const float* pos_emb = (const float*)d_in[1];
    const float* ln1_g   = (const float*)d_in[2];
    const float* ln1_b   = (const float*)d_in[3];
    const float* wq      = (const float*)d_in[4];
    const float* wk      = (const float*)d_in[5];
    const float* wv      = (const float*)d_in[6];
    const float* wo      = (const float*)d_in[7];
    const float* bo      = (const float*)d_in[8];
    const float* ln2_g   = (const float*)d_in[9];
    const float* ln2_b   = (const float*)d_in[10];
    const float* w1      = (const float*)d_in[11];
    const float* b1      = (const float*)d_in[12];
    const float* w2      = (const float*)d_in[13];
    const float* b2      = (const float*)d_in[14];
    const float* lnf_g   = (const float*)d_in[15];
    const float* lnf_b   = (const float*)d_in[16];
    const float* lm_w    = (const float*)d_in[17];
    const float* lm_b    = (const float*)d_in[18];
    const int*   idx     = (const int*)d_in[19];
    const int*   targets = (const int*)d_in[20];

    float *x, *lg, *tl;
    cudaGetSymbolAddress((void**)&x,  g_x);
    cudaGetSymbolAddress((void**)&lg, g_logits);
    cudaGetSymbolAddress((void**)&tl, g_tokloss);

    float* outp = (float*)d_out;
    const long LSZ = (long)NTOK * NVOCAB;
    float* logits = ((long)out_size >= LSZ) ? outp : lg;
    float* lossp;
    if ((long)out_size >= LSZ + 1)      lossp = outp + LSZ;
    else if (out_size == 1)             lossp = outp;
    else                                lossp = tl;

    const int ATTN_SMEM = (128 * 68 + 192 * 68 + 3 * 128 * 68) * 4;  // 191488
    const int FFN_SMEM  = (128 * 68 + 256 * 68 + 64 * 260) * 4;      // 171008
    cudaFuncSetAttribute(layer_attn, cudaFuncAttributeMaxDynamicSharedMemorySize, ATTN_SMEM);
    cudaFuncSetAttribute(layer_ffn,  cudaFuncAttributeMaxDynamicSharedMemorySize, FFN_SMEM);

    embed_kernel<<<(NTOK * 16) / 256, 256>>>(
        idx, (const float4*)tok_emb, (const float4*)pos_emb, (float4*)x);

    for (int l = 0; l < NLAYER; l++) {
        layer_attn<<<4096, 512, ATTN_SMEM>>>(
            x, ln1_g + l * 64, ln1_b + l * 64,
            wq + (long)l * 4096, wk + (long)l * 4096, wv + (long)l * 4096,
            wo + (long)l * 4096, bo + l * 64, x);
        layer_ffn<<<NTOK / 128, 512, FFN_SMEM>>>(
            x, ln2_g + l * 64, ln2_b + l * 64,
            w1 + (long)l * 64 * 256, b1 + l * 256,
            w2 + (long)l * 256 * 64, b2 + l * 64, x);
    }
    lmhead_kernel<<<NTOK / 32, 520>>>(x, lnf_g, lnf_b, lm_w, lm_b, targets,
                                      logits, tl);
    reduce_loss_kernel<<<1, 1024>>>(tl, lossp);
}

// round 5
// speedup vs baseline: 1.7391x; 1.1230x over previous
#include <cuda_runtime.h>
#include <cstdint>

// ---------------------------------------------------------------------------
// 3-layer transformer forward. B=4096, T=128, D=64, H=8, HD=8, DF=256, V=65.
// Round 5: causal-bounded complementary-pair attention + TF32 MMA for Wo.
// ---------------------------------------------------------------------------

#define NTOK (4096 * 128)
#define TSEQ 128
#define DMODEL 64
#define NVOCAB 65
#define NHEAD 8
#define DFF 256
#define NLAYER 3

__device__ float g_x[(size_t)NTOK * DMODEL];
__device__ float g_logits[(size_t)NTOK * NVOCAB];
__device__ float g_tokloss[NTOK];

// ---------------------------------------------------------------------------
__device__ __forceinline__ unsigned f2tf(float f) {
    unsigned r;
    asm("cvt.rna.tf32.f32 %0, %1;" : "=r"(r) : "f"(f));
    return r;
}

__device__ __forceinline__ void mma_tf32(float* c, const unsigned* a,
                                         const unsigned* b) {
    asm volatile(
        "mma.sync.aligned.m16n8k8.row.col.f32.tf32.tf32.f32 "
        "{%0,%1,%2,%3},{%4,%5,%6,%7},{%8,%9},{%0,%1,%2,%3};"
        : "+f"(c[0]), "+f"(c[1]), "+f"(c[2]), "+f"(c[3])
        : "r"(a[0]), "r"(a[1]), "r"(a[2]), "r"(a[3]), "r"(b[0]), "r"(b[1]));
}

__device__ __forceinline__ void warp_ln(const float* __restrict__ rowp, int lane,
                                        float gg0, float gg1, float bb0, float bb1,
                                        float& o0, float& o1) {
    float a0 = rowp[lane];
    float a1 = rowp[lane + 32];
    float s = a0 + a1;
#pragma unroll
    for (int o = 16; o; o >>= 1) s += __shfl_xor_sync(0xffffffffu, s, o);
    float mu = s * (1.0f / 64.0f);
    float d0 = a0 - mu, d1 = a1 - mu;
    float vs = d0 * d0 + d1 * d1;
#pragma unroll
    for (int o = 16; o; o >>= 1) vs += __shfl_xor_sync(0xffffffffu, vs, o);
    float inv = rsqrtf(vs * (1.0f / 64.0f) + 1e-5f);
    o0 = d0 * inv * gg0 + bb0;
    o1 = d1 * inv * gg1 + bb1;
}

// ---------------------------------------------------------------------------
__global__ void embed_kernel(const int* __restrict__ idx,
                             const float4* __restrict__ te,
                             const float4* __restrict__ pe,
                             float4* __restrict__ x) {
    long i = (long)blockIdx.x * blockDim.x + threadIdx.x;
    if (i >= (long)NTOK * 16) return;
    long tok = i >> 4;
    int d4 = (int)(i & 15);
    int id = idx[tok];
    int t = (int)(tok & (TSEQ - 1));
    float4 a = te[(long)id * 16 + d4];
    float4 p = pe[(long)t * 16 + d4];
    float4 r;
    r.x = a.x + p.x; r.y = a.y + p.y; r.z = a.z + p.z; r.w = a.w + p.w;
    x[i] = r;
}

// ---------------------------------------------------------------------------
// Mega-kernel 1: LN1 + QKV (MMA) + causal attention + Wo (MMA) + residual.
// One block = one batch (128 tokens, all heads). 512 threads.
// smem: As[128][68]u | Bs[192][68]u | qs/ks/vs[128][68]f  = 191488 B.
// As reused as ao (tf32) and Bs as Wo (tf32, col-major) for the epilogue.
// ---------------------------------------------------------------------------
__global__ __launch_bounds__(512) void layer_attn(
    const float* __restrict__ x, const float* __restrict__ lng,
    const float* __restrict__ lnb,
    const float* __restrict__ wq, const float* __restrict__ wk,
    const float* __restrict__ wv, const float* __restrict__ wo,
    const float* __restrict__ bo, float* __restrict__ xo) {
    extern __shared__ unsigned sm[];
    unsigned* As = sm;                       // [128][68]
    unsigned* Bs = sm + 128 * 68;            // [192][68]
    float* qs = (float*)(sm + 128 * 68 + 192 * 68);  // [128][68]
    float* ks = qs + 128 * 68;
    float* vs = ks + 128 * 68;

    const int tid = threadIdx.x;
    const long row0 = (long)blockIdx.x * 128;
    const long base = row0 * 64;

    // ---- stage Wqkv (transposed, tf32) + LN1 -> As ------------------------
    {
        const float* wsrc[3] = {wq, wk, wv};
#pragma unroll
        for (int s = 0; s < 3; s++) {
            const float* W = wsrc[s];
#pragma unroll
            for (int j = 0; j < 8; j++) {
                int e = tid + j * 512;
                int kk = e >> 6, n = e & 63;
                Bs[(s * 64 + n) * 68 + kk] = f2tf(W[e]);
            }
        }
    }
    {
        int warp = tid >> 5, lane = tid & 31;
        float gg0 = lng[lane], gg1 = lng[lane + 32];
        float bb0 = lnb[lane], bb1 = lnb[lane + 32];
        for (int r = warp; r < 128; r += 16) {
            float o0, o1;
            warp_ln(x + (row0 + r) * 64, lane, gg0, gg1, bb0, bb1, o0, o1);
            As[r * 68 + lane] = f2tf(o0);
            As[r * 68 + lane + 32] = f2tf(o1);
        }
    }
    __syncthreads();

    // ---- QKV MMA (128x192x64) -> qs/ks/vs smem ----------------------------
    const int wid = tid >> 5, lane = tid & 31;
    const int lr = lane >> 2, lc = lane & 3;
    {
        const int wm = wid >> 2, wn = wid & 3;
        const int m0 = wm * 32, n0 = wn * 48;
        float acc[2][6][4];
#pragma unroll
        for (int mi = 0; mi < 2; mi++)
#pragma unroll
            for (int ni = 0; ni < 6; ni++)
#pragma unroll
                for (int e = 0; e < 4; e++) acc[mi][ni][e] = 0.0f;
#pragma unroll
        for (int k0 = 0; k0 < 64; k0 += 8) {
            unsigned a[2][4];
#pragma unroll
            for (int mi = 0; mi < 2; mi++) {
                int rb = m0 + mi * 16 + lr;
                a[mi][0] = As[rb * 68 + k0 + lc];
                a[mi][1] = As[(rb + 8) * 68 + k0 + lc];
                a[mi][2] = As[rb * 68 + k0 + lc + 4];
                a[mi][3] = As[(rb + 8) * 68 + k0 + lc + 4];
            }
#pragma unroll
            for (int ni = 0; ni < 6; ni++) {
                int nb = n0 + ni * 8 + lr;
                unsigned b[2];
                b[0] = Bs[nb * 68 + k0 + lc];
                b[1] = Bs[nb * 68 + k0 + lc + 4];
#pragma unroll
                for (int mi = 0; mi < 2; mi++) mma_tf32(acc[mi][ni], a[mi], b);
            }
        }
        float* bufs[3] = {qs, ks, vs};
#pragma unroll
        for (int ni = 0; ni < 6; ni++) {
            int cg = n0 + ni * 8;
            float* buf = bufs[cg >> 6];
            int col = (cg & 63) + 2 * lc;
#pragma unroll
            for (int mi = 0; mi < 2; mi++) {
                int r = m0 + mi * 16 + lr;
                *(float2*)(buf + r * 68 + col) =
                    make_float2(acc[mi][ni][0], acc[mi][ni][1]);
                *(float2*)(buf + (r + 8) * 68 + col) =
                    make_float2(acc[mi][ni][2], acc[mi][ni][3]);
            }
        }
    }
    __syncthreads();

    // ---- stage Wo (col-major tf32) into Bs --------------------------------
#pragma unroll
    for (int j = 0; j < 8; j++) {
        int e = tid + j * 512;               // e = k*64 + n
        Bs[(e & 63) * 68 + (e >> 6)] = f2tf(wo[e]);
    }

    // ---- attention: complementary query pairs, causal-bounded loops -------
    {
        const int h = (tid >> 5) & 7, g = tid & 31, half = tid >> 8;
        const int tq0 = g + 64 * half;       // chunk count (tq0>>5)+1
        const int tq1 = 127 - tq0;
        const float scale = 0.35355339059327373f;
        const float4* kp = (const float4*)(ks + h * 8);
        const float4* vp = (const float4*)(vs + h * 8);

        int tqs[2] = {tq0, tq1};
#pragma unroll
        for (int i = 0; i < 2; i++) {
            const int tq = tqs[i];
            const float4* qp = (const float4*)(qs + tq * 68 + h * 8);
            float4 q0 = qp[0], q1 = qp[1];
            q0.x *= scale; q0.y *= scale; q0.z *= scale; q0.w *= scale;
            q1.x *= scale; q1.y *= scale; q1.z *= scale; q1.w *= scale;
            const int jmax = ((tq >> 5) + 1) << 5;   // warp-uniform
            float a0 = 0.f, a1 = 0.f, a2 = 0.f, a3 = 0.f;
            float a4 = 0.f, a5 = 0.f, a6 = 0.f, a7 = 0.f;
            float l = 0.0f;
#pragma unroll 4
            for (int j = 0; j < jmax; j++) {
                float4 k0 = kp[j * 17], k1 = kp[j * 17 + 1];
                float4 v0 = vp[j * 17], v1 = vp[j * 17 + 1];
                float s = q0.x * k0.x + q0.y * k0.y + q0.z * k0.z +
                          q0.w * k0.w + q1.x * k1.x + q1.y * k1.y +
                          q1.z * k1.z + q1.w * k1.w;
                float p = (j <= tq) ? __expf(s) : 0.0f;
                l += p;
                a0 += p * v0.x; a1 += p * v0.y; a2 += p * v0.z; a3 += p * v0.w;
                a4 += p * v1.x; a5 += p * v1.y; a6 += p * v1.z; a7 += p * v1.w;
            }
            float inv = 1.0f / l;
            unsigned* aop = As + tq * 68 + h * 8;
            aop[0] = f2tf(a0 * inv); aop[1] = f2tf(a1 * inv);
            aop[2] = f2tf(a2 * inv); aop[3] = f2tf(a3 * inv);
            aop[4] = f2tf(a4 * inv); aop[5] = f2tf(a5 * inv);
            aop[6] = f2tf(a6 * inv); aop[7] = f2tf(a7 * inv);
        }
    }
    __syncthreads();

    // ---- Wo MMA (128x64x64) + bias + residual ------------------------------
    {
        const int wm = wid >> 2, wn = wid & 3;
        const int m0 = wm * 32, n0 = wn * 16;
        float acc[2][2][4];
#pragma unroll
        for (int mi = 0; mi < 2; mi++)
#pragma unroll
            for (int ni = 0; ni < 2; ni++)
#pragma unroll
                for (int e = 0; e < 4; e++) acc[mi][ni][e] = 0.0f;
#pragma unroll
        for (int k0 = 0; k0 < 64; k0 += 8) {
            unsigned a[2][4];
#pragma unroll
            for (int mi = 0; mi < 2; mi++) {
                int rb = m0 + mi * 16 + lr;
                a[mi][0] = As[rb * 68 + k0 + lc];
                a[mi][1] = As[(rb + 8) * 68 + k0 + lc];
                a[mi][2] = As[rb * 68 + k0 + lc + 4];
                a[mi][3] = As[(rb + 8) * 68 + k0 + lc + 4];
            }
#pragma unroll
            for (int ni = 0; ni < 2; ni++) {
                int nb = n0 + ni * 8 + lr;
                unsigned b[2];
                b[0] = Bs[nb * 68 + k0 + lc];
                b[1] = Bs[nb * 68 + k0 + lc + 4];
#pragma unroll
                for (int mi = 0; mi < 2; mi++) mma_tf32(acc[mi][ni], a[mi], b);
            }
        }
#pragma unroll
        for (int ni = 0; ni < 2; ni++) {
            int col = n0 + ni * 8 + 2 * lc;
            float2 bb = *(const float2*)(bo + col);
#pragma unroll
            for (int mi = 0; mi < 2; mi++) {
                long r = row0 + m0 + mi * 16 + lr;
                float2* p0 = (float2*)(xo + r * 64 + col);
                float2* p1 = (float2*)(xo + (r + 8) * 64 + col);
                float2 r0 = *p0, r1 = *p1;
                r0.x += acc[mi][ni][0] + bb.x;
                r0.y += acc[mi][ni][1] + bb.y;
                r1.x += acc[mi][ni][2] + bb.x;
                r1.y += acc[mi][ni][3] + bb.y;
                *p0 = r0;
                *p1 = r1;
            }
        }
    }
}

// ---------------------------------------------------------------------------
// Mega-kernel 2: LN2 + W1 + bias + ReLU + W2 + bias + residual (unchanged).
// ---------------------------------------------------------------------------
__global__ __launch_bounds__(512) void layer_ffn(
    const float* __restrict__ x, const float* __restrict__ lng,
    const float* __restrict__ lnb, const float* __restrict__ w1,
    const float* __restrict__ b1, const float* __restrict__ w2,
    const float* __restrict__ b2, float* __restrict__ xo) {
    extern __shared__ unsigned sm[];
    unsigned* As = sm;                  // [128][68]
    unsigned* W1s = sm + 128 * 68;      // [256][68]
    unsigned* W2s = W1s + 256 * 68;     // [64][260]

    const int tid = threadIdx.x;
    const long row0 = (long)blockIdx.x * 128;

#pragma unroll
    for (int j = 0; j < 32; j++) {
        int e = tid + j * 512;
        W1s[(e & 255) * 68 + (e >> 8)] = f2tf(w1[e]);
    }
#pragma unroll
    for (int j = 0; j < 32; j++) {
        int e = tid + j * 512;
        W2s[(e & 63) * 260 + (e >> 6)] = f2tf(w2[e]);
    }
    {
        int warp = tid >> 5, lane = tid & 31;
        float gg0 = lng[lane], gg1 = lng[lane + 32];
        float bb0 = lnb[lane], bb1 = lnb[lane + 32];
        for (int r = warp; r < 128; r += 16) {
            float o0, o1;
            warp_ln(x + (row0 + r) * 64, lane, gg0, gg1, bb0, bb1, o0, o1);
            As[r * 68 + lane] = f2tf(o0);
            As[r * 68 + lane + 32] = f2tf(o1);
        }
    }
    __syncthreads();

    const int wid = tid >> 5, lane = tid & 31;
    const int wm = wid >> 2, wn = wid & 3;
    const int m0 = wm * 32;
    const int lr = lane >> 2, lc = lane & 3;

    const int n0 = wn * 64;
    float acc[2][8][4];
#pragma unroll
    for (int mi = 0; mi < 2; mi++)
#pragma unroll
        for (int ni = 0; ni < 8; ni++)
#pragma unroll
            for (int e = 0; e < 4; e++) acc[mi][ni][e] = 0.0f;
#pragma unroll
    for (int k0 = 0; k0 < 64; k0 += 8) {
        unsigned a[2][4];
#pragma unroll
        for (int mi = 0; mi < 2; mi++) {
            int rb = m0 + mi * 16 + lr;
            a[mi][0] = As[rb * 68 + k0 + lc];
            a[mi][1] = As[(rb + 8) * 68 + k0 + lc];
            a[mi][2] = As[rb * 68 + k0 + lc + 4];
            a[mi][3] = As[(rb + 8) * 68 + k0 + lc + 4];
        }
#pragma unroll
        for (int ni = 0; ni < 8; ni++) {
            int nb = n0 + ni * 8 + lr;
            unsigned b[2];
            b[0] = W1s[nb * 68 + k0 + lc];
            b[1] = W1s[nb * 68 + k0 + lc + 4];
#pragma unroll
            for (int mi = 0; mi < 2; mi++) mma_tf32(acc[mi][ni], a[mi], b);
        }
    }

    const int n02 = wn * 16;
    float acc2[2][2][4];
#pragma unroll
    for (int mi = 0; mi < 2; mi++)
#pragma unroll
        for (int ni = 0; ni < 2; ni++)
#pragma unroll
            for (int e = 0; e < 4; e++) acc2[mi][ni][e] = 0.0f;

#pragma unroll
    for (int kc = 0; kc < 4; kc++) {
        __syncthreads();
        if (wn == kc) {
#pragma unroll
            for (int ni = 0; ni < 8; ni++) {
                int coll = ni * 8 + 2 * lc;
                float2 bb = *(const float2*)(b1 + n0 + coll);
#pragma unroll
                for (int mi = 0; mi < 2; mi++) {
                    int r = m0 + mi * 16 + lr;
                    As[r * 68 + coll]       = f2tf(fmaxf(acc[mi][ni][0] + bb.x, 0.f));
                    As[r * 68 + coll + 1]   = f2tf(fmaxf(acc[mi][ni][1] + bb.y, 0.f));
                    As[(r + 8) * 68 + coll]     = f2tf(fmaxf(acc[mi][ni][2] + bb.x, 0.f));
                    As[(r + 8) * 68 + coll + 1] = f2tf(fmaxf(acc[mi][ni][3] + bb.y, 0.f));
                }
            }
        }
        __syncthreads();
#pragma unroll
        for (int k0 = 0; k0 < 64; k0 += 8) {
            unsigned a[2][4];
#pragma unroll
            for (int mi = 0; mi < 2; mi++) {
                int rb = m0 + mi * 16 + lr;
                a[mi][0] = As[rb * 68 + k0 + lc];
                a[mi][1] = As[(rb + 8) * 68 + k0 + lc];
                a[mi][2] = As[rb * 68 + k0 + lc + 4];
                a[mi][3] = As[(rb + 8) * 68 + k0 + lc + 4];
            }
#pragma unroll
            for (int ni = 0; ni < 2; ni++) {
                int nb = n02 + ni * 8 + lr;
                unsigned b[2];
                b[0] = W2s[nb * 260 + kc * 64 + k0 + lc];
                b[1] = W2s[nb * 260 + kc * 64 + k0 + lc + 4];
#pragma unroll
                for (int mi = 0; mi < 2; mi++) mma_tf32(acc2[mi][ni], a[mi], b);
            }
        }
    }

#pragma unroll
    for (int ni = 0; ni < 2; ni++) {
        int col = n02 + ni * 8 + 2 * lc;
        float2 bb = *(const float2*)(b2 + col);
#pragma unroll
        for (int mi = 0; mi < 2; mi++) {
            long r = row0 + m0 + mi * 16 + lr;
            float2* p0 = (float2*)(xo + r * 64 + col);
            float2* p1 = (float2*)(xo + (r + 8) * 64 + col);
            float2 r0 = *p0, r1 = *p1;
            r0.x += acc2[mi][ni][0] + bb.x;
            r0.y += acc2[mi][ni][1] + bb.y;
            r1.x += acc2[mi][ni][2] + bb.x;
            r1.y += acc2[mi][ni][3] + bb.y;
            *p0 = r0;
            *p1 = r1;
        }
    }
}

// ---------------------------------------------------------------------------
// Fused LNf + LM head + per-token loss (unchanged).
// ---------------------------------------------------------------------------
__global__ __launch_bounds__(520) void lmhead_kernel(
    const float* __restrict__ x, const float* __restrict__ lng,
    const float* __restrict__ lnb, const float* __restrict__ w,
    const float* __restrict__ bv, const int* __restrict__ tgt,
    float* __restrict__ logits, float* __restrict__ tokloss) {
    __shared__ float ws[64 * 65];
    __shared__ float xs[32][64];
    __shared__ float ls[32][65];
    int tid = threadIdx.x;
    long tok0 = (long)blockIdx.x * 32;
    for (int i = tid; i < 64 * 65; i += 520) ws[i] = w[i];
    if (tid < 512) {
        int warp = tid >> 5, lane = tid & 31;
        float gg0 = lng[lane], gg1 = lng[lane + 32];
        float bb0 = lnb[lane], bb1 = lnb[lane + 32];
#pragma unroll
        for (int rr = 0; rr < 2; rr++) {
            int r = warp * 2 + rr;
            float o0, o1;
            warp_ln(x + (tok0 + r) * 64, lane, gg0, gg1, bb0, bb1, o0, o1);
            xs[r][lane] = o0;
            xs[r][lane + 32] = o1;
        }
    }
    __syncthreads();

    int grp = tid / 65;
    int vv = tid - grp * 65;
    float wr[64];
#pragma unroll
    for (int d = 0; d < 64; d++) wr[d] = ws[d * 65 + vv];
    float bb = bv[vv];
    float acc[4] = {bb, bb, bb, bb};
#pragma unroll
    for (int d4 = 0; d4 < 16; d4++) {
        float4 xv[4];
#pragma unroll
        for (int u = 0; u < 4; u++)
            xv[u] = *reinterpret_cast<const float4*>(&xs[grp + 8 * u][d4 * 4]);
#pragma unroll
        for (int u = 0; u < 4; u++) {
            acc[u] += xv[u].x * wr[d4 * 4 + 0];
            acc[u] += xv[u].y * wr[d4 * 4 + 1];
            acc[u] += xv[u].z * wr[d4 * 4 + 2];
            acc[u] += xv[u].w * wr[d4 * 4 + 3];
        }
    }
#pragma unroll
    for (int u = 0; u < 4; u++) {
        logits[(tok0 + grp + 8 * u) * NVOCAB + vv] = acc[u];
        ls[grp + 8 * u][vv] = acc[u];
    }
    __syncthreads();

    if (tid < 512) {
        int warp = tid >> 5, lane = tid & 31;
#pragma unroll
        for (int rr = 0; rr < 2; rr++) {
            int t = warp * 2 + rr;
            float v0 = ls[t][lane];
            float v1 = ls[t][lane + 32];
            float v2 = (lane == 0) ? ls[t][64] : -1e30f;
            float mx = fmaxf(fmaxf(v0, v1), v2);
#pragma unroll
            for (int o = 16; o; o >>= 1)
                mx = fmaxf(mx, __shfl_xor_sync(0xffffffffu, mx, o));
            float se = expf(v0 - mx) + expf(v1 - mx) + expf(v2 - mx);
#pragma unroll
            for (int o = 16; o; o >>= 1) se += __shfl_xor_sync(0xffffffffu, se, o);
            if (lane == 0) {
                int tg = tgt[tok0 + t];
                tokloss[tok0 + t] = -(ls[t][tg] - mx - logf(se));
            }
        }
    }
}

__global__ void reduce_loss_kernel(const float* __restrict__ tokloss,
                                   float* __restrict__ out) {
    __shared__ double sm[1024];
    double s = 0.0;
    for (int i = threadIdx.x; i < NTOK; i += 1024) s += (double)tokloss[i];
    sm[threadIdx.x] = s;
    __syncthreads();
    for (int o = 512; o; o >>= 1) {
        if (threadIdx.x < o) sm[threadIdx.x] += sm[threadIdx.x + o];
        __syncthreads();
    }
    if (threadIdx.x == 0) out[0] = (float)(sm[0] / (double)NTOK);
}

// ---------------------------------------------------------------------------
extern "C" void kernel_launch(void* const* d_in, const int* in_sizes, int n_in,
                              void* d_out, int out_size) {
    const float* tok_emb = (const float*)d_in[0];
    const float* pos_emb = (const float*)d_in[1];
    const float* ln1_g   = (const float*)d_in[2];
    const float* ln1_b   = (const float*)d_in[3];
    const float* wq      = (const float*)d_in[4];
    const float* wk      = (const float*)d_in[5];
    const float* wv      = (const float*)d_in[6];
    const float* wo      = (const float*)d_in[7];
    const float* bo      = (const float*)d_in[8];
    const float* ln2_g   = (const float*)d_in[9];
    const float* ln2_b   = (const float*)d_in[10];
    const float* w1      = (const float*)d_in[11];
    const float* b1      = (const float*)d_in[12];
    const float* w2      = (const float*)d_in[13];
    const float* b2      = (const float*)d_in[14];
    const float* lnf_g   = (const float*)d_in[15];
    const float* lnf_b   = (const float*)d_in[16];
    const float* lm_w    = (const float*)d_in[17];
    const float* lm_b    = (const float*)d_in[18];
    const int*   idx     = (const int*)d_in[19];
    const int*   targets = (const int*)d_in[20];

    float *x, *lg, *tl;
    cudaGetSymbolAddress((void**)&x,  g_x);
    cudaGetSymbolAddress((void**)&lg, g_logits);
    cudaGetSymbolAddress((void**)&tl, g_tokloss);

    float* outp = (float*)d_out;
    const long LSZ = (long)NTOK * NVOCAB;
    float* logits = ((long)out_size >= LSZ) ? outp : lg;
    float* lossp;
    if ((long)out_size >= LSZ + 1)      lossp = outp + LSZ;
    else if (out_size == 1)             lossp = outp;
    else                                lossp = tl;

    const int ATTN_SMEM = (128 * 68 + 192 * 68 + 3 * 128 * 68) * 4;  // 191488
    const int FFN_SMEM  = (128 * 68 + 256 * 68 + 64 * 260) * 4;      // 171008
    cudaFuncSetAttribute(layer_attn, cudaFuncAttributeMaxDynamicSharedMemorySize, ATTN_SMEM);
    cudaFuncSetAttribute(layer_ffn,  cudaFuncAttributeMaxDynamicSharedMemorySize, FFN_SMEM);

    embed_kernel<<<(NTOK * 16) / 256, 256>>>(
        idx, (const float4*)tok_emb, (const float4*)pos_emb, (float4*)x);

    for (int l = 0; l < NLAYER; l++) {
        layer_attn<<<4096, 512, ATTN_SMEM>>>(
            x, ln1_g + l * 64, ln1_b + l * 64,
            wq + (long)l * 4096, wk + (long)l * 4096, wv + (long)l * 4096,
            wo + (long)l * 4096, bo + l * 64, x);
        layer_ffn<<<NTOK / 128, 512, FFN_SMEM>>>(
            x, ln2_g + l * 64, ln2_b + l * 64,
            w1 + (long)l * 64 * 256, b1 + l * 256,
            w2 + (long)l * 256 * 64, b2 + l * 64, x);
    }
    lmhead_kernel<<<NTOK / 32, 520>>>(x, lnf_g, lnf_b, lm_w, lm_b, targets,
                                      logits, tl);
    reduce_loss_kernel<<<1, 1024>>>(tl, lossp);
}

// round 6
// speedup vs baseline: 2.0770x; 1.1943x over previous
#include <cuda_runtime.h>
#include <cstdint>

// ---------------------------------------------------------------------------
// 3-layer transformer forward. B=4096, T=128, D=64, H=8, HD=8, DF=256, V=65.
// Round 6: full-MMA attention (S and PV on tensor cores, fragment-shuffle
// P handoff, causal tile skipping), MMA lm_head, two-stage loss reduce.
// ---------------------------------------------------------------------------

#define NTOK (4096 * 128)
#define TSEQ 128
#define DMODEL 64
#define NVOCAB 65
#define NHEAD 8
#define DFF 256
#define NLAYER 3

__device__ float g_x[(size_t)NTOK * DMODEL];
__device__ float g_logits[(size_t)NTOK * NVOCAB];
__device__ float g_tokloss[NTOK];
__device__ double g_partial[512];

// ---------------------------------------------------------------------------
__device__ __forceinline__ unsigned f2tf(float f) {
    unsigned r;
    asm("cvt.rna.tf32.f32 %0, %1;" : "=r"(r) : "f"(f));
    return r;
}

__device__ __forceinline__ void mma_tf32(float* c, const unsigned* a,
                                         const unsigned* b) {
    asm volatile(
        "mma.sync.aligned.m16n8k8.row.col.f32.tf32.tf32.f32 "
        "{%0,%1,%2,%3},{%4,%5,%6,%7},{%8,%9},{%0,%1,%2,%3};"
        : "+f"(c[0]), "+f"(c[1]), "+f"(c[2]), "+f"(c[3])
        : "r"(a[0]), "r"(a[1]), "r"(a[2]), "r"(a[3]), "r"(b[0]), "r"(b[1]));
}

__device__ __forceinline__ void warp_ln(const float* __restrict__ rowp, int lane,
                                        float gg0, float gg1, float bb0, float bb1,
                                        float& o0, float& o1) {
    float a0 = rowp[lane];
    float a1 = rowp[lane + 32];
    float s = a0 + a1;
#pragma unroll
    for (int o = 16; o; o >>= 1) s += __shfl_xor_sync(0xffffffffu, s, o);
    float mu = s * (1.0f / 64.0f);
    float d0 = a0 - mu, d1 = a1 - mu;
    float vs = d0 * d0 + d1 * d1;
#pragma unroll
    for (int o = 16; o; o >>= 1) vs += __shfl_xor_sync(0xffffffffu, vs, o);
    float inv = rsqrtf(vs * (1.0f / 64.0f) + 1e-5f);
    o0 = d0 * inv * gg0 + bb0;
    o1 = d1 * inv * gg1 + bb1;
}

// ---------------------------------------------------------------------------
__global__ void embed_kernel(const int* __restrict__ idx,
                             const float4* __restrict__ te,
                             const float4* __restrict__ pe,
                             float4* __restrict__ x) {
    long i = (long)blockIdx.x * blockDim.x + threadIdx.x;
    if (i >= (long)NTOK * 16) return;
    long tok = i >> 4;
    int d4 = (int)(i & 15);
    int id = idx[tok];
    int t = (int)(tok & (TSEQ - 1));
    float4 a = te[(long)id * 16 + d4];
    float4 p = pe[(long)t * 16 + d4];
    float4 r;
    r.x = a.x + p.x; r.y = a.y + p.y; r.z = a.z + p.z; r.w = a.w + p.w;
    x[i] = r;
}

// ---------------------------------------------------------------------------
// Mega-kernel 1: LN1 + QKV (MMA) + full-MMA causal attention + Wo (MMA) + res.
// One block = one batch (128 tokens). 512 threads.
// smem: As[128][68]u | Bs[192][68]u | qs/ks/vs[128][68]u(tf32) = 191488 B.
// ---------------------------------------------------------------------------
__global__ __launch_bounds__(512) void layer_attn(
    const float* __restrict__ x, const float* __restrict__ lng,
    const float* __restrict__ lnb,
    const float* __restrict__ wq, const float* __restrict__ wk,
    const float* __restrict__ wv, const float* __restrict__ wo,
    const float* __restrict__ bo, float* __restrict__ xo) {
    extern __shared__ unsigned sm[];
    unsigned* As = sm;                       // [128][68]
    unsigned* Bs = sm + 128 * 68;            // [192][68]
    unsigned* qs = sm + 128 * 68 + 192 * 68; // [128][68] tf32
    unsigned* ks = qs + 128 * 68;
    unsigned* vs = ks + 128 * 68;

    const int tid = threadIdx.x;
    const long row0 = (long)blockIdx.x * 128;

    // ---- stage Wqkv (transposed, tf32) + LN1 -> As ------------------------
    {
        const float* wsrc[3] = {wq, wk, wv};
#pragma unroll
        for (int s = 0; s < 3; s++) {
            const float* W = wsrc[s];
#pragma unroll
            for (int j = 0; j < 8; j++) {
                int e = tid + j * 512;
                int kk = e >> 6, n = e & 63;
                Bs[(s * 64 + n) * 68 + kk] = f2tf(W[e]);
            }
        }
    }
    {
        int warp = tid >> 5, lane = tid & 31;
        float gg0 = lng[lane], gg1 = lng[lane + 32];
        float bb0 = lnb[lane], bb1 = lnb[lane + 32];
        for (int r = warp; r < 128; r += 16) {
            float o0, o1;
            warp_ln(x + (row0 + r) * 64, lane, gg0, gg1, bb0, bb1, o0, o1);
            As[r * 68 + lane] = f2tf(o0);
            As[r * 68 + lane + 32] = f2tf(o1);
        }
    }
    __syncthreads();

    const int wid = tid >> 5, lane = tid & 31;
    const int lr = lane >> 2, lc = lane & 3;

    // ---- QKV MMA (128x192x64) -> qs/ks/vs (tf32, q pre-scaled) ------------
    {
        const int wm = wid >> 2, wn = wid & 3;
        const int m0 = wm * 32, n0 = wn * 48;
        float acc[2][6][4];
#pragma unroll
        for (int mi = 0; mi < 2; mi++)
#pragma unroll
            for (int ni = 0; ni < 6; ni++)
#pragma unroll
                for (int e = 0; e < 4; e++) acc[mi][ni][e] = 0.0f;
#pragma unroll
        for (int k0 = 0; k0 < 64; k0 += 8) {
            unsigned a[2][4];
#pragma unroll
            for (int mi = 0; mi < 2; mi++) {
                int rb = m0 + mi * 16 + lr;
                a[mi][0] = As[rb * 68 + k0 + lc];
                a[mi][1] = As[(rb + 8) * 68 + k0 + lc];
                a[mi][2] = As[rb * 68 + k0 + lc + 4];
                a[mi][3] = As[(rb + 8) * 68 + k0 + lc + 4];
            }
#pragma unroll
            for (int ni = 0; ni < 6; ni++) {
                int nb = n0 + ni * 8 + lr;
                unsigned b[2];
                b[0] = Bs[nb * 68 + k0 + lc];
                b[1] = Bs[nb * 68 + k0 + lc + 4];
#pragma unroll
                for (int mi = 0; mi < 2; mi++) mma_tf32(acc[mi][ni], a[mi], b);
            }
        }
        unsigned* bufs[3] = {qs, ks, vs};
#pragma unroll
        for (int ni = 0; ni < 6; ni++) {
            int cg = n0 + ni * 8;
            unsigned* buf = bufs[cg >> 6];
            float sc = (cg < 64) ? 0.35355339059327373f : 1.0f;  // 1/sqrt(8) on q
            int col = (cg & 63) + 2 * lc;
#pragma unroll
            for (int mi = 0; mi < 2; mi++) {
                int r = m0 + mi * 16 + lr;
                uint2 o0, o1;
                o0.x = f2tf(acc[mi][ni][0] * sc);
                o0.y = f2tf(acc[mi][ni][1] * sc);
                o1.x = f2tf(acc[mi][ni][2] * sc);
                o1.y = f2tf(acc[mi][ni][3] * sc);
                *(uint2*)(buf + r * 68 + col) = o0;
                *(uint2*)(buf + (r + 8) * 68 + col) = o1;
            }
        }
    }
    __syncthreads();

    // ---- stage Wo (col-major tf32) into freed Bs ---------------------------
#pragma unroll
    for (int j = 0; j < 8; j++) {
        int e = tid + j * 512;               // e = k*64 + n
        Bs[(e & 63) * 68 + (e >> 6)] = f2tf(wo[e]);
    }

    // ---- full-MMA attention: 4 iters x (2 heads x 8 M16-tiles) ------------
    // S = Q@K^T (one k-step), exp in fragments, rowsum in regs,
    // P fragments shuffled into A-operands for PV MMA. No syncs.
    {
        const int wq8 = wid & 7;
        const int hgrp = wid >> 3;
        const int src1 = (lane & 28) | (lc >> 1);
        const int src2 = src1 + 2;
        const int par = lc & 1;
#pragma unroll
        for (int it = 0; it < 4; it++) {
            const int h = 2 * it + hgrp;
            const int m = (wq8 + 2 * it) & 7;
            const int r0 = 16 * m + lr;
            unsigned aS[4];
            aS[0] = qs[(16 * m + lr) * 68 + 8 * h + lc];
            aS[1] = qs[(16 * m + lr + 8) * 68 + 8 * h + lc];
            aS[2] = qs[(16 * m + lr) * 68 + 8 * h + lc + 4];
            aS[3] = qs[(16 * m + lr + 8) * 68 + 8 * h + lc + 4];
            float rs0 = 0.f, rs1 = 0.f;
            float out[4] = {0.f, 0.f, 0.f, 0.f};
#pragma unroll
            for (int ni = 0; ni < 16; ni++) {
                if (ni <= 2 * m + 1) {            // causal tile skip (uniform)
                    float c[4] = {0.f, 0.f, 0.f, 0.f};
                    unsigned bK[2];
                    bK[0] = ks[(8 * ni + lr) * 68 + 8 * h + lc];
                    bK[1] = ks[(8 * ni + lr) * 68 + 8 * h + lc + 4];
                    mma_tf32(c, aS, bK);
                    if (8 * ni + 7 <= 16 * m) {   // fully unmasked tile
                        c[0] = __expf(c[0]); c[1] = __expf(c[1]);
                        c[2] = __expf(c[2]); c[3] = __expf(c[3]);
                    } else {                       // diagonal tile
                        int j0 = 8 * ni + 2 * lc, j1 = j0 + 1;
                        c[0] = (j0 <= r0) ? __expf(c[0]) : 0.f;
                        c[1] = (j1 <= r0) ? __expf(c[1]) : 0.f;
                        c[2] = (j0 <= r0 + 8) ? __expf(c[2]) : 0.f;
                        c[3] = (j1 <= r0 + 8) ? __expf(c[3]) : 0.f;
                    }
                    rs0 += c[0] + c[1];
                    rs1 += c[2] + c[3];
                    // shuffle P fragment -> A operand for PV
                    float t0 = __shfl_sync(0xffffffffu, c[0], src1);
                    float t1 = __shfl_sync(0xffffffffu, c[1], src1);
                    float t2 = __shfl_sync(0xffffffffu, c[2], src1);
                    float t3 = __shfl_sync(0xffffffffu, c[3], src1);
                    float u0 = __shfl_sync(0xffffffffu, c[0], src2);
                    float u1 = __shfl_sync(0xffffffffu, c[1], src2);
                    float u2 = __shfl_sync(0xffffffffu, c[2], src2);
                    float u3 = __shfl_sync(0xffffffffu, c[3], src2);
                    unsigned aP[4];
                    aP[0] = f2tf(par ? t1 : t0);
                    aP[1] = f2tf(par ? t3 : t2);
                    aP[2] = f2tf(par ? u1 : u0);
                    aP[3] = f2tf(par ? u3 : u2);
                    unsigned bV[2];
                    bV[0] = vs[(8 * ni + lc) * 68 + 8 * h + lr];
                    bV[1] = vs[(8 * ni + lc + 4) * 68 + 8 * h + lr];
                    mma_tf32(out, aP, bV);
                }
            }
            rs0 += __shfl_xor_sync(0xffffffffu, rs0, 1);
            rs0 += __shfl_xor_sync(0xffffffffu, rs0, 2);
            rs1 += __shfl_xor_sync(0xffffffffu, rs1, 1);
            rs1 += __shfl_xor_sync(0xffffffffu, rs1, 2);
            float inv0 = 1.0f / rs0, inv1 = 1.0f / rs1;
            unsigned* d0 = As + r0 * 68 + 8 * h + 2 * lc;
            unsigned* d1 = As + (r0 + 8) * 68 + 8 * h + 2 * lc;
            d0[0] = f2tf(out[0] * inv0); d0[1] = f2tf(out[1] * inv0);
            d1[0] = f2tf(out[2] * inv1); d1[1] = f2tf(out[3] * inv1);
        }
    }
    __syncthreads();

    // ---- Wo MMA (128x64x64) + bias + residual ------------------------------
    {
        const int wm = wid >> 2, wn = wid & 3;
        const int m0 = wm * 32, n0 = wn * 16;
        float acc[2][2][4];
#pragma unroll
        for (int mi = 0; mi < 2; mi++)
#pragma unroll
            for (int ni = 0; ni < 2; ni++)
#pragma unroll
                for (int e = 0; e < 4; e++) acc[mi][ni][e] = 0.0f;
#pragma unroll
        for (int k0 = 0; k0 < 64; k0 += 8) {
            unsigned a[2][4];
#pragma unroll
            for (int mi = 0; mi < 2; mi++) {
                int rb = m0 + mi * 16 + lr;
                a[mi][0] = As[rb * 68 + k0 + lc];
                a[mi][1] = As[(rb + 8) * 68 + k0 + lc];
                a[mi][2] = As[rb * 68 + k0 + lc + 4];
                a[mi][3] = As[(rb + 8) * 68 + k0 + lc + 4];
            }
#pragma unroll
            for (int ni = 0; ni < 2; ni++) {
                int nb = n0 + ni * 8 + lr;
                unsigned b[2];
                b[0] = Bs[nb * 68 + k0 + lc];
                b[1] = Bs[nb * 68 + k0 + lc + 4];
#pragma unroll
                for (int mi = 0; mi < 2; mi++) mma_tf32(acc[mi][ni], a[mi], b);
            }
        }
#pragma unroll
        for (int ni = 0; ni < 2; ni++) {
            int col = n0 + ni * 8 + 2 * lc;
            float2 bb = *(const float2*)(bo + col);
#pragma unroll
            for (int mi = 0; mi < 2; mi++) {
                long r = row0 + m0 + mi * 16 + lr;
                float2* p0 = (float2*)(xo + r * 64 + col);
                float2* p1 = (float2*)(xo + (r + 8) * 64 + col);
                float2 r0v = *p0, r1v = *p1;
                r0v.x += acc[mi][ni][0] + bb.x;
                r0v.y += acc[mi][ni][1] + bb.y;
                r1v.x += acc[mi][ni][2] + bb.x;
                r1v.y += acc[mi][ni][3] + bb.y;
                *p0 = r0v;
                *p1 = r1v;
            }
        }
    }
}

// ---------------------------------------------------------------------------
// Mega-kernel 2: LN2 + W1 + bias + ReLU + W2 + bias + residual (unchanged).
// ---------------------------------------------------------------------------
__global__ __launch_bounds__(512) void layer_ffn(
    const float* __restrict__ x, const float* __restrict__ lng,
    const float* __restrict__ lnb, const float* __restrict__ w1,
    const float* __restrict__ b1, const float* __restrict__ w2,
    const float* __restrict__ b2, float* __restrict__ xo) {
    extern __shared__ unsigned sm[];
    unsigned* As = sm;                  // [128][68]
    unsigned* W1s = sm + 128 * 68;      // [256][68]
    unsigned* W2s = W1s + 256 * 68;     // [64][260]

    const int tid = threadIdx.x;
    const long row0 = (long)blockIdx.x * 128;

#pragma unroll
    for (int j = 0; j < 32; j++) {
        int e = tid + j * 512;
        W1s[(e & 255) * 68 + (e >> 8)] = f2tf(w1[e]);
    }
#pragma unroll
    for (int j = 0; j < 32; j++) {
        int e = tid + j * 512;
        W2s[(e & 63) * 260 + (e >> 6)] = f2tf(w2[e]);
    }
    {
        int warp = tid >> 5, lane = tid & 31;
        float gg0 = lng[lane], gg1 = lng[lane + 32];
        float bb0 = lnb[lane], bb1 = lnb[lane + 32];
        for (int r = warp; r < 128; r += 16) {
            float o0, o1;
            warp_ln(x + (row0 + r) * 64, lane, gg0, gg1, bb0, bb1, o0, o1);
            As[r * 68 + lane] = f2tf(o0);
            As[r * 68 + lane + 32] = f2tf(o1);
        }
    }
    __syncthreads();

    const int wid = tid >> 5, lane = tid & 31;
    const int wm = wid >> 2, wn = wid & 3;
    const int m0 = wm * 32;
    const int lr = lane >> 2, lc = lane & 3;

    const int n0 = wn * 64;
    float acc[2][8][4];
#pragma unroll
    for (int mi = 0; mi < 2; mi++)
#pragma unroll
        for (int ni = 0; ni < 8; ni++)
#pragma unroll
            for (int e = 0; e < 4; e++) acc[mi][ni][e] = 0.0f;
#pragma unroll
    for (int k0 = 0; k0 < 64; k0 += 8) {
        unsigned a[2][4];
#pragma unroll
        for (int mi = 0; mi < 2; mi++) {
            int rb = m0 + mi * 16 + lr;
            a[mi][0] = As[rb * 68 + k0 + lc];
            a[mi][1] = As[(rb + 8) * 68 + k0 + lc];
            a[mi][2] = As[rb * 68 + k0 + lc + 4];
            a[mi][3] = As[(rb + 8) * 68 + k0 + lc + 4];
        }
#pragma unroll
        for (int ni = 0; ni < 8; ni++) {
            int nb = n0 + ni * 8 + lr;
            unsigned b[2];
            b[0] = W1s[nb * 68 + k0 + lc];
            b[1] = W1s[nb * 68 + k0 + lc + 4];
#pragma unroll
            for (int mi = 0; mi < 2; mi++) mma_tf32(acc[mi][ni], a[mi], b);
        }
    }

    const int n02 = wn * 16;
    float acc2[2][2][4];
#pragma unroll
    for (int mi = 0; mi < 2; mi++)
#pragma unroll
        for (int ni = 0; ni < 2; ni++)
#pragma unroll
            for (int e = 0; e < 4; e++) acc2[mi][ni][e] = 0.0f;

#pragma unroll
    for (int kc = 0; kc < 4; kc++) {
        __syncthreads();
        if (wn == kc) {
#pragma unroll
            for (int ni = 0; ni < 8; ni++) {
                int coll = ni * 8 + 2 * lc;
                float2 bb = *(const float2*)(b1 + n0 + coll);
#pragma unroll
                for (int mi = 0; mi < 2; mi++) {
                    int r = m0 + mi * 16 + lr;
                    As[r * 68 + coll]       = f2tf(fmaxf(acc[mi][ni][0] + bb.x, 0.f));
                    As[r * 68 + coll + 1]   = f2tf(fmaxf(acc[mi][ni][1] + bb.y, 0.f));
                    As[(r + 8) * 68 + coll]     = f2tf(fmaxf(acc[mi][ni][2] + bb.x, 0.f));
                    As[(r + 8) * 68 + coll + 1] = f2tf(fmaxf(acc[mi][ni][3] + bb.y, 0.f));
                }
            }
        }
        __syncthreads();
#pragma unroll
        for (int k0 = 0; k0 < 64; k0 += 8) {
            unsigned a[2][4];
#pragma unroll
            for (int mi = 0; mi < 2; mi++) {
                int rb = m0 + mi * 16 + lr;
                a[mi][0] = As[rb * 68 + k0 + lc];
                a[mi][1] = As[(rb + 8) * 68 + k0 + lc];
                a[mi][2] = As[rb * 68 + k0 + lc + 4];
                a[mi][3] = As[(rb + 8) * 68 + k0 + lc + 4];
            }
#pragma unroll
            for (int ni = 0; ni < 2; ni++) {
                int nb = n02 + ni * 8 + lr;
                unsigned b[2];
                b[0] = W2s[nb * 260 + kc * 64 + k0 + lc];
                b[1] = W2s[nb * 260 + kc * 64 + k0 + lc + 4];
#pragma unroll
                for (int mi = 0; mi < 2; mi++) mma_tf32(acc2[mi][ni], a[mi], b);
            }
        }
    }

#pragma unroll
    for (int ni = 0; ni < 2; ni++) {
        int col = n02 + ni * 8 + 2 * lc;
        float2 bb = *(const float2*)(b2 + col);
#pragma unroll
        for (int mi = 0; mi < 2; mi++) {
            long r = row0 + m0 + mi * 16 + lr;
            float2* p0 = (float2*)(xo + r * 64 + col);
            float2* p1 = (float2*)(xo + (r + 8) * 64 + col);
            float2 r0 = *p0, r1 = *p1;
            r0.x += acc2[mi][ni][0] + bb.x;
            r0.y += acc2[mi][ni][1] + bb.y;
            r1.x += acc2[mi][ni][2] + bb.x;
            r1.y += acc2[mi][ni][3] + bb.y;
            *p0 = r0;
            *p1 = r1;
        }
    }
}

// ---------------------------------------------------------------------------
// LNf + lm_head (TF32 MMA, V padded to 72) + coalesced logits + loss.
// Block = 128 tokens, 512 threads.
// smem: As[128][68]u | Bs[72][68]u | ls[128][66]f = 88192 B.
// ---------------------------------------------------------------------------
__global__ __launch_bounds__(512) void lmhead_v2(
    const float* __restrict__ x, const float* __restrict__ lng,
    const float* __restrict__ lnb, const float* __restrict__ w,
    const float* __restrict__ bv, const int* __restrict__ tgt,
    float* __restrict__ logits, float* __restrict__ tokloss) {
    extern __shared__ unsigned sm[];
    unsigned* As = sm;                  // [128][68]
    unsigned* Bs = sm + 128 * 68;       // [72][68]
    float* ls = (float*)(Bs + 72 * 68); // [128][66]

    const int tid = threadIdx.x;
    const long tok0 = (long)blockIdx.x * 128;

    if (tid < 7 * 68) Bs[65 * 68 + tid] = 0u;   // zero pad rows 65..71
#pragma unroll
    for (int j = 0; j < 9; j++) {
        int e = tid + j * 512;
        if (e < 65 * 64) {
            int n = e >> 6, k = e & 63;
            Bs[n * 68 + k] = f2tf(w[k * 65 + n]);
        }
    }
    {
        int warp = tid >> 5, lane = tid & 31;
        float gg0 = lng[lane], gg1 = lng[lane + 32];
        float bb0 = lnb[lane], bb1 = lnb[lane + 32];
        for (int r = warp; r < 128; r += 16) {
            float o0, o1;
            warp_ln(x + (tok0 + r) * 64, lane, gg0, gg1, bb0, bb1, o0, o1);
            As[r * 68 + lane] = f2tf(o0);
            As[r * 68 + lane + 32] = f2tf(o1);
        }
    }
    __syncthreads();

    const int wid = tid >> 5, lane = tid & 31;
    const int lr = lane >> 2, lc = lane & 3;
    const int m0 = (wid >> 1) * 16;
    const int nh = wid & 1;
    const int nt0 = nh ? 5 : 0, ntn = nh ? 4 : 5;

    float acc[5][4];
#pragma unroll
    for (int ni = 0; ni < 5; ni++)
#pragma unroll
        for (int e = 0; e < 4; e++) acc[ni][e] = 0.0f;

#pragma unroll
    for (int k0 = 0; k0 < 64; k0 += 8) {
        unsigned a[4];
        a[0] = As[(m0 + lr) * 68 + k0 + lc];
        a[1] = As[(m0 + lr + 8) * 68 + k0 + lc];
        a[2] = As[(m0 + lr) * 68 + k0 + lc + 4];
        a[3] = As[(m0 + lr + 8) * 68 + k0 + lc + 4];
#pragma unroll
        for (int ni = 0; ni < 5; ni++) {
            if (ni < ntn) {
                int nb = (nt0 + ni) * 8 + lr;
                unsigned b[2];
                b[0] = Bs[nb * 68 + k0 + lc];
                b[1] = Bs[nb * 68 + k0 + lc + 4];
                mma_tf32(acc[ni], a, b);
            }
        }
    }
#pragma unroll
    for (int ni = 0; ni < 5; ni++) {
        if (ni < ntn) {
            int col = (nt0 + ni) * 8 + 2 * lc;
            if (col < 65) {
                float b0 = bv[col];
                ls[(m0 + lr) * 66 + col] = acc[ni][0] + b0;
                ls[(m0 + lr + 8) * 66 + col] = acc[ni][2] + b0;
            }
            if (col + 1 < 65) {
                float b1 = bv[col + 1];
                ls[(m0 + lr) * 66 + col + 1] = acc[ni][1] + b1;
                ls[(m0 + lr + 8) * 66 + col + 1] = acc[ni][3] + b1;
            }
        }
    }
    __syncthreads();

    // coalesced logits write
    for (int i = tid; i < 128 * 65; i += 512) {
        int r = i / 65, c = i - r * 65;
        logits[tok0 * 65 + i] = ls[r * 66 + c];
    }
    // loss: 16 warps x 8 rows
    {
#pragma unroll
        for (int rr = 0; rr < 8; rr++) {
            int t = wid * 8 + rr;
            float v0 = ls[t * 66 + lane];
            float v1 = ls[t * 66 + lane + 32];
            float v2 = (lane == 0) ? ls[t * 66 + 64] : -1e30f;
            float mx = fmaxf(fmaxf(v0, v1), v2);
#pragma unroll
            for (int o = 16; o; o >>= 1)
                mx = fmaxf(mx, __shfl_xor_sync(0xffffffffu, mx, o));
            float se = expf(v0 - mx) + expf(v1 - mx) + expf(v2 - mx);
#pragma unroll
            for (int o = 16; o; o >>= 1) se += __shfl_xor_sync(0xffffffffu, se, o);
            if (lane == 0) {
                int tg = tgt[tok0 + t];
                tokloss[tok0 + t] = -(ls[t * 66 + tg] - mx - logf(se));
            }
        }
    }
}

// ---------------------------------------------------------------------------
// Two-stage deterministic mean reduction
// ---------------------------------------------------------------------------
__global__ void reduce1_kernel(const float* __restrict__ tl,
                               double* __restrict__ part) {
    __shared__ double smd[256];
    long base = (long)blockIdx.x * (NTOK / 512);
    double s = 0.0;
    for (int i = threadIdx.x; i < NTOK / 512; i += 256) s += (double)tl[base + i];
    smd[threadIdx.x] = s;
    __syncthreads();
    for (int o = 128; o; o >>= 1) {
        if (threadIdx.x < o) smd[threadIdx.x] += smd[threadIdx.x + o];
        __syncthreads();
    }
    if (threadIdx.x == 0) part[blockIdx.x] = smd[0];
}

__global__ void reduce2_kernel(const double* __restrict__ part,
                               float* __restrict__ out) {
    __shared__ double smd[512];
    smd[threadIdx.x] = part[threadIdx.x];
    __syncthreads();
    for (int o = 256; o; o >>= 1) {
        if (threadIdx.x < o) smd[threadIdx.x] += smd[threadIdx.x + o];
        __syncthreads();
    }
    if (threadIdx.x == 0) out[0] = (float)(smd[0] / (double)NTOK);
}

// ---------------------------------------------------------------------------
extern "C" void kernel_launch(void* const* d_in, const int* in_sizes, int n_in,
                              void* d_out, int out_size) {
    const float* tok_emb = (const float*)d_in[0];
    const float* pos_emb = (const float*)d_in[1];
    const float* ln1_g   = (const float*)d_in[2];
    const float* ln1_b   = (const float*)d_in[3];
    const float* wq      = (const float*)d_in[4];
    const float* wk      = (const float*)d_in[5];
    const float* wv      = (const float*)d_in[6];
    const float* wo      = (const float*)d_in[7];
    const float* bo      = (const float*)d_in[8];
    const float* ln2_g   = (const float*)d_in[9];
    const float* ln2_b   = (const float*)d_in[10];
    const float* w1      = (const float*)d_in[11];
    const float* b1      = (const float*)d_in[12];
    const float* w2      = (const float*)d_in[13];
    const float* b2      = (const float*)d_in[14];
    const float* lnf_g   = (const float*)d_in[15];
    const float* lnf_b   = (const float*)d_in[16];
    const float* lm_w    = (const float*)d_in[17];
    const float* lm_b    = (const float*)d_in[18];
    const int*   idx     = (const int*)d_in[19];
    const int*   targets = (const int*)d_in[20];

    float *x, *lg, *tl;
    double* part;
    cudaGetSymbolAddress((void**)&x,  g_x);
    cudaGetSymbolAddress((void**)&lg, g_logits);
    cudaGetSymbolAddress((void**)&tl, g_tokloss);
    cudaGetSymbolAddress((void**)&part, g_partial);

    float* outp = (float*)d_out;
    const long LSZ = (long)NTOK * NVOCAB;
    float* logits = ((long)out_size >= LSZ) ? outp : lg;
    float* lossp;
    if ((long)out_size >= LSZ + 1)      lossp = outp + LSZ;
    else if (out_size == 1)             lossp = outp;
    else                                lossp = tl;

    const int ATTN_SMEM = (128 * 68 + 192 * 68 + 3 * 128 * 68) * 4;  // 191488
    const int FFN_SMEM  = (128 * 68 + 256 * 68 + 64 * 260) * 4;      // 171008
    const int LMH_SMEM  = (128 * 68 + 72 * 68) * 4 + 128 * 66 * 4;   // 88192
    cudaFuncSetAttribute(layer_attn, cudaFuncAttributeMaxDynamicSharedMemorySize, ATTN_SMEM);
    cudaFuncSetAttribute(layer_ffn,  cudaFuncAttributeMaxDynamicSharedMemorySize, FFN_SMEM);
    cudaFuncSetAttribute(lmhead_v2,  cudaFuncAttributeMaxDynamicSharedMemorySize, LMH_SMEM);

    embed_kernel<<<(NTOK * 16) / 256, 256>>>(
        idx, (const float4*)tok_emb, (const float4*)pos_emb, (float4*)x);

    for (int l = 0; l < NLAYER; l++) {
        layer_attn<<<4096, 512, ATTN_SMEM>>>(
            x, ln1_g + l * 64, ln1_b + l * 64,
            wq + (long)l * 4096, wk + (long)l * 4096, wv + (long)l * 4096,
            wo + (long)l * 4096, bo + l * 64, x);
        layer_ffn<<<NTOK / 128, 512, FFN_SMEM>>>(
            x, ln2_g + l * 64, ln2_b + l * 64,
            w1 + (long)l * 64 * 256, b1 + l * 256,
            w2 + (long)l * 256 * 64, b2 + l * 64, x);
    }
    lmhead_v2<<<NTOK / 128, 512, LMH_SMEM>>>(x, lnf_g, lnf_b, lm_w, lm_b,
                                             targets, logits, tl);
    reduce1_kernel<<<512, 256>>>(tl, part);
    reduce2_kernel<<<1, 512>>>(part, lossp);
}

// round 7
// speedup vs baseline: 2.5304x; 1.2183x over previous
#include <cuda_runtime.h>
#include <cstdint>

// ---------------------------------------------------------------------------
// 3-layer transformer forward. B=4096, T=128, D=64, H=8, HD=8, DF=256, V=65.
// Round 7: 1024-thread mega-kernels (8 warps/SMSP for latency hiding).
// ---------------------------------------------------------------------------

#define NTOK (4096 * 128)
#define TSEQ 128
#define DMODEL 64
#define NVOCAB 65
#define NHEAD 8
#define DFF 256
#define NLAYER 3

__device__ float g_x[(size_t)NTOK * DMODEL];
__device__ float g_logits[(size_t)NTOK * NVOCAB];
__device__ float g_tokloss[NTOK];
__device__ double g_partial[512];

// ---------------------------------------------------------------------------
__device__ __forceinline__ unsigned f2tf(float f) {
    unsigned r;
    asm("cvt.rna.tf32.f32 %0, %1;" : "=r"(r) : "f"(f));
    return r;
}

__device__ __forceinline__ void mma_tf32(float* c, const unsigned* a,
                                         const unsigned* b) {
    asm volatile(
        "mma.sync.aligned.m16n8k8.row.col.f32.tf32.tf32.f32 "
        "{%0,%1,%2,%3},{%4,%5,%6,%7},{%8,%9},{%0,%1,%2,%3};"
        : "+f"(c[0]), "+f"(c[1]), "+f"(c[2]), "+f"(c[3])
        : "r"(a[0]), "r"(a[1]), "r"(a[2]), "r"(a[3]), "r"(b[0]), "r"(b[1]));
}

__device__ __forceinline__ void warp_ln(const float* __restrict__ rowp, int lane,
                                        float gg0, float gg1, float bb0, float bb1,
                                        float& o0, float& o1) {
    float a0 = rowp[lane];
    float a1 = rowp[lane + 32];
    float s = a0 + a1;
#pragma unroll
    for (int o = 16; o; o >>= 1) s += __shfl_xor_sync(0xffffffffu, s, o);
    float mu = s * (1.0f / 64.0f);
    float d0 = a0 - mu, d1 = a1 - mu;
    float vs = d0 * d0 + d1 * d1;
#pragma unroll
    for (int o = 16; o; o >>= 1) vs += __shfl_xor_sync(0xffffffffu, vs, o);
    float inv = rsqrtf(vs * (1.0f / 64.0f) + 1e-5f);
    o0 = d0 * inv * gg0 + bb0;
    o1 = d1 * inv * gg1 + bb1;
}

// ---------------------------------------------------------------------------
__global__ void embed_kernel(const int* __restrict__ idx,
                             const float4* __restrict__ te,
                             const float4* __restrict__ pe,
                             float4* __restrict__ x) {
    long i = (long)blockIdx.x * blockDim.x + threadIdx.x;
    if (i >= (long)NTOK * 16) return;
    long tok = i >> 4;
    int d4 = (int)(i & 15);
    int id = idx[tok];
    int t = (int)(tok & (TSEQ - 1));
    float4 a = te[(long)id * 16 + d4];
    float4 p = pe[(long)t * 16 + d4];
    float4 r;
    r.x = a.x + p.x; r.y = a.y + p.y; r.z = a.z + p.z; r.w = a.w + p.w;
    x[i] = r;
}

// ---------------------------------------------------------------------------
// Mega-kernel 1: LN1 + QKV (MMA) + full-MMA causal attention + Wo (MMA) + res.
// One block = one batch (128 tokens). 1024 threads (32 warps).
// smem: As[128][68]u | Bs[192][68]u | qs/ks/vs[128][68]u(tf32) = 191488 B.
// ---------------------------------------------------------------------------
__global__ __launch_bounds__(1024) void layer_attn(
    const float* __restrict__ x, const float* __restrict__ lng,
    const float* __restrict__ lnb,
    const float* __restrict__ wq, const float* __restrict__ wk,
    const float* __restrict__ wv, const float* __restrict__ wo,
    const float* __restrict__ bo, float* __restrict__ xo) {
    extern __shared__ unsigned sm[];
    unsigned* As = sm;                       // [128][68]
    unsigned* Bs = sm + 128 * 68;            // [192][68]
    unsigned* qs = sm + 128 * 68 + 192 * 68; // [128][68] tf32
    unsigned* ks = qs + 128 * 68;
    unsigned* vs = ks + 128 * 68;

    const int tid = threadIdx.x;
    const long row0 = (long)blockIdx.x * 128;

    // ---- stage Wqkv (transposed, tf32) + LN1 -> As ------------------------
    {
        const float* wsrc[3] = {wq, wk, wv};
#pragma unroll
        for (int s = 0; s < 3; s++) {
            const float* W = wsrc[s];
#pragma unroll
            for (int j = 0; j < 4; j++) {
                int e = tid + j * 1024;
                int kk = e >> 6, n = e & 63;
                Bs[(s * 64 + n) * 68 + kk] = f2tf(W[e]);
            }
        }
    }
    {
        int warp = tid >> 5, lane = tid & 31;
        float gg0 = lng[lane], gg1 = lng[lane + 32];
        float bb0 = lnb[lane], bb1 = lnb[lane + 32];
#pragma unroll
        for (int rr = 0; rr < 4; rr++) {
            int r = warp + rr * 32;
            float o0, o1;
            warp_ln(x + (row0 + r) * 64, lane, gg0, gg1, bb0, bb1, o0, o1);
            As[r * 68 + lane] = f2tf(o0);
            As[r * 68 + lane + 32] = f2tf(o1);
        }
    }
    __syncthreads();

    const int wid = tid >> 5, lane = tid & 31;
    const int lr = lane >> 2, lc = lane & 3;

    // ---- QKV MMA (128x192x64), warp tile 16x48 -> qs/ks/vs ----------------
    {
        const int wm = wid >> 2, wn = wid & 3;
        const int m0 = wm * 16, n0 = wn * 48;
        float acc[6][4];
#pragma unroll
        for (int ni = 0; ni < 6; ni++)
#pragma unroll
            for (int e = 0; e < 4; e++) acc[ni][e] = 0.0f;
#pragma unroll
        for (int k0 = 0; k0 < 64; k0 += 8) {
            unsigned a[4];
            a[0] = As[(m0 + lr) * 68 + k0 + lc];
            a[1] = As[(m0 + lr + 8) * 68 + k0 + lc];
            a[2] = As[(m0 + lr) * 68 + k0 + lc + 4];
            a[3] = As[(m0 + lr + 8) * 68 + k0 + lc + 4];
#pragma unroll
            for (int ni = 0; ni < 6; ni++) {
                int nb = n0 + ni * 8 + lr;
                unsigned b[2];
                b[0] = Bs[nb * 68 + k0 + lc];
                b[1] = Bs[nb * 68 + k0 + lc + 4];
                mma_tf32(acc[ni], a, b);
            }
        }
        unsigned* bufs[3] = {qs, ks, vs};
#pragma unroll
        for (int ni = 0; ni < 6; ni++) {
            int cg = n0 + ni * 8;
            unsigned* buf = bufs[cg >> 6];
            float sc = (cg < 64) ? 0.35355339059327373f : 1.0f;  // 1/sqrt(8) on q
            int col = (cg & 63) + 2 * lc;
            uint2 o0, o1;
            o0.x = f2tf(acc[ni][0] * sc);
            o0.y = f2tf(acc[ni][1] * sc);
            o1.x = f2tf(acc[ni][2] * sc);
            o1.y = f2tf(acc[ni][3] * sc);
            *(uint2*)(buf + (m0 + lr) * 68 + col) = o0;
            *(uint2*)(buf + (m0 + lr + 8) * 68 + col) = o1;
        }
    }
    __syncthreads();

    // ---- stage Wo (col-major tf32) into freed Bs ---------------------------
#pragma unroll
    for (int j = 0; j < 4; j++) {
        int e = tid + j * 1024;              // e = k*64 + n
        Bs[(e & 63) * 68 + (e >> 6)] = f2tf(wo[e]);
    }

    // ---- full-MMA attention: 2 tasks/warp, paired (m, 7-m) for balance ----
    {
        const int h = wid & 7;
        const int mbase = wid >> 3;          // 0..3
        const int src1 = (lane & 28) | (lc >> 1);
        const int src2 = src1 + 2;
        const int par = lc & 1;
#pragma unroll
        for (int it = 0; it < 2; it++) {
            const int m = it ? (7 - mbase) : mbase;
            const int r0 = 16 * m + lr;
            unsigned aS[4];
            aS[0] = qs[(16 * m + lr) * 68 + 8 * h + lc];
            aS[1] = qs[(16 * m + lr + 8) * 68 + 8 * h + lc];
            aS[2] = qs[(16 * m + lr) * 68 + 8 * h + lc + 4];
            aS[3] = qs[(16 * m + lr + 8) * 68 + 8 * h + lc + 4];
            float rs0 = 0.f, rs1 = 0.f;
            float out[4] = {0.f, 0.f, 0.f, 0.f};
#pragma unroll
            for (int ni = 0; ni < 16; ni++) {
                if (ni <= 2 * m + 1) {        // causal tile skip (warp-uniform)
                    float c[4] = {0.f, 0.f, 0.f, 0.f};
                    unsigned bK[2];
                    bK[0] = ks[(8 * ni + lr) * 68 + 8 * h + lc];
                    bK[1] = ks[(8 * ni + lr) * 68 + 8 * h + lc + 4];
                    mma_tf32(c, aS, bK);
                    if (8 * ni + 7 <= 16 * m) {
                        c[0] = __expf(c[0]); c[1] = __expf(c[1]);
                        c[2] = __expf(c[2]); c[3] = __expf(c[3]);
                    } else {
                        int j0 = 8 * ni + 2 * lc, j1 = j0 + 1;
                        c[0] = (j0 <= r0) ? __expf(c[0]) : 0.f;
                        c[1] = (j1 <= r0) ? __expf(c[1]) : 0.f;
                        c[2] = (j0 <= r0 + 8) ? __expf(c[2]) : 0.f;
                        c[3] = (j1 <= r0 + 8) ? __expf(c[3]) : 0.f;
                    }
                    rs0 += c[0] + c[1];
                    rs1 += c[2] + c[3];
                    float t0 = __shfl_sync(0xffffffffu, c[0], src1);
                    float t1 = __shfl_sync(0xffffffffu, c[1], src1);
                    float t2 = __shfl_sync(0xffffffffu, c[2], src1);
                    float t3 = __shfl_sync(0xffffffffu, c[3], src1);
                    float u0 = __shfl_sync(0xffffffffu, c[0], src2);
                    float u1 = __shfl_sync(0xffffffffu, c[1], src2);
                    float u2 = __shfl_sync(0xffffffffu, c[2], src2);
                    float u3 = __shfl_sync(0xffffffffu, c[3], src2);
                    unsigned aP[4];
                    aP[0] = f2tf(par ? t1 : t0);
                    aP[1] = f2tf(par ? t3 : t2);
                    aP[2] = f2tf(par ? u1 : u0);
                    aP[3] = f2tf(par ? u3 : u2);
                    unsigned bV[2];
                    bV[0] = vs[(8 * ni + lc) * 68 + 8 * h + lr];
                    bV[1] = vs[(8 * ni + lc + 4) * 68 + 8 * h + lr];
                    mma_tf32(out, aP, bV);
                }
            }
            rs0 += __shfl_xor_sync(0xffffffffu, rs0, 1);
            rs0 += __shfl_xor_sync(0xffffffffu, rs0, 2);
            rs1 += __shfl_xor_sync(0xffffffffu, rs1, 1);
            rs1 += __shfl_xor_sync(0xffffffffu, rs1, 2);
            float inv0 = 1.0f / rs0, inv1 = 1.0f / rs1;
            unsigned* d0 = As + r0 * 68 + 8 * h + 2 * lc;
            unsigned* d1 = As + (r0 + 8) * 68 + 8 * h + 2 * lc;
            d0[0] = f2tf(out[0] * inv0); d0[1] = f2tf(out[1] * inv0);
            d1[0] = f2tf(out[2] * inv1); d1[1] = f2tf(out[3] * inv1);
        }
    }
    __syncthreads();

    // ---- Wo MMA (128x64x64), warp tile 16x16 + bias + residual ------------
    {
        const int wm = wid >> 2, wn = wid & 3;
        const int m0 = wm * 16, n0 = wn * 16;
        float acc[2][4];
#pragma unroll
        for (int ni = 0; ni < 2; ni++)
#pragma unroll
            for (int e = 0; e < 4; e++) acc[ni][e] = 0.0f;
#pragma unroll
        for (int k0 = 0; k0 < 64; k0 += 8) {
            unsigned a[4];
            a[0] = As[(m0 + lr) * 68 + k0 + lc];
            a[1] = As[(m0 + lr + 8) * 68 + k0 + lc];
            a[2] = As[(m0 + lr) * 68 + k0 + lc + 4];
            a[3] = As[(m0 + lr + 8) * 68 + k0 + lc + 4];
#pragma unroll
            for (int ni = 0; ni < 2; ni++) {
                int nb = n0 + ni * 8 + lr;
                unsigned b[2];
                b[0] = Bs[nb * 68 + k0 + lc];
                b[1] = Bs[nb * 68 + k0 + lc + 4];
                mma_tf32(acc[ni], a, b);
            }
        }
#pragma unroll
        for (int ni = 0; ni < 2; ni++) {
            int col = n0 + ni * 8 + 2 * lc;
            float2 bb = *(const float2*)(bo + col);
            long r = row0 + m0 + lr;
            float2* p0 = (float2*)(xo + r * 64 + col);
            float2* p1 = (float2*)(xo + (r + 8) * 64 + col);
            float2 r0v = *p0, r1v = *p1;
            r0v.x += acc[ni][0] + bb.x;
            r0v.y += acc[ni][1] + bb.y;
            r1v.x += acc[ni][2] + bb.x;
            r1v.y += acc[ni][3] + bb.y;
            *p0 = r0v;
            *p1 = r1v;
        }
    }
}

// ---------------------------------------------------------------------------
// Mega-kernel 2: LN2 + W1 + bias + ReLU + W2 + bias + residual.
// 1024 threads (32 warps). GEMM1 warp tile 16x64, GEMM2 16x16.
// smem: As[128][68]u | W1s[256][68]u | W2s[64][260]u = 171008 B.
// ---------------------------------------------------------------------------
__global__ __launch_bounds__(1024) void layer_ffn(
    const float* __restrict__ x, const float* __restrict__ lng,
    const float* __restrict__ lnb, const float* __restrict__ w1,
    const float* __restrict__ b1, const float* __restrict__ w2,
    const float* __restrict__ b2, float* __restrict__ xo) {
    extern __shared__ unsigned sm[];
    unsigned* As = sm;                  // [128][68]
    unsigned* W1s = sm + 128 * 68;      // [256][68]
    unsigned* W2s = W1s + 256 * 68;     // [64][260]

    const int tid = threadIdx.x;
    const long row0 = (long)blockIdx.x * 128;

#pragma unroll
    for (int j = 0; j < 16; j++) {
        int e = tid + j * 1024;
        W1s[(e & 255) * 68 + (e >> 8)] = f2tf(w1[e]);
    }
#pragma unroll
    for (int j = 0; j < 16; j++) {
        int e = tid + j * 1024;
        W2s[(e & 63) * 260 + (e >> 6)] = f2tf(w2[e]);
    }
    {
        int warp = tid >> 5, lane = tid & 31;
        float gg0 = lng[lane], gg1 = lng[lane + 32];
        float bb0 = lnb[lane], bb1 = lnb[lane + 32];
#pragma unroll
        for (int rr = 0; rr < 4; rr++) {
            int r = warp + rr * 32;
            float o0, o1;
            warp_ln(x + (row0 + r) * 64, lane, gg0, gg1, bb0, bb1, o0, o1);
            As[r * 68 + lane] = f2tf(o0);
            As[r * 68 + lane + 32] = f2tf(o1);
        }
    }
    __syncthreads();

    const int wid = tid >> 5, lane = tid & 31;
    const int wm = wid >> 2, wn = wid & 3;
    const int m0 = wm * 16;
    const int lr = lane >> 2, lc = lane & 3;

    // ---- GEMM1: h1 = LN2(x) @ W1, warp tile 16x64 --------------------------
    const int n0 = wn * 64;
    float acc[8][4];
#pragma unroll
    for (int ni = 0; ni < 8; ni++)
#pragma unroll
        for (int e = 0; e < 4; e++) acc[ni][e] = 0.0f;
#pragma unroll
    for (int k0 = 0; k0 < 64; k0 += 8) {
        unsigned a[4];
        a[0] = As[(m0 + lr) * 68 + k0 + lc];
        a[1] = As[(m0 + lr + 8) * 68 + k0 + lc];
        a[2] = As[(m0 + lr) * 68 + k0 + lc + 4];
        a[3] = As[(m0 + lr + 8) * 68 + k0 + lc + 4];
#pragma unroll
        for (int ni = 0; ni < 8; ni++) {
            int nb = n0 + ni * 8 + lr;
            unsigned b[2];
            b[0] = W1s[nb * 68 + k0 + lc];
            b[1] = W1s[nb * 68 + k0 + lc + 4];
            mma_tf32(acc[ni], a, b);
        }
    }

    // ---- GEMM2: out = relu(h1+b1) @ W2, staged k-chunks --------------------
    const int n02 = wn * 16;
    float acc2[2][4];
#pragma unroll
    for (int ni = 0; ni < 2; ni++)
#pragma unroll
        for (int e = 0; e < 4; e++) acc2[ni][e] = 0.0f;

#pragma unroll
    for (int kc = 0; kc < 4; kc++) {
        __syncthreads();
        if (wn == kc) {
#pragma unroll
            for (int ni = 0; ni < 8; ni++) {
                int coll = ni * 8 + 2 * lc;
                float2 bb = *(const float2*)(b1 + n0 + coll);
                int r = m0 + lr;
                As[r * 68 + coll]           = f2tf(fmaxf(acc[ni][0] + bb.x, 0.f));
                As[r * 68 + coll + 1]       = f2tf(fmaxf(acc[ni][1] + bb.y, 0.f));
                As[(r + 8) * 68 + coll]     = f2tf(fmaxf(acc[ni][2] + bb.x, 0.f));
                As[(r + 8) * 68 + coll + 1] = f2tf(fmaxf(acc[ni][3] + bb.y, 0.f));
            }
        }
        __syncthreads();
#pragma unroll
        for (int k0 = 0; k0 < 64; k0 += 8) {
            unsigned a[4];
            a[0] = As[(m0 + lr) * 68 + k0 + lc];
            a[1] = As[(m0 + lr + 8) * 68 + k0 + lc];
            a[2] = As[(m0 + lr) * 68 + k0 + lc + 4];
            a[3] = As[(m0 + lr + 8) * 68 + k0 + lc + 4];
#pragma unroll
            for (int ni = 0; ni < 2; ni++) {
                int nb = n02 + ni * 8 + lr;
                unsigned b[2];
                b[0] = W2s[nb * 260 + kc * 64 + k0 + lc];
                b[1] = W2s[nb * 260 + kc * 64 + k0 + lc + 4];
                mma_tf32(acc2[ni], a, b);
            }
        }
    }

#pragma unroll
    for (int ni = 0; ni < 2; ni++) {
        int col = n02 + ni * 8 + 2 * lc;
        float2 bb = *(const float2*)(b2 + col);
        long r = row0 + m0 + lr;
        float2* p0 = (float2*)(xo + r * 64 + col);
        float2* p1 = (float2*)(xo + (r + 8) * 64 + col);
        float2 r0 = *p0, r1 = *p1;
        r0.x += acc2[ni][0] + bb.x;
        r0.y += acc2[ni][1] + bb.y;
        r1.x += acc2[ni][2] + bb.x;
        r1.y += acc2[ni][3] + bb.y;
        *p0 = r0;
        *p1 = r1;
    }
}

// ---------------------------------------------------------------------------
// LNf + lm_head (TF32 MMA, V padded to 72) + coalesced logits + loss.
// Block = 128 tokens, 512 threads. smem 88192 B -> 2 blocks/SM.
// ---------------------------------------------------------------------------
__global__ __launch_bounds__(512) void lmhead_v2(
    const float* __restrict__ x, const float* __restrict__ lng,
    const float* __restrict__ lnb, const float* __restrict__ w,
    const float* __restrict__ bv, const int* __restrict__ tgt,
    float* __restrict__ logits, float* __restrict__ tokloss) {
    extern __shared__ unsigned sm[];
    unsigned* As = sm;                  // [128][68]
    unsigned* Bs = sm + 128 * 68;       // [72][68]
    float* ls = (float*)(Bs + 72 * 68); // [128][66]

    const int tid = threadIdx.x;
    const long tok0 = (long)blockIdx.x * 128;

    if (tid < 7 * 68) Bs[65 * 68 + tid] = 0u;
#pragma unroll
    for (int j = 0; j < 9; j++) {
        int e = tid + j * 512;
        if (e < 65 * 64) {
            int n = e >> 6, k = e & 63;
            Bs[n * 68 + k] = f2tf(w[k * 65 + n]);
        }
    }
    {
        int warp = tid >> 5, lane = tid & 31;
        float gg0 = lng[lane], gg1 = lng[lane + 32];
        float bb0 = lnb[lane], bb1 = lnb[lane + 32];
        for (int r = warp; r < 128; r += 16) {
            float o0, o1;
            warp_ln(x + (tok0 + r) * 64, lane, gg0, gg1, bb0, bb1, o0, o1);
            As[r * 68 + lane] = f2tf(o0);
            As[r * 68 + lane + 32] = f2tf(o1);
        }
    }
    __syncthreads();

    const int wid = tid >> 5, lane = tid & 31;
    const int lr = lane >> 2, lc = lane & 3;
    const int m0 = (wid >> 1) * 16;
    const int nh = wid & 1;
    const int nt0 = nh ? 5 : 0, ntn = nh ? 4 : 5;

    float acc[5][4];
#pragma unroll
    for (int ni = 0; ni < 5; ni++)
#pragma unroll
        for (int e = 0; e < 4; e++) acc[ni][e] = 0.0f;

#pragma unroll
    for (int k0 = 0; k0 < 64; k0 += 8) {
        unsigned a[4];
        a[0] = As[(m0 + lr) * 68 + k0 + lc];
        a[1] = As[(m0 + lr + 8) * 68 + k0 + lc];
        a[2] = As[(m0 + lr) * 68 + k0 + lc + 4];
        a[3] = As[(m0 + lr + 8) * 68 + k0 + lc + 4];
#pragma unroll
        for (int ni = 0; ni < 5; ni++) {
            if (ni < ntn) {
                int nb = (nt0 + ni) * 8 + lr;
                unsigned b[2];
                b[0] = Bs[nb * 68 + k0 + lc];
                b[1] = Bs[nb * 68 + k0 + lc + 4];
                mma_tf32(acc[ni], a, b);
            }
        }
    }
#pragma unroll
    for (int ni = 0; ni < 5; ni++) {
        if (ni < ntn) {
            int col = (nt0 + ni) * 8 + 2 * lc;
            if (col < 65) {
                float b0 = bv[col];
                ls[(m0 + lr) * 66 + col] = acc[ni][0] + b0;
                ls[(m0 + lr + 8) * 66 + col] = acc[ni][2] + b0;
            }
            if (col + 1 < 65) {
                float b1 = bv[col + 1];
                ls[(m0 + lr) * 66 + col + 1] = acc[ni][1] + b1;
                ls[(m0 + lr + 8) * 66 + col + 1] = acc[ni][3] + b1;
            }
        }
    }
    __syncthreads();

    for (int i = tid; i < 128 * 65; i += 512) {
        int r = i / 65, c = i - r * 65;
        logits[tok0 * 65 + i] = ls[r * 66 + c];
    }
    {
#pragma unroll
        for (int rr = 0; rr < 8; rr++) {
            int t = wid * 8 + rr;
            float v0 = ls[t * 66 + lane];
            float v1 = ls[t * 66 + lane + 32];
            float v2 = (lane == 0) ? ls[t * 66 + 64] : -1e30f;
            float mx = fmaxf(fmaxf(v0, v1), v2);
#pragma unroll
            for (int o = 16; o; o >>= 1)
                mx = fmaxf(mx, __shfl_xor_sync(0xffffffffu, mx, o));
            float se = expf(v0 - mx) + expf(v1 - mx) + expf(v2 - mx);
#pragma unroll
            for (int o = 16; o; o >>= 1) se += __shfl_xor_sync(0xffffffffu, se, o);
            if (lane == 0) {
                int tg = tgt[tok0 + t];
                tokloss[tok0 + t] = -(ls[t * 66 + tg] - mx - logf(se));
            }
        }
    }
}

// ---------------------------------------------------------------------------
__global__ void reduce1_kernel(const float* __restrict__ tl,
                               double* __restrict__ part) {
    __shared__ double smd[256];
    long base = (long)blockIdx.x * (NTOK / 512);
    double s = 0.0;
    for (int i = threadIdx.x; i < NTOK / 512; i += 256) s += (double)tl[base + i];
    smd[threadIdx.x] = s;
    __syncthreads();
    for (int o = 128; o; o >>= 1) {
        if (threadIdx.x < o) smd[threadIdx.x] += smd[threadIdx.x + o];
        __syncthreads();
    }
    if (threadIdx.x == 0) part[blockIdx.x] = smd[0];
}

__global__ void reduce2_kernel(const double* __restrict__ part,
                               float* __restrict__ out) {
    __shared__ double smd[512];
    smd[threadIdx.x] = part[threadIdx.x];
    __syncthreads();
    for (int o = 256; o; o >>= 1) {
        if (threadIdx.x < o) smd[threadIdx.x] += smd[threadIdx.x + o];
        __syncthreads();
    }
    if (threadIdx.x == 0) out[0] = (float)(smd[0] / (double)NTOK);
}

// ---------------------------------------------------------------------------
extern "C" void kernel_launch(void* const* d_in, const int* in_sizes, int n_in,
                              void* d_out, int out_size) {
    const float* tok_emb = (const float*)d_in[0];
    const float* pos_emb = (const float*)d_in[1];
    const float* ln1_g   = (const float*)d_in[2];
    const float* ln1_b   = (const float*)d_in[3];
    const float* wq      = (const float*)d_in[4];
    const float* wk      = (const float*)d_in[5];
    const float* wv      = (const float*)d_in[6];
    const float* wo      = (const float*)d_in[7];
    const float* bo      = (const float*)d_in[8];
    const float* ln2_g   = (const float*)d_in[9];
    const float* ln2_b   = (const float*)d_in[10];
    const float* w1      = (const float*)d_in[11];
    const float* b1      = (const float*)d_in[12];
    const float* w2      = (const float*)d_in[13];
    const float* b2      = (const float*)d_in[14];
    const float* lnf_g   = (const float*)d_in[15];
    const float* lnf_b   = (const float*)d_in[16];
    const float* lm_w    = (const float*)d_in[17];
    const float* lm_b    = (const float*)d_in[18];
    const int*   idx     = (const int*)d_in[19];
    const int*   targets = (const int*)d_in[20];

    float *x, *lg, *tl;
    double* part;
    cudaGetSymbolAddress((void**)&x,  g_x);
    cudaGetSymbolAddress((void**)&lg, g_logits);
    cudaGetSymbolAddress((void**)&tl, g_tokloss);
    cudaGetSymbolAddress((void**)&part, g_partial);

    float* outp = (float*)d_out;
    const long LSZ = (long)NTOK * NVOCAB;
    float* logits = ((long)out_size >= LSZ) ? outp : lg;
    float* lossp;
    if ((long)out_size >= LSZ + 1)      lossp = outp + LSZ;
    else if (out_size == 1)             lossp = outp;
    else                                lossp = tl;

    const int ATTN_SMEM = (128 * 68 + 192 * 68 + 3 * 128 * 68) * 4;  // 191488
    const int FFN_SMEM  = (128 * 68 + 256 * 68 + 64 * 260) * 4;      // 171008
    const int LMH_SMEM  = (128 * 68 + 72 * 68) * 4 + 128 * 66 * 4;   // 88192
    cudaFuncSetAttribute(layer_attn, cudaFuncAttributeMaxDynamicSharedMemorySize, ATTN_SMEM);
    cudaFuncSetAttribute(layer_ffn,  cudaFuncAttributeMaxDynamicSharedMemorySize, FFN_SMEM);
    cudaFuncSetAttribute(lmhead_v2,  cudaFuncAttributeMaxDynamicSharedMemorySize, LMH_SMEM);

    embed_kernel<<<(NTOK * 16) / 256, 256>>>(
        idx, (const float4*)tok_emb, (const float4*)pos_emb, (float4*)x);

    for (int l = 0; l < NLAYER; l++) {
        layer_attn<<<4096, 1024, ATTN_SMEM>>>(
            x, ln1_g + l * 64, ln1_b + l * 64,
            wq + (long)l * 4096, wk + (long)l * 4096, wv + (long)l * 4096,
            wo + (long)l * 4096, bo + l * 64, x);
        layer_ffn<<<NTOK / 128, 1024, FFN_SMEM>>>(
            x, ln2_g + l * 64, ln2_b + l * 64,
            w1 + (long)l * 64 * 256, b1 + l * 256,
            w2 + (long)l * 256 * 64, b2 + l * 64, x);
    }
    lmhead_v2<<<NTOK / 128, 512, LMH_SMEM>>>(x, lnf_g, lnf_b, lm_w, lm_b,
                                             targets, logits, tl);
    reduce1_kernel<<<512, 256>>>(tl, part);
    reduce2_kernel<<<1, 512>>>(part, lossp);
}

// round 8
// speedup vs baseline: 2.7089x; 1.0706x over previous
#include <cuda_runtime.h>
#include <cstdint>

// ---------------------------------------------------------------------------
// 3-layer transformer forward. B=4096, T=128, D=64, H=8, HD=8, DF=256, V=65.
// Round 8: whole-layer fused kernel (x resident in smem), ldmatrix fragment
// loads everywhere, transposed-V PV MMA, fused attention pair loop,
// embed fused into layer 0 and lm_head+loss fused into layer 2.
// ---------------------------------------------------------------------------

#define NTOK (4096 * 128)
#define TSEQ 128
#define DMODEL 64
#define NVOCAB 65
#define NHEAD 8
#define DFF 256
#define NLAYER 3

__device__ float g_x[(size_t)NTOK * DMODEL];
__device__ float g_logits[(size_t)NTOK * NVOCAB];
__device__ float g_tokloss[NTOK];
__device__ double g_partial[512];

// ---------------------------------------------------------------------------
__device__ __forceinline__ unsigned f2tf(float f) {
    unsigned r;
    asm("cvt.rna.tf32.f32 %0, %1;" : "=r"(r) : "f"(f));
    return r;
}

__device__ __forceinline__ unsigned s2u(const void* p) {
    return (unsigned)__cvta_generic_to_shared(p);
}

__device__ __forceinline__ void ldsm4(unsigned* d, unsigned addr) {
    asm volatile(
        "ldmatrix.sync.aligned.m8n8.x4.shared.b16 {%0,%1,%2,%3}, [%4];"
        : "=r"(d[0]), "=r"(d[1]), "=r"(d[2]), "=r"(d[3]) : "r"(addr));
}

__device__ __forceinline__ void ldsm2(unsigned* d, unsigned addr) {
    asm volatile(
        "ldmatrix.sync.aligned.m8n8.x2.shared.b16 {%0,%1}, [%2];"
        : "=r"(d[0]), "=r"(d[1]) : "r"(addr));
}

__device__ __forceinline__ void mma_tf32(float* c, const unsigned* a,
                                         const unsigned* b) {
    asm volatile(
        "mma.sync.aligned.m16n8k8.row.col.f32.tf32.tf32.f32 "
        "{%0,%1,%2,%3},{%4,%5,%6,%7},{%8,%9},{%0,%1,%2,%3};"
        : "+f"(c[0]), "+f"(c[1]), "+f"(c[2]), "+f"(c[3])
        : "r"(a[0]), "r"(a[1]), "r"(a[2]), "r"(a[3]), "r"(b[0]), "r"(b[1]));
}

__device__ __forceinline__ void warp_ln(const float* __restrict__ rowp, int lane,
                                        float gg0, float gg1, float bb0, float bb1,
                                        float& o0, float& o1) {
    float a0 = rowp[lane];
    float a1 = rowp[lane + 32];
    float s = a0 + a1;
#pragma unroll
    for (int o = 16; o; o >>= 1) s += __shfl_xor_sync(0xffffffffu, s, o);
    float mu = s * (1.0f / 64.0f);
    float d0 = a0 - mu, d1 = a1 - mu;
    float vs = d0 * d0 + d1 * d1;
#pragma unroll
    for (int o = 16; o; o >>= 1) vs += __shfl_xor_sync(0xffffffffu, vs, o);
    float inv = rsqrtf(vs * (1.0f / 64.0f) + 1e-5f);
    o0 = d0 * inv * gg0 + bb0;
    o1 = d1 * inv * gg1 + bb1;
}

// One attention k-tile: S-MMA, masked exp, rowsum, fragment-shuffle P, PV-MMA.
__device__ __forceinline__ void attn_tile_proc(
    float* out, float& rs0, float& rs1,
    const unsigned* aS, const unsigned* bK, const unsigned* bV,
    int ni, int m, int r0, int lc, int src1, int src2, int par) {
    float c[4] = {0.f, 0.f, 0.f, 0.f};
    mma_tf32(c, aS, bK);
    if (8 * ni + 7 <= 16 * m) {
        c[0] = __expf(c[0]); c[1] = __expf(c[1]);
        c[2] = __expf(c[2]); c[3] = __expf(c[3]);
    } else {
        int j0 = 8 * ni + 2 * lc, j1 = j0 + 1;
        c[0] = (j0 <= r0) ? __expf(c[0]) : 0.f;
        c[1] = (j1 <= r0) ? __expf(c[1]) : 0.f;
        c[2] = (j0 <= r0 + 8) ? __expf(c[2]) : 0.f;
        c[3] = (j1 <= r0 + 8) ? __expf(c[3]) : 0.f;
    }
    rs0 += c[0] + c[1];
    rs1 += c[2] + c[3];
    float t0 = __shfl_sync(0xffffffffu, c[0], src1);
    float t1 = __shfl_sync(0xffffffffu, c[1], src1);
    float t2 = __shfl_sync(0xffffffffu, c[2], src1);
    float t3 = __shfl_sync(0xffffffffu, c[3], src1);
    float u0 = __shfl_sync(0xffffffffu, c[0], src2);
    float u1 = __shfl_sync(0xffffffffu, c[1], src2);
    float u2 = __shfl_sync(0xffffffffu, c[2], src2);
    float u3 = __shfl_sync(0xffffffffu, c[3], src2);
    unsigned aP[4];
    aP[0] = f2tf(par ? t1 : t0);
    aP[1] = f2tf(par ? t3 : t2);
    aP[2] = f2tf(par ? u1 : u0);
    aP[3] = f2tf(par ? u3 : u2);
    mma_tf32(out, aP, bV);
}

// ---------------------------------------------------------------------------
// Whole-layer fused kernel. One block = one batch (128 tokens), 1024 threads.
// MODE: 0 = first layer (embed fused), 1 = middle, 2 = last (lm_head fused).
// smem (words): xres[128][68]f | As[128][68] | qs[128][68] | ks[128][68] |
//               vsT[64][132]  | Bs[192][68]   = 56320 words = 225280 B.
// Overlays: W1s[256][68]=qs..ks, W2s[64][260]=vsT..Bs, lmw[72][68]=qs,
//           ls[128][66]f=ks.
// ---------------------------------------------------------------------------
template <int MODE>
__global__ __launch_bounds__(1024) void layer_fused(
    const float* __restrict__ x, const int* __restrict__ idx,
    const float* __restrict__ te, const float* __restrict__ pe,
    const float* __restrict__ ln1g, const float* __restrict__ ln1b,
    const float* __restrict__ wq, const float* __restrict__ wk,
    const float* __restrict__ wv, const float* __restrict__ wo,
    const float* __restrict__ bo,
    const float* __restrict__ ln2g, const float* __restrict__ ln2b,
    const float* __restrict__ w1, const float* __restrict__ b1,
    const float* __restrict__ w2, const float* __restrict__ b2,
    const float* __restrict__ lnfg, const float* __restrict__ lnfb,
    const float* __restrict__ lmw, const float* __restrict__ lmb,
    const int* __restrict__ tgt,
    float* __restrict__ xo, float* __restrict__ logits,
    float* __restrict__ tokloss) {
    extern __shared__ unsigned sm[];
    float* xres = (float*)sm;            // [128][68] f32
    unsigned* As = sm + 8704;            // [128][68]
    unsigned* qs = As + 8704;            // [128][68]
    unsigned* ks = qs + 8704;            // [128][68]
    unsigned* vsT = ks + 8704;           // [64][132]
    unsigned* Bs = vsT + 8448;           // [192][68]

    const int tid = threadIdx.x;
    const long row0 = (long)blockIdx.x * 128;
    const int wid = tid >> 5, lane = tid & 31;
    const int lr = lane >> 2, lc = lane & 3;

    // ---- P0: load residual x into smem (embed for MODE 0) + stage Wqkv ----
#pragma unroll
    for (int j = 0; j < 2; j++) {
        int e = tid + j * 1024;          // float4 index 0..2047
        int r = e >> 4, c4 = e & 15;
        float4 val;
        if (MODE == 0) {
            int id = idx[row0 + r];
            float4 a = ((const float4*)te)[id * 16 + c4];
            float4 p = ((const float4*)pe)[r * 16 + c4];
            val.x = a.x + p.x; val.y = a.y + p.y;
            val.z = a.z + p.z; val.w = a.w + p.w;
        } else {
            val = ((const float4*)x)[row0 * 16 + e];
        }
        *(float4*)(xres + r * 68 + c4 * 4) = val;
    }
    {
        const float* wsrc[3] = {wq, wk, wv};
#pragma unroll
        for (int s = 0; s < 3; s++) {
            const float* W = wsrc[s];
#pragma unroll
            for (int j = 0; j < 4; j++) {
                int e = tid + j * 1024;
                Bs[(s * 64 + (e & 63)) * 68 + (e >> 6)] = f2tf(W[e]);
            }
        }
    }
    __syncthreads();

    // ---- P1: LN1 xres -> As (tf32) -----------------------------------------
    {
        float gg0 = ln1g[lane], gg1 = ln1g[lane + 32];
        float bb0 = ln1b[lane], bb1 = ln1b[lane + 32];
#pragma unroll
        for (int rr = 0; rr < 4; rr++) {
            int r = wid + rr * 32;
            float o0, o1;
            warp_ln(xres + r * 68, lane, gg0, gg1, bb0, bb1, o0, o1);
            As[r * 68 + lane] = f2tf(o0);
            As[r * 68 + lane + 32] = f2tf(o1);
        }
    }
    __syncthreads();

    // ---- P2: QKV MMA (warp tile 16x48) -> qs, ks, vsT ----------------------
    {
        const int wm = wid >> 2, wn = wid & 3;
        const int m0 = wm * 16, n0 = wn * 48;
        float acc[6][4];
#pragma unroll
        for (int ni = 0; ni < 6; ni++)
#pragma unroll
            for (int e = 0; e < 4; e++) acc[ni][e] = 0.0f;
        unsigned abase = s2u(As + (m0 + (lane & 15)) * 68 + ((lane >> 4) << 2));
        unsigned bbase = s2u(Bs + (n0 + (lane & 7)) * 68 + (((lane >> 3) & 1) << 2));
#pragma unroll
        for (int k0 = 0; k0 < 64; k0 += 8) {
            unsigned a[4];
            ldsm4(a, abase + k0 * 4);
#pragma unroll
            for (int ni = 0; ni < 6; ni++) {
                unsigned b[2];
                ldsm2(b, bbase + (ni * 8 * 68 + k0) * 4);
                mma_tf32(acc[ni], a, b);
            }
        }
#pragma unroll
        for (int ni = 0; ni < 6; ni++) {
            int cg = n0 + ni * 8;
            if (cg < 64) {                           // q (pre-scaled)
                const float sc = 0.35355339059327373f;
                int col = cg + 2 * lc;
                uint2 o0, o1;
                o0.x = f2tf(acc[ni][0] * sc); o0.y = f2tf(acc[ni][1] * sc);
                o1.x = f2tf(acc[ni][2] * sc); o1.y = f2tf(acc[ni][3] * sc);
                *(uint2*)(qs + (m0 + lr) * 68 + col) = o0;
                *(uint2*)(qs + (m0 + lr + 8) * 68 + col) = o1;
            } else if (cg < 128) {                   // k
                int col = cg - 64 + 2 * lc;
                uint2 o0, o1;
                o0.x = f2tf(acc[ni][0]); o0.y = f2tf(acc[ni][1]);
                o1.x = f2tf(acc[ni][2]); o1.y = f2tf(acc[ni][3]);
                *(uint2*)(ks + (m0 + lr) * 68 + col) = o0;
                *(uint2*)(ks + (m0 + lr + 8) * 68 + col) = o1;
            } else {                                 // v, transposed
                int hd = cg - 128 + 2 * lc;
                vsT[hd * 132 + m0 + lr]           = f2tf(acc[ni][0]);
                vsT[(hd + 1) * 132 + m0 + lr]     = f2tf(acc[ni][1]);
                vsT[hd * 132 + m0 + lr + 8]       = f2tf(acc[ni][2]);
                vsT[(hd + 1) * 132 + m0 + lr + 8] = f2tf(acc[ni][3]);
            }
        }
    }
    __syncthreads();

    // ---- P3: stage Wo (col-major) into Bs; fused-pair MMA attention -------
#pragma unroll
    for (int j = 0; j < 4; j++) {
        int e = tid + j * 1024;                      // e = k*64 + n
        Bs[(e & 63) * 68 + (e >> 6)] = f2tf(wo[e]);
    }
    {
        const int h = wid & 7;
        const int mb = wid >> 3;                     // 0..3
        const int m1 = mb, m2 = 7 - mb;
        const int nt1 = 2 * m1 + 2, nt2 = 2 * m2 + 2;
        const int r01 = 16 * m1 + lr, r02 = 16 * m2 + lr;
        const int src1 = (lane & 28) | (lc >> 1);
        const int src2 = src1 + 2;
        const int par = lc & 1;
        unsigned aS1[4], aS2[4];
        ldsm4(aS1, s2u(qs + (16 * m1 + (lane & 15)) * 68 + 8 * h + ((lane >> 4) << 2)));
        ldsm4(aS2, s2u(qs + (16 * m2 + (lane & 15)) * 68 + 8 * h + ((lane >> 4) << 2)));
        float out1[4] = {0.f, 0.f, 0.f, 0.f}, out2[4] = {0.f, 0.f, 0.f, 0.f};
        float rs10 = 0.f, rs11 = 0.f, rs20 = 0.f, rs21 = 0.f;
        unsigned kb = s2u(ks + (lane & 7) * 68 + 8 * h + (((lane >> 3) & 1) << 2));
        unsigned vb = s2u(vsT + (8 * h + (lane & 7)) * 132 + (((lane >> 3) & 1) << 2));
#pragma unroll
        for (int ni = 0; ni < 16; ni++) {
            if (ni < nt2) {
                unsigned bK[2], bV[2];
                ldsm2(bK, kb + ni * (8 * 68 * 4));
                ldsm2(bV, vb + ni * 32);
                attn_tile_proc(out2, rs20, rs21, aS2, bK, bV, ni, m2, r02,
                               lc, src1, src2, par);
                if (ni < nt1)
                    attn_tile_proc(out1, rs10, rs11, aS1, bK, bV, ni, m1, r01,
                                   lc, src1, src2, par);
            }
        }
#pragma unroll
        for (int t = 0; t < 2; t++) {
            float a0 = t ? rs20 : rs10, a1 = t ? rs21 : rs11;
            const float* ov = t ? out2 : out1;
            int r0 = t ? r02 : r01;
            a0 += __shfl_xor_sync(0xffffffffu, a0, 1);
            a0 += __shfl_xor_sync(0xffffffffu, a0, 2);
            a1 += __shfl_xor_sync(0xffffffffu, a1, 1);
            a1 += __shfl_xor_sync(0xffffffffu, a1, 2);
            float inv0 = 1.0f / a0, inv1 = 1.0f / a1;
            unsigned* d0 = As + r0 * 68 + 8 * h + 2 * lc;
            unsigned* d1 = As + (r0 + 8) * 68 + 8 * h + 2 * lc;
            d0[0] = f2tf(ov[0] * inv0); d0[1] = f2tf(ov[1] * inv0);
            d1[0] = f2tf(ov[2] * inv1); d1[1] = f2tf(ov[3] * inv1);
        }
    }
    __syncthreads();

    // ---- P4: Wo MMA (16x16) + bias + residual into xres --------------------
    {
        const int wm = wid >> 2, wn = wid & 3;
        const int m0 = wm * 16, n0 = wn * 16;
        float acc[2][4];
#pragma unroll
        for (int ni = 0; ni < 2; ni++)
#pragma unroll
            for (int e = 0; e < 4; e++) acc[ni][e] = 0.0f;
        unsigned abase = s2u(As + (m0 + (lane & 15)) * 68 + ((lane >> 4) << 2));
        unsigned bbase = s2u(Bs + (n0 + (lane & 7)) * 68 + (((lane >> 3) & 1) << 2));
#pragma unroll
        for (int k0 = 0; k0 < 64; k0 += 8) {
            unsigned a[4];
            ldsm4(a, abase + k0 * 4);
#pragma unroll
            for (int ni = 0; ni < 2; ni++) {
                unsigned b[2];
                ldsm2(b, bbase + (ni * 8 * 68 + k0) * 4);
                mma_tf32(acc[ni], a, b);
            }
        }
#pragma unroll
        for (int ni = 0; ni < 2; ni++) {
            int col = n0 + ni * 8 + 2 * lc;
            float2 bb = *(const float2*)(bo + col);
            float* p0 = xres + (m0 + lr) * 68 + col;
            float* p1 = xres + (m0 + lr + 8) * 68 + col;
            p0[0] += acc[ni][0] + bb.x; p0[1] += acc[ni][1] + bb.y;
            p1[0] += acc[ni][2] + bb.x; p1[1] += acc[ni][3] + bb.y;
        }
    }
    __syncthreads();

    // ---- P5: stage W1/W2; LN2 xres -> As ------------------------------------
    unsigned* W1s = qs;                   // [256][68] over qs..ks
    unsigned* W2s = vsT;                  // [64][260] over vsT..Bs
#pragma unroll
    for (int j = 0; j < 16; j++) {
        int e = tid + j * 1024;
        W1s[(e & 255) * 68 + (e >> 8)] = f2tf(w1[e]);
    }
#pragma unroll
    for (int j = 0; j < 16; j++) {
        int e = tid + j * 1024;
        W2s[(e & 63) * 260 + (e >> 6)] = f2tf(w2[e]);
    }
    {
        float gg0 = ln2g[lane], gg1 = ln2g[lane + 32];
        float bb0 = ln2b[lane], bb1 = ln2b[lane + 32];
#pragma unroll
        for (int rr = 0; rr < 4; rr++) {
            int r = wid + rr * 32;
            float o0, o1;
            warp_ln(xres + r * 68, lane, gg0, gg1, bb0, bb1, o0, o1);
            As[r * 68 + lane] = f2tf(o0);
            As[r * 68 + lane + 32] = f2tf(o1);
        }
    }
    __syncthreads();

    // ---- P6: FFN GEMM1 (16x64) + staged GEMM2 (16x16) + residual ----------
    {
        const int wm = wid >> 2, wn = wid & 3;
        const int m0 = wm * 16;
        const int n0 = wn * 64;
        float acc[8][4];
#pragma unroll
        for (int ni = 0; ni < 8; ni++)
#pragma unroll
            for (int e = 0; e < 4; e++) acc[ni][e] = 0.0f;
        unsigned abase = s2u(As + (m0 + (lane & 15)) * 68 + ((lane >> 4) << 2));
        unsigned b1base = s2u(W1s + (n0 + (lane & 7)) * 68 + (((lane >> 3) & 1) << 2));
#pragma unroll
        for (int k0 = 0; k0 < 64; k0 += 8) {
            unsigned a[4];
            ldsm4(a, abase + k0 * 4);
#pragma unroll
            for (int ni = 0; ni < 8; ni++) {
                unsigned b[2];
                ldsm2(b, b1base + (ni * 8 * 68 + k0) * 4);
                mma_tf32(acc[ni], a, b);
            }
        }

        const int n02 = wn * 16;
        float acc2[2][4];
#pragma unroll
        for (int ni = 0; ni < 2; ni++)
#pragma unroll
            for (int e = 0; e < 4; e++) acc2[ni][e] = 0.0f;
        unsigned b2base = s2u(W2s + (n02 + (lane & 7)) * 260 + (((lane >> 3) & 1) << 2));
#pragma unroll
        for (int kc = 0; kc < 4; kc++) {
            __syncthreads();
            if (wn == kc) {
#pragma unroll
                for (int ni = 0; ni < 8; ni++) {
                    int coll = ni * 8 + 2 * lc;
                    float2 bb = *(const float2*)(b1 + n0 + coll);
                    int r = m0 + lr;
                    As[r * 68 + coll]           = f2tf(fmaxf(acc[ni][0] + bb.x, 0.f));
                    As[r * 68 + coll + 1]       = f2tf(fmaxf(acc[ni][1] + bb.y, 0.f));
                    As[(r + 8) * 68 + coll]     = f2tf(fmaxf(acc[ni][2] + bb.x, 0.f));
                    As[(r + 8) * 68 + coll + 1] = f2tf(fmaxf(acc[ni][3] + bb.y, 0.f));
                }
            }
            __syncthreads();
#pragma unroll
            for (int k0 = 0; k0 < 64; k0 += 8) {
                unsigned a[4];
                ldsm4(a, abase + k0 * 4);
#pragma unroll
                for (int ni = 0; ni < 2; ni++) {
                    unsigned b[2];
                    ldsm2(b, b2base + (ni * 8 * 260 + kc * 64 + k0) * 4);
                    mma_tf32(acc2[ni], a, b);
                }
            }
        }
#pragma unroll
        for (int ni = 0; ni < 2; ni++) {
            int col = n02 + ni * 8 + 2 * lc;
            float2 bb = *(const float2*)(b2 + col);
            float v00 = xres[(m0 + lr) * 68 + col]     + acc2[ni][0] + bb.x;
            float v01 = xres[(m0 + lr) * 68 + col + 1] + acc2[ni][1] + bb.y;
            float v10 = xres[(m0 + lr + 8) * 68 + col]     + acc2[ni][2] + bb.x;
            float v11 = xres[(m0 + lr + 8) * 68 + col + 1] + acc2[ni][3] + bb.y;
            if (MODE == 2) {
                xres[(m0 + lr) * 68 + col] = v00;
                xres[(m0 + lr) * 68 + col + 1] = v01;
                xres[(m0 + lr + 8) * 68 + col] = v10;
                xres[(m0 + lr + 8) * 68 + col + 1] = v11;
            } else {
                *(float2*)(xo + (row0 + m0 + lr) * 64 + col) = make_float2(v00, v01);
                *(float2*)(xo + (row0 + m0 + lr + 8) * 64 + col) = make_float2(v10, v11);
            }
        }
    }

    // ---- P7 (last layer): LNf + lm_head MMA + logits + loss ----------------
    if (MODE == 2) {
        __syncthreads();
        unsigned* lmws = qs;              // [72][68]
        float* ls = (float*)ks;           // [128][66]
        if (tid < 7 * 68) lmws[65 * 68 + tid] = 0u;
#pragma unroll
        for (int j = 0; j < 5; j++) {
            int e = tid + j * 1024;
            if (e < 65 * 64) {
                int n = e >> 6, k = e & 63;
                lmws[n * 68 + k] = f2tf(lmw[k * 65 + n]);
            }
        }
        {
            float gg0 = lnfg[lane], gg1 = lnfg[lane + 32];
            float bb0 = lnfb[lane], bb1 = lnfb[lane + 32];
#pragma unroll
            for (int rr = 0; rr < 4; rr++) {
                int r = wid + rr * 32;
                float o0, o1;
                warp_ln(xres + r * 68, lane, gg0, gg1, bb0, bb1, o0, o1);
                As[r * 68 + lane] = f2tf(o0);
                As[r * 68 + lane + 32] = f2tf(o1);
            }
        }
        __syncthreads();

        const int m0 = (wid >> 2) * 16;
        const int nq = wid & 3;
        const int nt0 = (nq == 0) ? 0 : (nq == 1) ? 3 : (nq == 2) ? 5 : 7;
        const int ntn = (nq == 0) ? 3 : 2;
        float acc[3][4];
#pragma unroll
        for (int ni = 0; ni < 3; ni++)
#pragma unroll
            for (int e = 0; e < 4; e++) acc[ni][e] = 0.0f;
        unsigned abase = s2u(As + (m0 + (lane & 15)) * 68 + ((lane >> 4) << 2));
        unsigned bbase = s2u(lmws + (nt0 * 8 + (lane & 7)) * 68 + (((lane >> 3) & 1) << 2));
#pragma unroll
        for (int k0 = 0; k0 < 64; k0 += 8) {
            unsigned a[4];
            ldsm4(a, abase + k0 * 4);
#pragma unroll
            for (int ni = 0; ni < 3; ni++) {
                if (ni < ntn) {
                    unsigned b[2];
                    ldsm2(b, bbase + (ni * 8 * 68 + k0) * 4);
                    mma_tf32(acc[ni], a, b);
                }
            }
        }
#pragma unroll
        for (int ni = 0; ni < 3; ni++) {
            if (ni < ntn) {
                int col = (nt0 + ni) * 8 + 2 * lc;
                if (col < 65) {
                    float bb = lmb[col];
                    ls[(m0 + lr) * 66 + col] = acc[ni][0] + bb;
                    ls[(m0 + lr + 8) * 66 + col] = acc[ni][2] + bb;
                }
                if (col + 1 < 65) {
                    float bb = lmb[col + 1];
                    ls[(m0 + lr) * 66 + col + 1] = acc[ni][1] + bb;
                    ls[(m0 + lr + 8) * 66 + col + 1] = acc[ni][3] + bb;
                }
            }
        }
        __syncthreads();

        for (int i = tid; i < 128 * 65; i += 1024) {
            int r = i / 65, c = i - r * 65;
            logits[row0 * 65 + i] = ls[r * 66 + c];
        }
#pragma unroll
        for (int rr = 0; rr < 4; rr++) {
            int t = wid * 4 + rr;
            float v0 = ls[t * 66 + lane];
            float v1 = ls[t * 66 + lane + 32];
            float v2 = (lane == 0) ? ls[t * 66 + 64] : -1e30f;
            float mx = fmaxf(fmaxf(v0, v1), v2);
#pragma unroll
            for (int o = 16; o; o >>= 1)
                mx = fmaxf(mx, __shfl_xor_sync(0xffffffffu, mx, o));
            float se = expf(v0 - mx) + expf(v1 - mx) + expf(v2 - mx);
#pragma unroll
            for (int o = 16; o; o >>= 1) se += __shfl_xor_sync(0xffffffffu, se, o);
            if (lane == 0) {
                int tg = tgt[row0 + t];
                tokloss[row0 + t] = -(ls[t * 66 + tg] - mx - logf(se));
            }
        }
    }
}

// ---------------------------------------------------------------------------
__global__ void reduce1_kernel(const float* __restrict__ tl,
                               double* __restrict__ part) {
    __shared__ double smd[256];
    long base = (long)blockIdx.x * (NTOK / 512);
    double s = 0.0;
    for (int i = threadIdx.x; i < NTOK / 512; i += 256) s += (double)tl[base + i];
    smd[threadIdx.x] = s;
    __syncthreads();
    for (int o = 128; o; o >>= 1) {
        if (threadIdx.x < o) smd[threadIdx.x] += smd[threadIdx.x + o];
        __syncthreads();
    }
    if (threadIdx.x == 0) part[blockIdx.x] = smd[0];
}

__global__ void reduce2_kernel(const double* __restrict__ part,
                               float* __restrict__ out) {
    __shared__ double smd[512];
    smd[threadIdx.x] = part[threadIdx.x];
    __syncthreads();
    for (int o = 256; o; o >>= 1) {
        if (threadIdx.x < o) smd[threadIdx.x] += smd[threadIdx.x + o];
        __syncthreads();
    }
    if (threadIdx.x == 0) out[0] = (float)(smd[0] / (double)NTOK);
}

// ---------------------------------------------------------------------------
extern "C" void kernel_launch(void* const* d_in, const int* in_sizes, int n_in,
                              void* d_out, int out_size) {
    const float* tok_emb = (const float*)d_in[0];
    const float* pos_emb = (const float*)d_in[1];
    const float* ln1_g   = (const float*)d_in[2];
    const float* ln1_b   = (const float*)d_in[3];
    const float* wq      = (const float*)d_in[4];
    const float* wk      = (const float*)d_in[5];
    const float* wv      = (const float*)d_in[6];
    const float* wo      = (const float*)d_in[7];
    const float* bo      = (const float*)d_in[8];
    const float* ln2_g   = (const float*)d_in[9];
    const float* ln2_b   = (const float*)d_in[10];
    const float* w1      = (const float*)d_in[11];
    const float* b1      = (const float*)d_in[12];
    const float* w2      = (const float*)d_in[13];
    const float* b2      = (const float*)d_in[14];
    const float* lnf_g   = (const float*)d_in[15];
    const float* lnf_b   = (const float*)d_in[16];
    const float* lm_w    = (const float*)d_in[17];
    const float* lm_b    = (const float*)d_in[18];
    const int*   idx     = (const int*)d_in[19];
    const int*   targets = (const int*)d_in[20];

    float *x, *lg, *tl;
    double* part;
    cudaGetSymbolAddress((void**)&x,  g_x);
    cudaGetSymbolAddress((void**)&lg, g_logits);
    cudaGetSymbolAddress((void**)&tl, g_tokloss);
    cudaGetSymbolAddress((void**)&part, g_partial);

    float* outp = (float*)d_out;
    const long LSZ = (long)NTOK * NVOCAB;
    float* logits = ((long)out_size >= LSZ) ? outp : lg;
    float* lossp;
    if ((long)out_size >= LSZ + 1)      lossp = outp + LSZ;
    else if (out_size == 1)             lossp = outp;
    else                                lossp = tl;

    const int SMEM = 56320 * 4;   // 225280 B
    cudaFuncSetAttribute(layer_fused<0>, cudaFuncAttributeMaxDynamicSharedMemorySize, SMEM);
    cudaFuncSetAttribute(layer_fused<1>, cudaFuncAttributeMaxDynamicSharedMemorySize, SMEM);
    cudaFuncSetAttribute(layer_fused<2>, cudaFuncAttributeMaxDynamicSharedMemorySize, SMEM);

    layer_fused<0><<<4096, 1024, SMEM>>>(
        x, idx, tok_emb, pos_emb,
        ln1_g, ln1_b, wq, wk, wv, wo, bo, ln2_g, ln2_b,
        w1, b1, w2, b2, lnf_g, lnf_b, lm_w, lm_b, targets,
        x, logits, tl);
    layer_fused<1><<<4096, 1024, SMEM>>>(
        x, idx, tok_emb, pos_emb,
        ln1_g + 64, ln1_b + 64, wq + 4096, wk + 4096, wv + 4096,
        wo + 4096, bo + 64, ln2_g + 64, ln2_b + 64,
        w1 + 64 * 256, b1 + 256, w2 + 256 * 64, b2 + 64,
        lnf_g, lnf_b, lm_w, lm_b, targets,
        x, logits, tl);
    layer_fused<2><<<4096, 1024, SMEM>>>(
        x, idx, tok_emb, pos_emb,
        ln1_g + 128, ln1_b + 128, wq + 8192, wk + 8192, wv + 8192,
        wo + 8192, bo + 128, ln2_g + 128, ln2_b + 128,
        w1 + 2 * 64 * 256, b1 + 512, w2 + 2 * 256 * 64, b2 + 128,
        lnf_g, lnf_b, lm_w, lm_b, targets,
        x, logits, tl);
    reduce1_kernel<<<512, 256>>>(tl, part);
    reduce2_kernel<<<1, 512>>>(part, lossp);
}

// round 9
// speedup vs baseline: 2.7423x; 1.0123x over previous
#include <cuda_runtime.h>
#include <cstdint>

// ---------------------------------------------------------------------------
// 3-layer transformer forward. B=4096, T=128, D=64, H=8, HD=8, DF=256, V=65.
// Round 9: attention P-fragment handoff via warp-local smem scratch
// (replaces 8xSHFL+4xSEL per tile with 2xSTS.64 + 1xldsm4), fast-math loss.
// ---------------------------------------------------------------------------

#define NTOK (4096 * 128)
#define TSEQ 128
#define DMODEL 64
#define NVOCAB 65
#define NHEAD 8
#define DFF 256
#define NLAYER 3

__device__ float g_x[(size_t)NTOK * DMODEL];
__device__ float g_logits[(size_t)NTOK * NVOCAB];
__device__ float g_tokloss[NTOK];
__device__ double g_partial[512];

// ---------------------------------------------------------------------------
__device__ __forceinline__ unsigned f2tf(float f) {
    unsigned r;
    asm("cvt.rna.tf32.f32 %0, %1;" : "=r"(r) : "f"(f));
    return r;
}

__device__ __forceinline__ unsigned s2u(const void* p) {
    return (unsigned)__cvta_generic_to_shared(p);
}

__device__ __forceinline__ void ldsm4(unsigned* d, unsigned addr) {
    asm volatile(
        "ldmatrix.sync.aligned.m8n8.x4.shared.b16 {%0,%1,%2,%3}, [%4];"
        : "=r"(d[0]), "=r"(d[1]), "=r"(d[2]), "=r"(d[3]) : "r"(addr));
}

__device__ __forceinline__ void ldsm2(unsigned* d, unsigned addr) {
    asm volatile(
        "ldmatrix.sync.aligned.m8n8.x2.shared.b16 {%0,%1}, [%2];"
        : "=r"(d[0]), "=r"(d[1]) : "r"(addr));
}

__device__ __forceinline__ void mma_tf32(float* c, const unsigned* a,
                                         const unsigned* b) {
    asm volatile(
        "mma.sync.aligned.m16n8k8.row.col.f32.tf32.tf32.f32 "
        "{%0,%1,%2,%3},{%4,%5,%6,%7},{%8,%9},{%0,%1,%2,%3};"
        : "+f"(c[0]), "+f"(c[1]), "+f"(c[2]), "+f"(c[3])
        : "r"(a[0]), "r"(a[1]), "r"(a[2]), "r"(a[3]), "r"(b[0]), "r"(b[1]));
}

__device__ __forceinline__ void warp_ln(const float* __restrict__ rowp, int lane,
                                        float gg0, float gg1, float bb0, float bb1,
                                        float& o0, float& o1) {
    float a0 = rowp[lane];
    float a1 = rowp[lane + 32];
    float s = a0 + a1;
#pragma unroll
    for (int o = 16; o; o >>= 1) s += __shfl_xor_sync(0xffffffffu, s, o);
    float mu = s * (1.0f / 64.0f);
    float d0 = a0 - mu, d1 = a1 - mu;
    float vs = d0 * d0 + d1 * d1;
#pragma unroll
    for (int o = 16; o; o >>= 1) vs += __shfl_xor_sync(0xffffffffu, vs, o);
    float inv = rsqrtf(vs * (1.0f / 64.0f) + 1e-5f);
    o0 = d0 * inv * gg0 + bb0;
    o1 = d1 * inv * gg1 + bb1;
}

// One attention k-tile: S-MMA, masked exp, rowsum, P -> A-fragment via
// warp-private smem scratch (conflict-free ldmatrix, stride 12), PV-MMA.
__device__ __forceinline__ void attn_tile_proc(
    float* out, float& rs0, float& rs1,
    const unsigned* aS, const unsigned* bK, const unsigned* bV,
    unsigned* st0, unsigned* st1, unsigned pldsm,
    int ni, int m, int r0, int lc) {
    float c[4] = {0.f, 0.f, 0.f, 0.f};
    mma_tf32(c, aS, bK);
    if (8 * ni + 7 <= 16 * m) {
        c[0] = __expf(c[0]); c[1] = __expf(c[1]);
        c[2] = __expf(c[2]); c[3] = __expf(c[3]);
    } else {
        int j0 = 8 * ni + 2 * lc, j1 = j0 + 1;
        c[0] = (j0 <= r0) ? __expf(c[0]) : 0.f;
        c[1] = (j1 <= r0) ? __expf(c[1]) : 0.f;
        c[2] = (j0 <= r0 + 8) ? __expf(c[2]) : 0.f;
        c[3] = (j1 <= r0 + 8) ? __expf(c[3]) : 0.f;
    }
    rs0 += c[0] + c[1];
    rs1 += c[2] + c[3];
    // previous tile's ldsm reads are complete (its PV-MMA was issued by all
    // lanes before they can reach this barrier), so scratch reuse is safe.
    __syncwarp();
    *(uint2*)st0 = make_uint2(f2tf(c[0]), f2tf(c[1]));
    *(uint2*)st1 = make_uint2(f2tf(c[2]), f2tf(c[3]));
    __syncwarp();
    unsigned aP[4];
    ldsm4(aP, pldsm);
    mma_tf32(out, aP, bV);
}

// ---------------------------------------------------------------------------
// Whole-layer fused kernel. One block = one batch (128 tokens), 1024 threads.
// MODE: 0 = first layer (embed fused), 1 = middle, 2 = last (lm_head fused).
// smem (words): xres[128][68]f | As[128][68] | qs[128][68] | ks[128][68] |
//               vsT[64][132]  | Bs[192][68]   = 56320 words = 225280 B.
// Overlays: W1s[256][68]=qs..ks, W2s[64][260]=vsT..Bs, lmw[72][68]=qs,
//           ls[128][66]f=ks; attention P-scratch = Bs[4352..10496).
// ---------------------------------------------------------------------------
template <int MODE>
__global__ __launch_bounds__(1024) void layer_fused(
    const float* __restrict__ x, const int* __restrict__ idx,
    const float* __restrict__ te, const float* __restrict__ pe,
    const float* __restrict__ ln1g, const float* __restrict__ ln1b,
    const float* __restrict__ wq, const float* __restrict__ wk,
    const float* __restrict__ wv, const float* __restrict__ wo,
    const float* __restrict__ bo,
    const float* __restrict__ ln2g, const float* __restrict__ ln2b,
    const float* __restrict__ w1, const float* __restrict__ b1,
    const float* __restrict__ w2, const float* __restrict__ b2,
    const float* __restrict__ lnfg, const float* __restrict__ lnfb,
    const float* __restrict__ lmw, const float* __restrict__ lmb,
    const int* __restrict__ tgt,
    float* __restrict__ xo, float* __restrict__ logits,
    float* __restrict__ tokloss) {
    extern __shared__ unsigned sm[];
    float* xres = (float*)sm;            // [128][68] f32
    unsigned* As = sm + 8704;            // [128][68]
    unsigned* qs = As + 8704;            // [128][68]
    unsigned* ks = qs + 8704;            // [128][68]
    unsigned* vsT = ks + 8704;           // [64][132]
    unsigned* Bs = vsT + 8448;           // [192][68]

    const int tid = threadIdx.x;
    const long row0 = (long)blockIdx.x * 128;
    const int wid = tid >> 5, lane = tid & 31;
    const int lr = lane >> 2, lc = lane & 3;

    // ---- P0: load residual x into smem (embed for MODE 0) + stage Wqkv ----
#pragma unroll
    for (int j = 0; j < 2; j++) {
        int e = tid + j * 1024;          // float4 index 0..2047
        int r = e >> 4, c4 = e & 15;
        float4 val;
        if (MODE == 0) {
            int id = idx[row0 + r];
            float4 a = ((const float4*)te)[id * 16 + c4];
            float4 p = ((const float4*)pe)[r * 16 + c4];
            val.x = a.x + p.x; val.y = a.y + p.y;
            val.z = a.z + p.z; val.w = a.w + p.w;
        } else {
            val = ((const float4*)x)[row0 * 16 + e];
        }
        *(float4*)(xres + r * 68 + c4 * 4) = val;
    }
    {
        const float* wsrc[3] = {wq, wk, wv};
#pragma unroll
        for (int s = 0; s < 3; s++) {
            const float* W = wsrc[s];
#pragma unroll
            for (int j = 0; j < 4; j++) {
                int e = tid + j * 1024;
                Bs[(s * 64 + (e & 63)) * 68 + (e >> 6)] = f2tf(W[e]);
            }
        }
    }
    __syncthreads();

    // ---- P1: LN1 xres -> As (tf32) -----------------------------------------
    {
        float gg0 = ln1g[lane], gg1 = ln1g[lane + 32];
        float bb0 = ln1b[lane], bb1 = ln1b[lane + 32];
#pragma unroll
        for (int rr = 0; rr < 4; rr++) {
            int r = wid + rr * 32;
            float o0, o1;
            warp_ln(xres + r * 68, lane, gg0, gg1, bb0, bb1, o0, o1);
            As[r * 68 + lane] = f2tf(o0);
            As[r * 68 + lane + 32] = f2tf(o1);
        }
    }
    __syncthreads();

    // ---- P2: QKV MMA (warp tile 16x48) -> qs, ks, vsT ----------------------
    {
        const int wm = wid >> 2, wn = wid & 3;
        const int m0 = wm * 16, n0 = wn * 48;
        float acc[6][4];
#pragma unroll
        for (int ni = 0; ni < 6; ni++)
#pragma unroll
            for (int e = 0; e < 4; e++) acc[ni][e] = 0.0f;
        unsigned abase = s2u(As + (m0 + (lane & 15)) * 68 + ((lane >> 4) << 2));
        unsigned bbase = s2u(Bs + (n0 + (lane & 7)) * 68 + (((lane >> 3) & 1) << 2));
#pragma unroll
        for (int k0 = 0; k0 < 64; k0 += 8) {
            unsigned a[4];
            ldsm4(a, abase + k0 * 4);
#pragma unroll
            for (int ni = 0; ni < 6; ni++) {
                unsigned b[2];
                ldsm2(b, bbase + (ni * 8 * 68 + k0) * 4);
                mma_tf32(acc[ni], a, b);
            }
        }
#pragma unroll
        for (int ni = 0; ni < 6; ni++) {
            int cg = n0 + ni * 8;
            if (cg < 64) {                           // q (pre-scaled)
                const float sc = 0.35355339059327373f;
                int col = cg + 2 * lc;
                uint2 o0, o1;
                o0.x = f2tf(acc[ni][0] * sc); o0.y = f2tf(acc[ni][1] * sc);
                o1.x = f2tf(acc[ni][2] * sc); o1.y = f2tf(acc[ni][3] * sc);
                *(uint2*)(qs + (m0 + lr) * 68 + col) = o0;
                *(uint2*)(qs + (m0 + lr + 8) * 68 + col) = o1;
            } else if (cg < 128) {                   // k
                int col = cg - 64 + 2 * lc;
                uint2 o0, o1;
                o0.x = f2tf(acc[ni][0]); o0.y = f2tf(acc[ni][1]);
                o1.x = f2tf(acc[ni][2]); o1.y = f2tf(acc[ni][3]);
                *(uint2*)(ks + (m0 + lr) * 68 + col) = o0;
                *(uint2*)(ks + (m0 + lr + 8) * 68 + col) = o1;
            } else {                                 // v, transposed
                int hd = cg - 128 + 2 * lc;
                vsT[hd * 132 + m0 + lr]           = f2tf(acc[ni][0]);
                vsT[(hd + 1) * 132 + m0 + lr]     = f2tf(acc[ni][1]);
                vsT[hd * 132 + m0 + lr + 8]       = f2tf(acc[ni][2]);
                vsT[(hd + 1) * 132 + m0 + lr + 8] = f2tf(acc[ni][3]);
            }
        }
    }
    __syncthreads();

    // ---- P3: stage Wo (col-major) into Bs; fused-pair MMA attention -------
#pragma unroll
    for (int j = 0; j < 4; j++) {
        int e = tid + j * 1024;                      // e = k*64 + n
        Bs[(e & 63) * 68 + (e >> 6)] = f2tf(wo[e]);  // rows 0..63 -> < 4352
    }
    {
        const int h = wid & 7;
        const int mb = wid >> 3;                     // 0..3
        const int m1 = mb, m2 = 7 - mb;
        const int nt1 = 2 * m1 + 2, nt2 = 2 * m2 + 2;
        const int r01 = 16 * m1 + lr, r02 = 16 * m2 + lr;
        // per-warp P scratch: 16 rows x stride 12 words, in free Bs tail
        unsigned* pscr = Bs + 4352 + wid * 192;
        unsigned* st0 = pscr + lr * 12 + 2 * lc;
        unsigned* st1 = pscr + (lr + 8) * 12 + 2 * lc;
        unsigned pldsm = s2u(pscr + (lane & 15) * 12 + ((lane >> 4) << 2));
        unsigned aS1[4], aS2[4];
        ldsm4(aS1, s2u(qs + (16 * m1 + (lane & 15)) * 68 + 8 * h + ((lane >> 4) << 2)));
        ldsm4(aS2, s2u(qs + (16 * m2 + (lane & 15)) * 68 + 8 * h + ((lane >> 4) << 2)));
        float out1[4] = {0.f, 0.f, 0.f, 0.f}, out2[4] = {0.f, 0.f, 0.f, 0.f};
        float rs10 = 0.f, rs11 = 0.f, rs20 = 0.f, rs21 = 0.f;
        unsigned kb = s2u(ks + (lane & 7) * 68 + 8 * h + (((lane >> 3) & 1) << 2));
        unsigned vb = s2u(vsT + (8 * h + (lane & 7)) * 132 + (((lane >> 3) & 1) << 2));
#pragma unroll
        for (int ni = 0; ni < 16; ni++) {
            if (ni < nt2) {
                unsigned bK[2], bV[2];
                ldsm2(bK, kb + ni * (8 * 68 * 4));
                ldsm2(bV, vb + ni * 32);
                attn_tile_proc(out2, rs20, rs21, aS2, bK, bV,
                               st0, st1, pldsm, ni, m2, r02, lc);
                if (ni < nt1)
                    attn_tile_proc(out1, rs10, rs11, aS1, bK, bV,
                                   st0, st1, pldsm, ni, m1, r01, lc);
            }
        }
#pragma unroll
        for (int t = 0; t < 2; t++) {
            float a0 = t ? rs20 : rs10, a1 = t ? rs21 : rs11;
            const float* ov = t ? out2 : out1;
            int r0 = t ? r02 : r01;
            a0 += __shfl_xor_sync(0xffffffffu, a0, 1);
            a0 += __shfl_xor_sync(0xffffffffu, a0, 2);
            a1 += __shfl_xor_sync(0xffffffffu, a1, 1);
            a1 += __shfl_xor_sync(0xffffffffu, a1, 2);
            float inv0 = 1.0f / a0, inv1 = 1.0f / a1;
            unsigned* d0 = As + r0 * 68 + 8 * h + 2 * lc;
            unsigned* d1 = As + (r0 + 8) * 68 + 8 * h + 2 * lc;
            d0[0] = f2tf(ov[0] * inv0); d0[1] = f2tf(ov[1] * inv0);
            d1[0] = f2tf(ov[2] * inv1); d1[1] = f2tf(ov[3] * inv1);
        }
    }
    __syncthreads();

    // ---- P4: Wo MMA (16x16) + bias + residual into xres --------------------
    {
        const int wm = wid >> 2, wn = wid & 3;
        const int m0 = wm * 16, n0 = wn * 16;
        float acc[2][4];
#pragma unroll
        for (int ni = 0; ni < 2; ni++)
#pragma unroll
            for (int e = 0; e < 4; e++) acc[ni][e] = 0.0f;
        unsigned abase = s2u(As + (m0 + (lane & 15)) * 68 + ((lane >> 4) << 2));
        unsigned bbase = s2u(Bs + (n0 + (lane & 7)) * 68 + (((lane >> 3) & 1) << 2));
#pragma unroll
        for (int k0 = 0; k0 < 64; k0 += 8) {
            unsigned a[4];
            ldsm4(a, abase + k0 * 4);
#pragma unroll
            for (int ni = 0; ni < 2; ni++) {
                unsigned b[2];
                ldsm2(b, bbase + (ni * 8 * 68 + k0) * 4);
                mma_tf32(acc[ni], a, b);
            }
        }
#pragma unroll
        for (int ni = 0; ni < 2; ni++) {
            int col = n0 + ni * 8 + 2 * lc;
            float2 bb = *(const float2*)(bo + col);
            float* p0 = xres + (m0 + lr) * 68 + col;
            float* p1 = xres + (m0 + lr + 8) * 68 + col;
            p0[0] += acc[ni][0] + bb.x; p0[1] += acc[ni][1] + bb.y;
            p1[0] += acc[ni][2] + bb.x; p1[1] += acc[ni][3] + bb.y;
        }
    }
    __syncthreads();

    // ---- P5: stage W1/W2; LN2 xres -> As ------------------------------------
    unsigned* W1s = qs;                   // [256][68] over qs..ks
    unsigned* W2s = vsT;                  // [64][260] over vsT..Bs
#pragma unroll
    for (int j = 0; j < 16; j++) {
        int e = tid + j * 1024;
        W1s[(e & 255) * 68 + (e >> 8)] = f2tf(w1[e]);
    }
#pragma unroll
    for (int j = 0; j < 16; j++) {
        int e = tid + j * 1024;
        W2s[(e & 63) * 260 + (e >> 6)] = f2tf(w2[e]);
    }
    {
        float gg0 = ln2g[lane], gg1 = ln2g[lane + 32];
        float bb0 = ln2b[lane], bb1 = ln2b[lane + 32];
#pragma unroll
        for (int rr = 0; rr < 4; rr++) {
            int r = wid + rr * 32;
            float o0, o1;
            warp_ln(xres + r * 68, lane, gg0, gg1, bb0, bb1, o0, o1);
            As[r * 68 + lane] = f2tf(o0);
            As[r * 68 + lane + 32] = f2tf(o1);
        }
    }
    __syncthreads();

    // ---- P6: FFN GEMM1 (16x64) + staged GEMM2 (16x16) + residual ----------
    {
        const int wm = wid >> 2, wn = wid & 3;
        const int m0 = wm * 16;
        const int n0 = wn * 64;
        float acc[8][4];
#pragma unroll
        for (int ni = 0; ni < 8; ni++)
#pragma unroll
            for (int e = 0; e < 4; e++) acc[ni][e] = 0.0f;
        unsigned abase = s2u(As + (m0 + (lane & 15)) * 68 + ((lane >> 4) << 2));
        unsigned b1base = s2u(W1s + (n0 + (lane & 7)) * 68 + (((lane >> 3) & 1) << 2));
#pragma unroll
        for (int k0 = 0; k0 < 64; k0 += 8) {
            unsigned a[4];
            ldsm4(a, abase + k0 * 4);
#pragma unroll
            for (int ni = 0; ni < 8; ni++) {
                unsigned b[2];
                ldsm2(b, b1base + (ni * 8 * 68 + k0) * 4);
                mma_tf32(acc[ni], a, b);
            }
        }

        const int n02 = wn * 16;
        float acc2[2][4];
#pragma unroll
        for (int ni = 0; ni < 2; ni++)
#pragma unroll
            for (int e = 0; e < 4; e++) acc2[ni][e] = 0.0f;
        unsigned b2base = s2u(W2s + (n02 + (lane & 7)) * 260 + (((lane >> 3) & 1) << 2));
#pragma unroll
        for (int kc = 0; kc < 4; kc++) {
            __syncthreads();
            if (wn == kc) {
#pragma unroll
                for (int ni = 0; ni < 8; ni++) {
                    int coll = ni * 8 + 2 * lc;
                    float2 bb = *(const float2*)(b1 + n0 + coll);
                    int r = m0 + lr;
                    As[r * 68 + coll]           = f2tf(fmaxf(acc[ni][0] + bb.x, 0.f));
                    As[r * 68 + coll + 1]       = f2tf(fmaxf(acc[ni][1] + bb.y, 0.f));
                    As[(r + 8) * 68 + coll]     = f2tf(fmaxf(acc[ni][2] + bb.x, 0.f));
                    As[(r + 8) * 68 + coll + 1] = f2tf(fmaxf(acc[ni][3] + bb.y, 0.f));
                }
            }
            __syncthreads();
#pragma unroll
            for (int k0 = 0; k0 < 64; k0 += 8) {
                unsigned a[4];
                ldsm4(a, abase + k0 * 4);
#pragma unroll
                for (int ni = 0; ni < 2; ni++) {
                    unsigned b[2];
                    ldsm2(b, b2base + (ni * 8 * 260 + kc * 64 + k0) * 4);
                    mma_tf32(acc2[ni], a, b);
                }
            }
        }
#pragma unroll
        for (int ni = 0; ni < 2; ni++) {
            int col = n02 + ni * 8 + 2 * lc;
            float2 bb = *(const float2*)(b2 + col);
            float v00 = xres[(m0 + lr) * 68 + col]     + acc2[ni][0] + bb.x;
            float v01 = xres[(m0 + lr) * 68 + col + 1] + acc2[ni][1] + bb.y;
            float v10 = xres[(m0 + lr + 8) * 68 + col]     + acc2[ni][2] + bb.x;
            float v11 = xres[(m0 + lr + 8) * 68 + col + 1] + acc2[ni][3] + bb.y;
            if (MODE == 2) {
                xres[(m0 + lr) * 68 + col] = v00;
                xres[(m0 + lr) * 68 + col + 1] = v01;
                xres[(m0 + lr + 8) * 68 + col] = v10;
                xres[(m0 + lr + 8) * 68 + col + 1] = v11;
            } else {
                *(float2*)(xo + (row0 + m0 + lr) * 64 + col) = make_float2(v00, v01);
                *(float2*)(xo + (row0 + m0 + lr + 8) * 64 + col) = make_float2(v10, v11);
            }
        }
    }

    // ---- P7 (last layer): LNf + lm_head MMA + logits + loss ----------------
    if (MODE == 2) {
        __syncthreads();
        unsigned* lmws = qs;              // [72][68]
        float* ls = (float*)ks;           // [128][66]
        if (tid < 7 * 68) lmws[65 * 68 + tid] = 0u;
#pragma unroll
        for (int j = 0; j < 5; j++) {
            int e = tid + j * 1024;
            if (e < 65 * 64) {
                int n = e >> 6, k = e & 63;
                lmws[n * 68 + k] = f2tf(lmw[k * 65 + n]);
            }
        }
        {
            float gg0 = lnfg[lane], gg1 = lnfg[lane + 32];
            float bb0 = lnfb[lane], bb1 = lnfb[lane + 32];
#pragma unroll
            for (int rr = 0; rr < 4; rr++) {
                int r = wid + rr * 32;
                float o0, o1;
                warp_ln(xres + r * 68, lane, gg0, gg1, bb0, bb1, o0, o1);
                As[r * 68 + lane] = f2tf(o0);
                As[r * 68 + lane + 32] = f2tf(o1);
            }
        }
        __syncthreads();

        const int m0 = (wid >> 2) * 16;
        const int nq = wid & 3;
        const int nt0 = (nq == 0) ? 0 : (nq == 1) ? 3 : (nq == 2) ? 5 : 7;
        const int ntn = (nq == 0) ? 3 : 2;
        float acc[3][4];
#pragma unroll
        for (int ni = 0; ni < 3; ni++)
#pragma unroll
            for (int e = 0; e < 4; e++) acc[ni][e] = 0.0f;
        unsigned abase = s2u(As + (m0 + (lane & 15)) * 68 + ((lane >> 4) << 2));
        unsigned bbase = s2u(lmws + (nt0 * 8 + (lane & 7)) * 68 + (((lane >> 3) & 1) << 2));
#pragma unroll
        for (int k0 = 0; k0 < 64; k0 += 8) {
            unsigned a[4];
            ldsm4(a, abase + k0 * 4);
#pragma unroll
            for (int ni = 0; ni < 3; ni++) {
                if (ni < ntn) {
                    unsigned b[2];
                    ldsm2(b, bbase + (ni * 8 * 68 + k0) * 4);
                    mma_tf32(acc[ni], a, b);
                }
            }
        }
#pragma unroll
        for (int ni = 0; ni < 3; ni++) {
            if (ni < ntn) {
                int col = (nt0 + ni) * 8 + 2 * lc;
                if (col < 65) {
                    float bb = lmb[col];
                    ls[(m0 + lr) * 66 + col] = acc[ni][0] + bb;
                    ls[(m0 + lr + 8) * 66 + col] = acc[ni][2] + bb;
                }
                if (col + 1 < 65) {
                    float bb = lmb[col + 1];
                    ls[(m0 + lr) * 66 + col + 1] = acc[ni][1] + bb;
                    ls[(m0 + lr + 8) * 66 + col + 1] = acc[ni][3] + bb;
                }
            }
        }
        __syncthreads();

        for (int i = tid; i < 128 * 65; i += 1024) {
            int r = i / 65, c = i - r * 65;
            logits[row0 * 65 + i] = ls[r * 66 + c];
        }
#pragma unroll
        for (int rr = 0; rr < 4; rr++) {
            int t = wid * 4 + rr;
            float v0 = ls[t * 66 + lane];
            float v1 = ls[t * 66 + lane + 32];
            float v2 = (lane == 0) ? ls[t * 66 + 64] : -1e30f;
            float mx = fmaxf(fmaxf(v0, v1), v2);
#pragma unroll
            for (int o = 16; o; o >>= 1)
                mx = fmaxf(mx, __shfl_xor_sync(0xffffffffu, mx, o));
            float se = __expf(v0 - mx) + __expf(v1 - mx) + __expf(v2 - mx);
#pragma unroll
            for (int o = 16; o; o >>= 1) se += __shfl_xor_sync(0xffffffffu, se, o);
            if (lane == 0) {
                int tg = tgt[row0 + t];
                tokloss[row0 + t] = -(ls[t * 66 + tg] - mx - __logf(se));
            }
        }
    }
}

// ---------------------------------------------------------------------------
__global__ void reduce1_kernel(const float* __restrict__ tl,
                               double* __restrict__ part) {
    __shared__ double smd[256];
    long base = (long)blockIdx.x * (NTOK / 512);
    double s = 0.0;
    for (int i = threadIdx.x; i < NTOK / 512; i += 256) s += (double)tl[base + i];
    smd[threadIdx.x] = s;
    __syncthreads();
    for (int o = 128; o; o >>= 1) {
        if (threadIdx.x < o) smd[threadIdx.x] += smd[threadIdx.x + o];
        __syncthreads();
    }
    if (threadIdx.x == 0) part[blockIdx.x] = smd[0];
}

__global__ void reduce2_kernel(const double* __restrict__ part,
                               float* __restrict__ out) {
    __shared__ double smd[512];
    smd[threadIdx.x] = part[threadIdx.x];
    __syncthreads();
    for (int o = 256; o; o >>= 1) {
        if (threadIdx.x < o) smd[threadIdx.x] += smd[threadIdx.x + o];
        __syncthreads();
    }
    if (threadIdx.x == 0) out[0] = (float)(smd[0] / (double)NTOK);
}

// ---------------------------------------------------------------------------
extern "C" void kernel_launch(void* const* d_in, const int* in_sizes, int n_in,
                              void* d_out, int out_size) {
    const float* tok_emb = (const float*)d_in[0];
    const float* pos_emb = (const float*)d_in[1];
    const float* ln1_g   = (const float*)d_in[2];
    const float* ln1_b   = (const float*)d_in[3];
    const float* wq      = (const float*)d_in[4];
    const float* wk      = (const float*)d_in[5];
    const float* wv      = (const float*)d_in[6];
    const float* wo      = (const float*)d_in[7];
    const float* bo      = (const float*)d_in[8];
    const float* ln2_g   = (const float*)d_in[9];
    const float* ln2_b   = (const float*)d_in[10];
    const float* w1      = (const float*)d_in[11];
    const float* b1      = (const float*)d_in[12];
    const float* w2      = (const float*)d_in[13];
    const float* b2      = (const float*)d_in[14];
    const float* lnf_g   = (const float*)d_in[15];
    const float* lnf_b   = (const float*)d_in[16];
    const float* lm_w    = (const float*)d_in[17];
    const float* lm_b    = (const float*)d_in[18];
    const int*   idx     = (const int*)d_in[19];
    const int*   targets = (const int*)d_in[20];

    float *x, *lg, *tl;
    double* part;
    cudaGetSymbolAddress((void**)&x,  g_x);
    cudaGetSymbolAddress((void**)&lg, g_logits);
    cudaGetSymbolAddress((void**)&tl, g_tokloss);
    cudaGetSymbolAddress((void**)&part, g_partial);

    float* outp = (float*)d_out;
    const long LSZ = (long)NTOK * NVOCAB;
    float* logits = ((long)out_size >= LSZ) ? outp : lg;
    float* lossp;
    if ((long)out_size >= LSZ + 1)      lossp = outp + LSZ;
    else if (out_size == 1)             lossp = outp;
    else                                lossp = tl;

    const int SMEM = 56320 * 4;   // 225280 B
    cudaFuncSetAttribute(layer_fused<0>, cudaFuncAttributeMaxDynamicSharedMemorySize, SMEM);
    cudaFuncSetAttribute(layer_fused<1>, cudaFuncAttributeMaxDynamicSharedMemorySize, SMEM);
    cudaFuncSetAttribute(layer_fused<2>, cudaFuncAttributeMaxDynamicSharedMemorySize, SMEM);

    layer_fused<0><<<4096, 1024, SMEM>>>(
        x, idx, tok_emb, pos_emb,
        ln1_g, ln1_b, wq, wk, wv, wo, bo, ln2_g, ln2_b,
        w1, b1, w2, b2, lnf_g, lnf_b, lm_w, lm_b, targets,
        x, logits, tl);
    layer_fused<1><<<4096, 1024, SMEM>>>(
        x, idx, tok_emb, pos_emb,
        ln1_g + 64, ln1_b + 64, wq + 4096, wk + 4096, wv + 4096,
        wo + 4096, bo + 64, ln2_g + 64, ln2_b + 64,
        w1 + 64 * 256, b1 + 256, w2 + 256 * 64, b2 + 64,
        lnf_g, lnf_b, lm_w, lm_b, targets,
        x, logits, tl);
    layer_fused<2><<<4096, 1024, SMEM>>>(
        x, idx, tok_emb, pos_emb,
        ln1_g + 128, ln1_b + 128, wq + 8192, wk + 8192, wv + 8192,
        wo + 8192, bo + 128, ln2_g + 128, ln2_b + 128,
        w1 + 2 * 64 * 256, b1 + 512, w2 + 2 * 256 * 64, b2 + 128,
        lnf_g, lnf_b, lm_w, lm_b, targets,
        x, logits, tl);
    reduce1_kernel<<<512, 256>>>(tl, part);
    reduce2_kernel<<<1, 512>>>(part, lossp);
}

// round 10
// speedup vs baseline: 3.0226x; 1.1022x over previous
#include <cuda_runtime.h>
#include <cstdint>

// ---------------------------------------------------------------------------
// 3-layer transformer forward. B=4096, T=128, D=64, H=8, HD=8, DF=256, V=65.
// Round 10: persistent kernels — weights staged ONCE per block per layer,
// block loops over batches. attn kernel (Wqkv+Wo resident) + ffn kernel
// (W1+W2[+lm_w] resident, lm_head fused in last layer).
// ---------------------------------------------------------------------------

#define NTOK (4096 * 128)
#define NBATCH 4096
#define TSEQ 128
#define DMODEL 64
#define NVOCAB 65
#define NHEAD 8
#define DFF 256
#define NLAYER 3
#define PGRID 152

__device__ float g_x[(size_t)NTOK * DMODEL];
__device__ float g_logits[(size_t)NTOK * NVOCAB];
__device__ float g_tokloss[NTOK];
__device__ double g_partial[512];

// ---------------------------------------------------------------------------
__device__ __forceinline__ unsigned f2tf(float f) {
    unsigned r;
    asm("cvt.rna.tf32.f32 %0, %1;" : "=r"(r) : "f"(f));
    return r;
}

__device__ __forceinline__ unsigned s2u(const void* p) {
    return (unsigned)__cvta_generic_to_shared(p);
}

__device__ __forceinline__ void ldsm4(unsigned* d, unsigned addr) {
    asm volatile(
        "ldmatrix.sync.aligned.m8n8.x4.shared.b16 {%0,%1,%2,%3}, [%4];"
        : "=r"(d[0]), "=r"(d[1]), "=r"(d[2]), "=r"(d[3]) : "r"(addr));
}

__device__ __forceinline__ void ldsm2(unsigned* d, unsigned addr) {
    asm volatile(
        "ldmatrix.sync.aligned.m8n8.x2.shared.b16 {%0,%1}, [%2];"
        : "=r"(d[0]), "=r"(d[1]) : "r"(addr));
}

__device__ __forceinline__ void mma_tf32(float* c, const unsigned* a,
                                         const unsigned* b) {
    asm volatile(
        "mma.sync.aligned.m16n8k8.row.col.f32.tf32.tf32.f32 "
        "{%0,%1,%2,%3},{%4,%5,%6,%7},{%8,%9},{%0,%1,%2,%3};"
        : "+f"(c[0]), "+f"(c[1]), "+f"(c[2]), "+f"(c[3])
        : "r"(a[0]), "r"(a[1]), "r"(a[2]), "r"(a[3]), "r"(b[0]), "r"(b[1]));
}

__device__ __forceinline__ void warp_ln(const float* __restrict__ rowp, int lane,
                                        float gg0, float gg1, float bb0, float bb1,
                                        float& o0, float& o1) {
    float a0 = rowp[lane];
    float a1 = rowp[lane + 32];
    float s = a0 + a1;
#pragma unroll
    for (int o = 16; o; o >>= 1) s += __shfl_xor_sync(0xffffffffu, s, o);
    float mu = s * (1.0f / 64.0f);
    float d0 = a0 - mu, d1 = a1 - mu;
    float vs = d0 * d0 + d1 * d1;
#pragma unroll
    for (int o = 16; o; o >>= 1) vs += __shfl_xor_sync(0xffffffffu, vs, o);
    float inv = rsqrtf(vs * (1.0f / 64.0f) + 1e-5f);
    o0 = d0 * inv * gg0 + bb0;
    o1 = d1 * inv * gg1 + bb1;
}

// One attention k-tile: S-MMA, masked exp, rowsum, shuffle P->A frag, PV-MMA.
__device__ __forceinline__ void attn_tile_proc(
    float* out, float& rs0, float& rs1,
    const unsigned* aS, const unsigned* bK, const unsigned* bV,
    int ni, int m, int r0, int lc, int src1, int src2, int par) {
    float c[4] = {0.f, 0.f, 0.f, 0.f};
    mma_tf32(c, aS, bK);
    if (8 * ni + 7 <= 16 * m) {
        c[0] = __expf(c[0]); c[1] = __expf(c[1]);
        c[2] = __expf(c[2]); c[3] = __expf(c[3]);
    } else {
        int j0 = 8 * ni + 2 * lc, j1 = j0 + 1;
        c[0] = (j0 <= r0) ? __expf(c[0]) : 0.f;
        c[1] = (j1 <= r0) ? __expf(c[1]) : 0.f;
        c[2] = (j0 <= r0 + 8) ? __expf(c[2]) : 0.f;
        c[3] = (j1 <= r0 + 8) ? __expf(c[3]) : 0.f;
    }
    rs0 += c[0] + c[1];
    rs1 += c[2] + c[3];
    float t0 = __shfl_sync(0xffffffffu, c[0], src1);
    float t1 = __shfl_sync(0xffffffffu, c[1], src1);
    float t2 = __shfl_sync(0xffffffffu, c[2], src1);
    float t3 = __shfl_sync(0xffffffffu, c[3], src1);
    float u0 = __shfl_sync(0xffffffffu, c[0], src2);
    float u1 = __shfl_sync(0xffffffffu, c[1], src2);
    float u2 = __shfl_sync(0xffffffffu, c[2], src2);
    float u3 = __shfl_sync(0xffffffffu, c[3], src2);
    unsigned aP[4];
    aP[0] = f2tf(par ? t1 : t0);
    aP[1] = f2tf(par ? t3 : t2);
    aP[2] = f2tf(par ? u1 : u0);
    aP[3] = f2tf(par ? u3 : u2);
    mma_tf32(out, aP, bV);
}

// ---------------------------------------------------------------------------
__global__ void embed_kernel(const int* __restrict__ idx,
                             const float4* __restrict__ te,
                             const float4* __restrict__ pe,
                             float4* __restrict__ x) {
    long i = (long)blockIdx.x * blockDim.x + threadIdx.x;
    if (i >= (long)NTOK * 16) return;
    long tok = i >> 4;
    int d4 = (int)(i & 15);
    int id = idx[tok];
    int t = (int)(tok & (TSEQ - 1));
    float4 a = te[(long)id * 16 + d4];
    float4 p = pe[(long)t * 16 + d4];
    float4 r;
    r.x = a.x + p.x; r.y = a.y + p.y; r.z = a.z + p.z; r.w = a.w + p.w;
    x[i] = r;
}

// ---------------------------------------------------------------------------
// Persistent attention kernel: LN1 + QKV MMA + MMA attention + Wo MMA + res.
// Weights (Wqkv, Wo) staged once; block loops over batches.
// smem (words): As[128][68] | qs[128][68] | ks[128][68] | vsT[64][132] |
//               Ws[192][68] | Wos[64][68]  = 51968 words = 207872 B.
// ---------------------------------------------------------------------------
__global__ __launch_bounds__(1024) void attn_p(
    float* __restrict__ x,
    const float* __restrict__ lng, const float* __restrict__ lnb,
    const float* __restrict__ wq, const float* __restrict__ wk,
    const float* __restrict__ wv, const float* __restrict__ wo,
    const float* __restrict__ bo) {
    extern __shared__ unsigned sm[];
    unsigned* As = sm;                   // [128][68]
    unsigned* qs = As + 8704;            // [128][68]
    unsigned* ks = qs + 8704;            // [128][68]
    unsigned* vsT = ks + 8704;           // [64][132]
    unsigned* Ws = vsT + 8448;           // [192][68]
    unsigned* Wos = Ws + 13056;          // [64][68]

    const int tid = threadIdx.x;
    const int wid = tid >> 5, lane = tid & 31;
    const int lr = lane >> 2, lc = lane & 3;

    // ---- stage weights ONCE ------------------------------------------------
    {
        const float* wsrc[3] = {wq, wk, wv};
#pragma unroll
        for (int s = 0; s < 3; s++) {
            const float* W = wsrc[s];
#pragma unroll
            for (int j = 0; j < 4; j++) {
                int e = tid + j * 1024;
                Ws[(s * 64 + (e & 63)) * 68 + (e >> 6)] = f2tf(W[e]);
            }
        }
#pragma unroll
        for (int j = 0; j < 4; j++) {
            int e = tid + j * 1024;          // e = k*64 + n
            Wos[(e & 63) * 68 + (e >> 6)] = f2tf(wo[e]);
        }
    }
    const float gg0 = lng[lane], gg1 = lng[lane + 32];
    const float bbl0 = lnb[lane], bbl1 = lnb[lane + 32];

    // hoisted fragment base addresses
    const int wm = wid >> 2, wn = wid & 3;
    const int m0q = wm * 16, n0q = wn * 48;
    const unsigned qkv_a = s2u(As + (m0q + (lane & 15)) * 68 + ((lane >> 4) << 2));
    const unsigned qkv_b = s2u(Ws + (n0q + (lane & 7)) * 68 + (((lane >> 3) & 1) << 2));
    const int h = wid & 7;
    const int mb = wid >> 3;
    const int m1 = mb, m2 = 7 - mb;
    const int nt1 = 2 * m1 + 2, nt2 = 2 * m2 + 2;
    const int r01 = 16 * m1 + lr, r02 = 16 * m2 + lr;
    const int src1 = (lane & 28) | (lc >> 1);
    const int src2 = src1 + 2;
    const int par = lc & 1;
    const unsigned aS1a = s2u(qs + (16 * m1 + (lane & 15)) * 68 + 8 * h + ((lane >> 4) << 2));
    const unsigned aS2a = s2u(qs + (16 * m2 + (lane & 15)) * 68 + 8 * h + ((lane >> 4) << 2));
    const unsigned kb = s2u(ks + (lane & 7) * 68 + 8 * h + (((lane >> 3) & 1) << 2));
    const unsigned vb = s2u(vsT + (8 * h + (lane & 7)) * 132 + (((lane >> 3) & 1) << 2));
    const int n0o = wn * 16;
    const unsigned wo_b = s2u(Wos + (n0o + (lane & 7)) * 68 + (((lane >> 3) & 1) << 2));

    for (int b = blockIdx.x; b < NBATCH; b += PGRID) {
        const long row0 = (long)b * 128;
        __syncthreads();   // protect As/qs/ks/vsT reuse across iterations

        // ---- LN1 -> As (tf32) ----------------------------------------------
#pragma unroll
        for (int rr = 0; rr < 4; rr++) {
            int r = wid + rr * 32;
            float o0, o1;
            warp_ln(x + (row0 + r) * 64, lane, gg0, gg1, bbl0, bbl1, o0, o1);
            As[r * 68 + lane] = f2tf(o0);
            As[r * 68 + lane + 32] = f2tf(o1);
        }
        __syncthreads();

        // ---- QKV MMA (16x48) -> qs, ks, vsT --------------------------------
        {
            float acc[6][4];
#pragma unroll
            for (int ni = 0; ni < 6; ni++)
#pragma unroll
                for (int e = 0; e < 4; e++) acc[ni][e] = 0.0f;
#pragma unroll
            for (int k0 = 0; k0 < 64; k0 += 8) {
                unsigned a[4];
                ldsm4(a, qkv_a + k0 * 4);
#pragma unroll
                for (int ni = 0; ni < 6; ni++) {
                    unsigned bfr[2];
                    ldsm2(bfr, qkv_b + (ni * 8 * 68 + k0) * 4);
                    mma_tf32(acc[ni], a, bfr);
                }
            }
#pragma unroll
            for (int ni = 0; ni < 6; ni++) {
                int cg = n0q + ni * 8;
                if (cg < 64) {                       // q (pre-scaled)
                    const float sc = 0.35355339059327373f;
                    int col = cg + 2 * lc;
                    *(uint2*)(qs + (m0q + lr) * 68 + col) =
                        make_uint2(f2tf(acc[ni][0] * sc), f2tf(acc[ni][1] * sc));
                    *(uint2*)(qs + (m0q + lr + 8) * 68 + col) =
                        make_uint2(f2tf(acc[ni][2] * sc), f2tf(acc[ni][3] * sc));
                } else if (cg < 128) {               // k
                    int col = cg - 64 + 2 * lc;
                    *(uint2*)(ks + (m0q + lr) * 68 + col) =
                        make_uint2(f2tf(acc[ni][0]), f2tf(acc[ni][1]));
                    *(uint2*)(ks + (m0q + lr + 8) * 68 + col) =
                        make_uint2(f2tf(acc[ni][2]), f2tf(acc[ni][3]));
                } else {                             // v, transposed
                    int hd = cg - 128 + 2 * lc;
                    vsT[hd * 132 + m0q + lr]           = f2tf(acc[ni][0]);
                    vsT[(hd + 1) * 132 + m0q + lr]     = f2tf(acc[ni][1]);
                    vsT[hd * 132 + m0q + lr + 8]       = f2tf(acc[ni][2]);
                    vsT[(hd + 1) * 132 + m0q + lr + 8] = f2tf(acc[ni][3]);
                }
            }
        }
        __syncthreads();

        // ---- fused-pair MMA attention -> As --------------------------------
        {
            unsigned aS1[4], aS2[4];
            ldsm4(aS1, aS1a);
            ldsm4(aS2, aS2a);
            float out1[4] = {0.f, 0.f, 0.f, 0.f}, out2[4] = {0.f, 0.f, 0.f, 0.f};
            float rs10 = 0.f, rs11 = 0.f, rs20 = 0.f, rs21 = 0.f;
#pragma unroll
            for (int ni = 0; ni < 16; ni++) {
                if (ni < nt2) {
                    unsigned bK[2], bV[2];
                    ldsm2(bK, kb + ni * (8 * 68 * 4));
                    ldsm2(bV, vb + ni * 32);
                    attn_tile_proc(out2, rs20, rs21, aS2, bK, bV, ni, m2, r02,
                                   lc, src1, src2, par);
                    if (ni < nt1)
                        attn_tile_proc(out1, rs10, rs11, aS1, bK, bV, ni, m1, r01,
                                       lc, src1, src2, par);
                }
            }
#pragma unroll
            for (int t = 0; t < 2; t++) {
                float a0 = t ? rs20 : rs10, a1 = t ? rs21 : rs11;
                const float* ov = t ? out2 : out1;
                int r0 = t ? r02 : r01;
                a0 += __shfl_xor_sync(0xffffffffu, a0, 1);
                a0 += __shfl_xor_sync(0xffffffffu, a0, 2);
                a1 += __shfl_xor_sync(0xffffffffu, a1, 1);
                a1 += __shfl_xor_sync(0xffffffffu, a1, 2);
                float inv0 = 1.0f / a0, inv1 = 1.0f / a1;
                unsigned* d0 = As + r0 * 68 + 8 * h + 2 * lc;
                unsigned* d1 = As + (r0 + 8) * 68 + 8 * h + 2 * lc;
                d0[0] = f2tf(ov[0] * inv0); d0[1] = f2tf(ov[1] * inv0);
                d1[0] = f2tf(ov[2] * inv1); d1[1] = f2tf(ov[3] * inv1);
            }
        }
        __syncthreads();

        // ---- Wo MMA (16x16) + bias + residual rmw on x ----------------------
        {
            float acc[2][4];
#pragma unroll
            for (int ni = 0; ni < 2; ni++)
#pragma unroll
                for (int e = 0; e < 4; e++) acc[ni][e] = 0.0f;
#pragma unroll
            for (int k0 = 0; k0 < 64; k0 += 8) {
                unsigned a[4];
                ldsm4(a, qkv_a + k0 * 4);   // As, same m-tile as QKV
#pragma unroll
                for (int ni = 0; ni < 2; ni++) {
                    unsigned bfr[2];
                    ldsm2(bfr, wo_b + (ni * 8 * 68 + k0) * 4);
                    mma_tf32(acc[ni], a, bfr);
                }
            }
#pragma unroll
            for (int ni = 0; ni < 2; ni++) {
                int col = n0o + ni * 8 + 2 * lc;
                float2 bb = *(const float2*)(bo + col);
                float2* p0 = (float2*)(x + (row0 + m0q + lr) * 64 + col);
                float2* p1 = (float2*)(x + (row0 + m0q + lr + 8) * 64 + col);
                float2 r0v = *p0, r1v = *p1;
                r0v.x += acc[ni][0] + bb.x;
                r0v.y += acc[ni][1] + bb.y;
                r1v.x += acc[ni][2] + bb.x;
                r1v.y += acc[ni][3] + bb.y;
                *p0 = r0v;
                *p1 = r1v;
            }
        }
    }
}

// ---------------------------------------------------------------------------
// Persistent FFN kernel: LN2 + W1+ReLU MMA + W2 MMA + residual.
// MODE 2 additionally: LNf + lm_head MMA + logits + loss.
// smem (words): As[128][68] | W1s[256][68] | W2s[64][260]
//               [MODE2: lmws[72][68] | ls[128][66]f]
// ---------------------------------------------------------------------------
template <int MODE>
__global__ __launch_bounds__(1024) void ffn_p(
    float* __restrict__ x,
    const float* __restrict__ lng, const float* __restrict__ lnb,
    const float* __restrict__ w1, const float* __restrict__ b1,
    const float* __restrict__ w2, const float* __restrict__ b2,
    const float* __restrict__ lnfg, const float* __restrict__ lnfb,
    const float* __restrict__ lmw, const float* __restrict__ lmb,
    const int* __restrict__ tgt,
    float* __restrict__ logits, float* __restrict__ tokloss) {
    extern __shared__ unsigned sm[];
    unsigned* As = sm;                   // [128][68]
    unsigned* W1s = As + 8704;           // [256][68]
    unsigned* W2s = W1s + 17408;         // [64][260]
    unsigned* lmws = W2s + 16640;        // [72][68]   (MODE 2)
    float* ls = (float*)(lmws + 4896);   // [128][66]  (MODE 2)

    const int tid = threadIdx.x;
    const int wid = tid >> 5, lane = tid & 31;
    const int lr = lane >> 2, lc = lane & 3;

    // ---- stage weights ONCE ------------------------------------------------
#pragma unroll
    for (int j = 0; j < 16; j++) {
        int e = tid + j * 1024;
        W1s[(e & 255) * 68 + (e >> 8)] = f2tf(w1[e]);
    }
#pragma unroll
    for (int j = 0; j < 16; j++) {
        int e = tid + j * 1024;
        W2s[(e & 63) * 260 + (e >> 6)] = f2tf(w2[e]);
    }
    if (MODE == 2) {
        if (tid < 7 * 68) lmws[65 * 68 + tid] = 0u;
#pragma unroll
        for (int j = 0; j < 5; j++) {
            int e = tid + j * 1024;
            if (e < 65 * 64) {
                int n = e >> 6, k = e & 63;
                lmws[n * 68 + k] = f2tf(lmw[k * 65 + n]);
            }
        }
    }
    const float gg0 = lng[lane], gg1 = lng[lane + 32];
    const float bbl0 = lnb[lane], bbl1 = lnb[lane + 32];

    const int wm = wid >> 2, wn = wid & 3;
    const int m0 = wm * 16;
    const int n0 = wn * 64;
    const int n02 = wn * 16;
    const unsigned abase = s2u(As + (m0 + (lane & 15)) * 68 + ((lane >> 4) << 2));
    const unsigned b1base = s2u(W1s + (n0 + (lane & 7)) * 68 + (((lane >> 3) & 1) << 2));
    const unsigned b2base = s2u(W2s + (n02 + (lane & 7)) * 260 + (((lane >> 3) & 1) << 2));

    for (int b = blockIdx.x; b < NBATCH; b += PGRID) {
        const long row0 = (long)b * 128;
        __syncthreads();   // protect As reuse across iterations

        // ---- LN2 -> As (tf32) ----------------------------------------------
#pragma unroll
        for (int rr = 0; rr < 4; rr++) {
            int r = wid + rr * 32;
            float o0, o1;
            warp_ln(x + (row0 + r) * 64, lane, gg0, gg1, bbl0, bbl1, o0, o1);
            As[r * 68 + lane] = f2tf(o0);
            As[r * 68 + lane + 32] = f2tf(o1);
        }
        __syncthreads();

        // ---- GEMM1 (16x64) -------------------------------------------------
        float acc[8][4];
#pragma unroll
        for (int ni = 0; ni < 8; ni++)
#pragma unroll
            for (int e = 0; e < 4; e++) acc[ni][e] = 0.0f;
#pragma unroll
        for (int k0 = 0; k0 < 64; k0 += 8) {
            unsigned a[4];
            ldsm4(a, abase + k0 * 4);
#pragma unroll
            for (int ni = 0; ni < 8; ni++) {
                unsigned bfr[2];
                ldsm2(bfr, b1base + (ni * 8 * 68 + k0) * 4);
                mma_tf32(acc[ni], a, bfr);
            }
        }

        // ---- GEMM2 (16x16), relu(h1) staged in As chunks --------------------
        float acc2[2][4];
#pragma unroll
        for (int ni = 0; ni < 2; ni++)
#pragma unroll
            for (int e = 0; e < 4; e++) acc2[ni][e] = 0.0f;
#pragma unroll
        for (int kc = 0; kc < 4; kc++) {
            __syncthreads();
            if (wn == kc) {
#pragma unroll
                for (int ni = 0; ni < 8; ni++) {
                    int coll = ni * 8 + 2 * lc;
                    float2 bb = *(const float2*)(b1 + n0 + coll);
                    int r = m0 + lr;
                    As[r * 68 + coll]           = f2tf(fmaxf(acc[ni][0] + bb.x, 0.f));
                    As[r * 68 + coll + 1]       = f2tf(fmaxf(acc[ni][1] + bb.y, 0.f));
                    As[(r + 8) * 68 + coll]     = f2tf(fmaxf(acc[ni][2] + bb.x, 0.f));
                    As[(r + 8) * 68 + coll + 1] = f2tf(fmaxf(acc[ni][3] + bb.y, 0.f));
                }
            }
            __syncthreads();
#pragma unroll
            for (int k0 = 0; k0 < 64; k0 += 8) {
                unsigned a[4];
                ldsm4(a, abase + k0 * 4);
#pragma unroll
                for (int ni = 0; ni < 2; ni++) {
                    unsigned bfr[2];
                    ldsm2(bfr, b2base + (ni * 8 * 260 + kc * 64 + k0) * 4);
                    mma_tf32(acc2[ni], a, bfr);
                }
            }
        }

        // ---- epilogue: + bias + residual rmw on x ---------------------------
#pragma unroll
        for (int ni = 0; ni < 2; ni++) {
            int col = n02 + ni * 8 + 2 * lc;
            float2 bb = *(const float2*)(b2 + col);
            float2* p0 = (float2*)(x + (row0 + m0 + lr) * 64 + col);
            float2* p1 = (float2*)(x + (row0 + m0 + lr + 8) * 64 + col);
            float2 r0v = *p0, r1v = *p1;
            r0v.x += acc2[ni][0] + bb.x;
            r0v.y += acc2[ni][1] + bb.y;
            r1v.x += acc2[ni][2] + bb.x;
            r1v.y += acc2[ni][3] + bb.y;
            *p0 = r0v;
            *p1 = r1v;
        }

        // ---- MODE 2: LNf + lm_head + logits + loss --------------------------
        if (MODE == 2) {
            __syncthreads();   // x writes visible block-wide
            {
                float fg0 = lnfg[lane], fg1 = lnfg[lane + 32];
                float fb0 = lnfb[lane], fb1 = lnfb[lane + 32];
#pragma unroll
                for (int rr = 0; rr < 4; rr++) {
                    int r = wid + rr * 32;
                    float o0, o1;
                    warp_ln(x + (row0 + r) * 64, lane, fg0, fg1, fb0, fb1, o0, o1);
                    As[r * 68 + lane] = f2tf(o0);
                    As[r * 68 + lane + 32] = f2tf(o1);
                }
            }
            __syncthreads();

            const int mh = (wid >> 2) * 16;
            const int nq = wid & 3;
            const int nt0 = (nq == 0) ? 0 : (nq == 1) ? 3 : (nq == 2) ? 5 : 7;
            const int ntn = (nq == 0) ? 3 : 2;
            float lacc[3][4];
#pragma unroll
            for (int ni = 0; ni < 3; ni++)
#pragma unroll
                for (int e = 0; e < 4; e++) lacc[ni][e] = 0.0f;
            unsigned la = s2u(As + (mh + (lane & 15)) * 68 + ((lane >> 4) << 2));
            unsigned lb = s2u(lmws + (nt0 * 8 + (lane & 7)) * 68 + (((lane >> 3) & 1) << 2));
#pragma unroll
            for (int k0 = 0; k0 < 64; k0 += 8) {
                unsigned a[4];
                ldsm4(a, la + k0 * 4);
#pragma unroll
                for (int ni = 0; ni < 3; ni++) {
                    if (ni < ntn) {
                        unsigned bfr[2];
                        ldsm2(bfr, lb + (ni * 8 * 68 + k0) * 4);
                        mma_tf32(lacc[ni], a, bfr);
                    }
                }
            }
#pragma unroll
            for (int ni = 0; ni < 3; ni++) {
                if (ni < ntn) {
                    int col = (nt0 + ni) * 8 + 2 * lc;
                    if (col < 65) {
                        float bb = lmb[col];
                        ls[(mh + lr) * 66 + col] = lacc[ni][0] + bb;
                        ls[(mh + lr + 8) * 66 + col] = lacc[ni][2] + bb;
                    }
                    if (col + 1 < 65) {
                        float bb = lmb[col + 1];
                        ls[(mh + lr) * 66 + col + 1] = lacc[ni][1] + bb;
                        ls[(mh + lr + 8) * 66 + col + 1] = lacc[ni][3] + bb;
                    }
                }
            }
            __syncthreads();

            for (int i = tid; i < 128 * 65; i += 1024) {
                int r = i / 65, c = i - r * 65;
                logits[row0 * 65 + i] = ls[r * 66 + c];
            }
#pragma unroll
            for (int rr = 0; rr < 4; rr++) {
                int t = wid * 4 + rr;
                float v0 = ls[t * 66 + lane];
                float v1 = ls[t * 66 + lane + 32];
                float v2 = (lane == 0) ? ls[t * 66 + 64] : -1e30f;
                float mx = fmaxf(fmaxf(v0, v1), v2);
#pragma unroll
                for (int o = 16; o; o >>= 1)
                    mx = fmaxf(mx, __shfl_xor_sync(0xffffffffu, mx, o));
                float se = __expf(v0 - mx) + __expf(v1 - mx) + __expf(v2 - mx);
#pragma unroll
                for (int o = 16; o; o >>= 1)
                    se += __shfl_xor_sync(0xffffffffu, se, o);
                if (lane == 0) {
                    int tg = tgt[row0 + t];
                    tokloss[row0 + t] = -(ls[t * 66 + tg] - mx - __logf(se));
                }
            }
        }
    }
}

// ---------------------------------------------------------------------------
__global__ void reduce1_kernel(const float* __restrict__ tl,
                               double* __restrict__ part) {
    __shared__ double smd[256];
    long base = (long)blockIdx.x * (NTOK / 512);
    double s = 0.0;
    for (int i = threadIdx.x; i < NTOK / 512; i += 256) s += (double)tl[base + i];
    smd[threadIdx.x] = s;
    __syncthreads();
    for (int o = 128; o; o >>= 1) {
        if (threadIdx.x < o) smd[threadIdx.x] += smd[threadIdx.x + o];
        __syncthreads();
    }
    if (threadIdx.x == 0) part[blockIdx.x] = smd[0];
}

__global__ void reduce2_kernel(const double* __restrict__ part,
                               float* __restrict__ out) {
    __shared__ double smd[512];
    smd[threadIdx.x] = part[threadIdx.x];
    __syncthreads();
    for (int o = 256; o; o >>= 1) {
        if (threadIdx.x < o) smd[threadIdx.x] += smd[threadIdx.x + o];
        __syncthreads();
    }
    if (threadIdx.x == 0) out[0] = (float)(smd[0] / (double)NTOK);
}

// ---------------------------------------------------------------------------
extern "C" void kernel_launch(void* const* d_in, const int* in_sizes, int n_in,
                              void* d_out, int out_size) {
    const float* tok_emb = (const float*)d_in[0];
    const float* pos_emb = (const float*)d_in[1];
    const float* ln1_g   = (const float*)d_in[2];
    const float* ln1_b   = (const float*)d_in[3];
    const float* wq      = (const float*)d_in[4];
    const float* wk      = (const float*)d_in[5];
    const float* wv      = (const float*)d_in[6];
    const float* wo      = (const float*)d_in[7];
    const float* bo      = (const float*)d_in[8];
    const float* ln2_g   = (const float*)d_in[9];
    const float* ln2_b   = (const float*)d_in[10];
    const float* w1      = (const float*)d_in[11];
    const float* b1      = (const float*)d_in[12];
    const float* w2      = (const float*)d_in[13];
    const float* b2      = (const float*)d_in[14];
    const float* lnf_g   = (const float*)d_in[15];
    const float* lnf_b   = (const float*)d_in[16];
    const float* lm_w    = (const float*)d_in[17];
    const float* lm_b    = (const float*)d_in[18];
    const int*   idx     = (const int*)d_in[19];
    const int*   targets = (const int*)d_in[20];

    float *x, *lg, *tl;
    double* part;
    cudaGetSymbolAddress((void**)&x,  g_x);
    cudaGetSymbolAddress((void**)&lg, g_logits);
    cudaGetSymbolAddress((void**)&tl, g_tokloss);
    cudaGetSymbolAddress((void**)&part, g_partial);

    float* outp = (float*)d_out;
    const long LSZ = (long)NTOK * NVOCAB;
    float* logits = ((long)out_size >= LSZ) ? outp : lg;
    float* lossp;
    if ((long)out_size >= LSZ + 1)      lossp = outp + LSZ;
    else if (out_size == 1)             lossp = outp;
    else                                lossp = tl;

    const int ATTN_SMEM = 51968 * 4;   // 207872 B
    const int FFN_SMEM  = 42752 * 4;   // 171008 B
    const int FFN2_SMEM = 56096 * 4;   // 224384 B
    cudaFuncSetAttribute(attn_p,    cudaFuncAttributeMaxDynamicSharedMemorySize, ATTN_SMEM);
    cudaFuncSetAttribute(ffn_p<0>,  cudaFuncAttributeMaxDynamicSharedMemorySize, FFN_SMEM);
    cudaFuncSetAttribute(ffn_p<2>,  cudaFuncAttributeMaxDynamicSharedMemorySize, FFN2_SMEM);

    embed_kernel<<<(NTOK * 16) / 256, 256>>>(
        idx, (const float4*)tok_emb, (const float4*)pos_emb, (float4*)x);

    for (int l = 0; l < NLAYER; l++) {
        attn_p<<<PGRID, 1024, ATTN_SMEM>>>(
            x, ln1_g + l * 64, ln1_b + l * 64,
            wq + (long)l * 4096, wk + (long)l * 4096, wv + (long)l * 4096,
            wo + (long)l * 4096, bo + l * 64);
        if (l < NLAYER - 1) {
            ffn_p<0><<<PGRID, 1024, FFN_SMEM>>>(
                x, ln2_g + l * 64, ln2_b + l * 64,
                w1 + (long)l * 64 * 256, b1 + l * 256,
                w2 + (long)l * 256 * 64, b2 + l * 64,
                lnf_g, lnf_b, lm_w, lm_b, targets, logits, tl);
        } else {
            ffn_p<2><<<PGRID, 1024, FFN2_SMEM>>>(
                x, ln2_g + l * 64, ln2_b + l * 64,
                w1 + (long)l * 64 * 256, b1 + l * 256,
                w2 + (long)l * 256 * 64, b2 + l * 64,
                lnf_g, lnf_b, lm_w, lm_b, targets, logits, tl);
        }
    }
    reduce1_kernel<<<512, 256>>>(tl, part);
    reduce2_kernel<<<1, 512>>>(part, lossp);
}

// round 11
// speedup vs baseline: 3.0676x; 1.0149x over previous
#include <cuda_runtime.h>
#include <cstdint>

// ---------------------------------------------------------------------------
// 3-layer transformer forward. B=4096, T=128, D=64, H=8, HD=8, DF=256, V=65.
// Round 11: ldsm4-paired B-operand loads everywhere, raw-bit P handoff,
// double-buffered FFN GEMM2 staging. Persistent kernels as in R10.
// ---------------------------------------------------------------------------

#define NTOK (4096 * 128)
#define NBATCH 4096
#define TSEQ 128
#define DMODEL 64
#define NVOCAB 65
#define NHEAD 8
#define DFF 256
#define NLAYER 3
#define PGRID 152

__device__ float g_x[(size_t)NTOK * DMODEL];
__device__ float g_logits[(size_t)NTOK * NVOCAB];
__device__ float g_tokloss[NTOK];
__device__ double g_partial[512];

// ---------------------------------------------------------------------------
__device__ __forceinline__ unsigned f2tf(float f) {
    unsigned r;
    asm("cvt.rna.tf32.f32 %0, %1;" : "=r"(r) : "f"(f));
    return r;
}

__device__ __forceinline__ unsigned s2u(const void* p) {
    return (unsigned)__cvta_generic_to_shared(p);
}

__device__ __forceinline__ void ldsm4(unsigned* d, unsigned addr) {
    asm volatile(
        "ldmatrix.sync.aligned.m8n8.x4.shared.b16 {%0,%1,%2,%3}, [%4];"
        : "=r"(d[0]), "=r"(d[1]), "=r"(d[2]), "=r"(d[3]) : "r"(addr));
}

__device__ __forceinline__ void ldsm2(unsigned* d, unsigned addr) {
    asm volatile(
        "ldmatrix.sync.aligned.m8n8.x2.shared.b16 {%0,%1}, [%2];"
        : "=r"(d[0]), "=r"(d[1]) : "r"(addr));
}

__device__ __forceinline__ void mma_tf32(float* c, const unsigned* a,
                                         const unsigned* b) {
    asm volatile(
        "mma.sync.aligned.m16n8k8.row.col.f32.tf32.tf32.f32 "
        "{%0,%1,%2,%3},{%4,%5,%6,%7},{%8,%9},{%0,%1,%2,%3};"
        : "+f"(c[0]), "+f"(c[1]), "+f"(c[2]), "+f"(c[3])
        : "r"(a[0]), "r"(a[1]), "r"(a[2]), "r"(a[3]), "r"(b[0]), "r"(b[1]));
}

__device__ __forceinline__ void warp_ln(const float* __restrict__ rowp, int lane,
                                        float gg0, float gg1, float bb0, float bb1,
                                        float& o0, float& o1) {
    float a0 = rowp[lane];
    float a1 = rowp[lane + 32];
    float s = a0 + a1;
#pragma unroll
    for (int o = 16; o; o >>= 1) s += __shfl_xor_sync(0xffffffffu, s, o);
    float mu = s * (1.0f / 64.0f);
    float d0 = a0 - mu, d1 = a1 - mu;
    float vs = d0 * d0 + d1 * d1;
#pragma unroll
    for (int o = 16; o; o >>= 1) vs += __shfl_xor_sync(0xffffffffu, vs, o);
    float inv = rsqrtf(vs * (1.0f / 64.0f) + 1e-5f);
    o0 = d0 * inv * gg0 + bb0;
    o1 = d1 * inv * gg1 + bb1;
}

// One attention k-tile: S-MMA, masked exp, rowsum, shuffle P->A frag (raw
// fp32 bits as tf32 operands: HW truncation, P>0), PV-MMA.
__device__ __forceinline__ void attn_tile_proc(
    float* out, float& rs0, float& rs1,
    const unsigned* aS, const unsigned* bK, const unsigned* bV,
    int ni, int m, int r0, int lc, int src1, int src2, int par) {
    float c[4] = {0.f, 0.f, 0.f, 0.f};
    mma_tf32(c, aS, bK);
    if (8 * ni + 7 <= 16 * m) {
        c[0] = __expf(c[0]); c[1] = __expf(c[1]);
        c[2] = __expf(c[2]); c[3] = __expf(c[3]);
    } else {
        int j0 = 8 * ni + 2 * lc, j1 = j0 + 1;
        c[0] = (j0 <= r0) ? __expf(c[0]) : 0.f;
        c[1] = (j1 <= r0) ? __expf(c[1]) : 0.f;
        c[2] = (j0 <= r0 + 8) ? __expf(c[2]) : 0.f;
        c[3] = (j1 <= r0 + 8) ? __expf(c[3]) : 0.f;
    }
    rs0 += c[0] + c[1];
    rs1 += c[2] + c[3];
    float t0 = __shfl_sync(0xffffffffu, c[0], src1);
    float t1 = __shfl_sync(0xffffffffu, c[1], src1);
    float t2 = __shfl_sync(0xffffffffu, c[2], src1);
    float t3 = __shfl_sync(0xffffffffu, c[3], src1);
    float u0 = __shfl_sync(0xffffffffu, c[0], src2);
    float u1 = __shfl_sync(0xffffffffu, c[1], src2);
    float u2 = __shfl_sync(0xffffffffu, c[2], src2);
    float u3 = __shfl_sync(0xffffffffu, c[3], src2);
    unsigned aP[4];
    aP[0] = __float_as_uint(par ? t1 : t0);
    aP[1] = __float_as_uint(par ? t3 : t2);
    aP[2] = __float_as_uint(par ? u1 : u0);
    aP[3] = __float_as_uint(par ? u3 : u2);
    mma_tf32(out, aP, bV);
}

// ---------------------------------------------------------------------------
__global__ void embed_kernel(const int* __restrict__ idx,
                             const float4* __restrict__ te,
                             const float4* __restrict__ pe,
                             float4* __restrict__ x) {
    long i = (long)blockIdx.x * blockDim.x + threadIdx.x;
    if (i >= (long)NTOK * 16) return;
    long tok = i >> 4;
    int d4 = (int)(i & 15);
    int id = idx[tok];
    int t = (int)(tok & (TSEQ - 1));
    float4 a = te[(long)id * 16 + d4];
    float4 p = pe[(long)t * 16 + d4];
    float4 r;
    r.x = a.x + p.x; r.y = a.y + p.y; r.z = a.z + p.z; r.w = a.w + p.w;
    x[i] = r;
}

// ---------------------------------------------------------------------------
// Persistent attention kernel: LN1 + QKV MMA + MMA attention + Wo MMA + res.
// smem (words): As[128][68] | qs[128][68] | ks[128][68] | vsT[64][132] |
//               Ws[192][68] | Wos[64][68]  = 51968 words = 207872 B.
// ---------------------------------------------------------------------------
__global__ __launch_bounds__(1024) void attn_p(
    float* __restrict__ x,
    const float* __restrict__ lng, const float* __restrict__ lnb,
    const float* __restrict__ wq, const float* __restrict__ wk,
    const float* __restrict__ wv, const float* __restrict__ wo,
    const float* __restrict__ bo) {
    extern __shared__ unsigned sm[];
    unsigned* As = sm;                   // [128][68]
    unsigned* qs = As + 8704;            // [128][68]
    unsigned* ks = qs + 8704;            // [128][68]
    unsigned* vsT = ks + 8704;           // [64][132]
    unsigned* Ws = vsT + 8448;           // [192][68]
    unsigned* Wos = Ws + 13056;          // [64][68]

    const int tid = threadIdx.x;
    const int wid = tid >> 5, lane = tid & 31;
    const int lr = lane >> 2, lc = lane & 3;
    const int pl8 = ((lane >> 4) & 1) * 8;   // pair row offset for ldsm4 B
    const int hk4 = ((lane >> 3) & 1) << 2;  // k-half col offset

    // ---- stage weights ONCE ------------------------------------------------
    {
        const float* wsrc[3] = {wq, wk, wv};
#pragma unroll
        for (int s = 0; s < 3; s++) {
            const float* W = wsrc[s];
#pragma unroll
            for (int j = 0; j < 4; j++) {
                int e = tid + j * 1024;
                Ws[(s * 64 + (e & 63)) * 68 + (e >> 6)] = f2tf(W[e]);
            }
        }
#pragma unroll
        for (int j = 0; j < 4; j++) {
            int e = tid + j * 1024;          // e = k*64 + n
            Wos[(e & 63) * 68 + (e >> 6)] = f2tf(wo[e]);
        }
    }
    const float gg0 = lng[lane], gg1 = lng[lane + 32];
    const float bbl0 = lnb[lane], bbl1 = lnb[lane + 32];

    // hoisted fragment base addresses
    const int wm = wid >> 2, wn = wid & 3;
    const int m0q = wm * 16, n0q = wn * 48;
    const unsigned qkv_a = s2u(As + (m0q + (lane & 15)) * 68 + ((lane >> 4) << 2));
    const unsigned qkv_b4 = s2u(Ws + (n0q + pl8 + (lane & 7)) * 68 + hk4);
    const int h = wid & 7;
    const int mb = wid >> 3;
    const int m1 = mb, m2 = 7 - mb;
    const int nt1 = 2 * m1 + 2, nt2 = 2 * m2 + 2;
    const int r01 = 16 * m1 + lr, r02 = 16 * m2 + lr;
    const int src1 = (lane & 28) | (lc >> 1);
    const int src2 = src1 + 2;
    const int par = lc & 1;
    const unsigned aS1a = s2u(qs + (16 * m1 + (lane & 15)) * 68 + 8 * h + ((lane >> 4) << 2));
    const unsigned aS2a = s2u(qs + (16 * m2 + (lane & 15)) * 68 + 8 * h + ((lane >> 4) << 2));
    const unsigned kb4 = s2u(ks + (pl8 + (lane & 7)) * 68 + 8 * h + hk4);
    const unsigned vb4 = s2u(vsT + (8 * h + (lane & 7)) * 132 + hk4 + pl8);
    const int n0o = wn * 16;
    const unsigned wo_b4 = s2u(Wos + (n0o + pl8 + (lane & 7)) * 68 + hk4);

    for (int b = blockIdx.x; b < NBATCH; b += PGRID) {
        const long row0 = (long)b * 128;
        __syncthreads();   // protect As/qs/ks/vsT reuse across iterations

        // ---- LN1 -> As (tf32) ----------------------------------------------
#pragma unroll
        for (int rr = 0; rr < 4; rr++) {
            int r = wid + rr * 32;
            float o0, o1;
            warp_ln(x + (row0 + r) * 64, lane, gg0, gg1, bbl0, bbl1, o0, o1);
            As[r * 68 + lane] = f2tf(o0);
            As[r * 68 + lane + 32] = f2tf(o1);
        }
        __syncthreads();

        // ---- QKV MMA (16x48, paired B loads) -> qs, ks, vsT -----------------
        {
            float acc[6][4];
#pragma unroll
            for (int ni = 0; ni < 6; ni++)
#pragma unroll
                for (int e = 0; e < 4; e++) acc[ni][e] = 0.0f;
#pragma unroll
            for (int k0 = 0; k0 < 64; k0 += 8) {
                unsigned a[4];
                ldsm4(a, qkv_a + k0 * 4);
#pragma unroll
                for (int p = 0; p < 3; p++) {
                    unsigned bp[4];
                    ldsm4(bp, qkv_b4 + (p * 16 * 68 + k0) * 4);
                    mma_tf32(acc[2 * p], a, bp);
                    mma_tf32(acc[2 * p + 1], a, bp + 2);
                }
            }
#pragma unroll
            for (int ni = 0; ni < 6; ni++) {
                int cg = n0q + ni * 8;
                if (cg < 64) {                       // q (pre-scaled)
                    const float sc = 0.35355339059327373f;
                    int col = cg + 2 * lc;
                    *(uint2*)(qs + (m0q + lr) * 68 + col) =
                        make_uint2(f2tf(acc[ni][0] * sc), f2tf(acc[ni][1] * sc));
                    *(uint2*)(qs + (m0q + lr + 8) * 68 + col) =
                        make_uint2(f2tf(acc[ni][2] * sc), f2tf(acc[ni][3] * sc));
                } else if (cg < 128) {               // k
                    int col = cg - 64 + 2 * lc;
                    *(uint2*)(ks + (m0q + lr) * 68 + col) =
                        make_uint2(f2tf(acc[ni][0]), f2tf(acc[ni][1]));
                    *(uint2*)(ks + (m0q + lr + 8) * 68 + col) =
                        make_uint2(f2tf(acc[ni][2]), f2tf(acc[ni][3]));
                } else {                             // v, transposed
                    int hd = cg - 128 + 2 * lc;
                    vsT[hd * 132 + m0q + lr]           = f2tf(acc[ni][0]);
                    vsT[(hd + 1) * 132 + m0q + lr]     = f2tf(acc[ni][1]);
                    vsT[hd * 132 + m0q + lr + 8]       = f2tf(acc[ni][2]);
                    vsT[(hd + 1) * 132 + m0q + lr + 8] = f2tf(acc[ni][3]);
                }
            }
        }
        __syncthreads();

        // ---- fused-pair MMA attention (paired K/V loads) -> As --------------
        {
            unsigned aS1[4], aS2[4];
            ldsm4(aS1, aS1a);
            ldsm4(aS2, aS2a);
            float out1[4] = {0.f, 0.f, 0.f, 0.f}, out2[4] = {0.f, 0.f, 0.f, 0.f};
            float rs10 = 0.f, rs11 = 0.f, rs20 = 0.f, rs21 = 0.f;
            unsigned kaddr = kb4, vaddr = vb4;
            for (int ni = 0; ni < nt2; ni += 2) {
                unsigned bK[4], bV[4];
                ldsm4(bK, kaddr);
                ldsm4(bV, vaddr);
                kaddr += 2 * 8 * 68 * 4;
                vaddr += 64;
                attn_tile_proc(out2, rs20, rs21, aS2, bK, bV, ni, m2, r02,
                               lc, src1, src2, par);
                attn_tile_proc(out2, rs20, rs21, aS2, bK + 2, bV + 2, ni + 1,
                               m2, r02, lc, src1, src2, par);
                if (ni < nt1) {
                    attn_tile_proc(out1, rs10, rs11, aS1, bK, bV, ni, m1, r01,
                                   lc, src1, src2, par);
                    attn_tile_proc(out1, rs10, rs11, aS1, bK + 2, bV + 2,
                                   ni + 1, m1, r01, lc, src1, src2, par);
                }
            }
#pragma unroll
            for (int t = 0; t < 2; t++) {
                float a0 = t ? rs20 : rs10, a1 = t ? rs21 : rs11;
                const float* ov = t ? out2 : out1;
                int r0 = t ? r02 : r01;
                a0 += __shfl_xor_sync(0xffffffffu, a0, 1);
                a0 += __shfl_xor_sync(0xffffffffu, a0, 2);
                a1 += __shfl_xor_sync(0xffffffffu, a1, 1);
                a1 += __shfl_xor_sync(0xffffffffu, a1, 2);
                float inv0 = 1.0f / a0, inv1 = 1.0f / a1;
                unsigned* d0 = As + r0 * 68 + 8 * h + 2 * lc;
                unsigned* d1 = As + (r0 + 8) * 68 + 8 * h + 2 * lc;
                d0[0] = f2tf(ov[0] * inv0); d0[1] = f2tf(ov[1] * inv0);
                d1[0] = f2tf(ov[2] * inv1); d1[1] = f2tf(ov[3] * inv1);
            }
        }
        __syncthreads();

        // ---- Wo MMA (16x16, paired B) + bias + residual rmw on x ------------
        {
            float acc[2][4];
#pragma unroll
            for (int ni = 0; ni < 2; ni++)
#pragma unroll
                for (int e = 0; e < 4; e++) acc[ni][e] = 0.0f;
#pragma unroll
            for (int k0 = 0; k0 < 64; k0 += 8) {
                unsigned a[4];
                ldsm4(a, qkv_a + k0 * 4);   // As, same m-tile as QKV
                unsigned bp[4];
                ldsm4(bp, wo_b4 + k0 * 4);
                mma_tf32(acc[0], a, bp);
                mma_tf32(acc[1], a, bp + 2);
            }
#pragma unroll
            for (int ni = 0; ni < 2; ni++) {
                int col = n0o + ni * 8 + 2 * lc;
                float2 bb = *(const float2*)(bo + col);
                float2* p0 = (float2*)(x + (row0 + m0q + lr) * 64 + col);
                float2* p1 = (float2*)(x + (row0 + m0q + lr + 8) * 64 + col);
                float2 r0v = *p0, r1v = *p1;
                r0v.x += acc[ni][0] + bb.x;
                r0v.y += acc[ni][1] + bb.y;
                r1v.x += acc[ni][2] + bb.x;
                r1v.y += acc[ni][3] + bb.y;
                *p0 = r0v;
                *p1 = r1v;
            }
        }
    }
}

// stage relu(h1 chunk) into a buffer (warp-local, from GEMM1 accumulators)
__device__ __forceinline__ void stage_relu(
    unsigned* buf, const float acc[8][4], const float* __restrict__ b1,
    int n0, int m0, int lr, int lc) {
#pragma unroll
    for (int ni = 0; ni < 8; ni++) {
        int coll = ni * 8 + 2 * lc;
        float2 bb = *(const float2*)(b1 + n0 + coll);
        int r = m0 + lr;
        buf[r * 68 + coll]           = f2tf(fmaxf(acc[ni][0] + bb.x, 0.f));
        buf[r * 68 + coll + 1]       = f2tf(fmaxf(acc[ni][1] + bb.y, 0.f));
        buf[(r + 8) * 68 + coll]     = f2tf(fmaxf(acc[ni][2] + bb.x, 0.f));
        buf[(r + 8) * 68 + coll + 1] = f2tf(fmaxf(acc[ni][3] + bb.y, 0.f));
    }
}

// ---------------------------------------------------------------------------
// Persistent FFN kernel: LN2 + W1+ReLU MMA + W2 MMA + residual.
// MODE 0: double-buffered GEMM2 staging. MODE 2: + LNf + lm_head + loss.
// smem (words): As[128][68] | W1s[256][68] | W2s[64][260] |
//               MODE0: As2[128][68]; MODE2: lmws[72][68] | ls[128][66]f
// ---------------------------------------------------------------------------
template <int MODE>
__global__ __launch_bounds__(1024) void ffn_p(
    float* __restrict__ x,
    const float* __restrict__ lng, const float* __restrict__ lnb,
    const float* __restrict__ w1, const float* __restrict__ b1,
    const float* __restrict__ w2, const float* __restrict__ b2,
    const float* __restrict__ lnfg, const float* __restrict__ lnfb,
    const float* __restrict__ lmw, const float* __restrict__ lmb,
    const int* __restrict__ tgt,
    float* __restrict__ logits, float* __restrict__ tokloss) {
    extern __shared__ unsigned sm[];
    unsigned* As = sm;                   // [128][68]
    unsigned* W1s = As + 8704;           // [256][68]
    unsigned* W2s = W1s + 17408;         // [64][260]
    unsigned* As2 = W2s + 16640;         // [128][68]  (MODE 0 second buffer)
    unsigned* lmws = W2s + 16640;        // [72][68]   (MODE 2)
    float* ls = (float*)(lmws + 4896);   // [128][66]  (MODE 2)

    const int tid = threadIdx.x;
    const int wid = tid >> 5, lane = tid & 31;
    const int lr = lane >> 2, lc = lane & 3;
    const int pl8 = ((lane >> 4) & 1) * 8;
    const int hk4 = ((lane >> 3) & 1) << 2;

    // ---- stage weights ONCE ------------------------------------------------
#pragma unroll
    for (int j = 0; j < 16; j++) {
        int e = tid + j * 1024;
        W1s[(e & 255) * 68 + (e >> 8)] = f2tf(w1[e]);
    }
#pragma unroll
    for (int j = 0; j < 16; j++) {
        int e = tid + j * 1024;
        W2s[(e & 63) * 260 + (e >> 6)] = f2tf(w2[e]);
    }
    if (MODE == 2) {
        if (tid < 7 * 68) lmws[65 * 68 + tid] = 0u;
#pragma unroll
        for (int j = 0; j < 5; j++) {
            int e = tid + j * 1024;
            if (e < 65 * 64) {
                int n = e >> 6, k = e & 63;
                lmws[n * 68 + k] = f2tf(lmw[k * 65 + n]);
            }
        }
    }
    const float gg0 = lng[lane], gg1 = lng[lane + 32];
    const float bbl0 = lnb[lane], bbl1 = lnb[lane + 32];

    const int wm = wid >> 2, wn = wid & 3;
    const int m0 = wm * 16;
    const int n0 = wn * 64;
    const int n02 = wn * 16;
    const unsigned abase0 = s2u(As + (m0 + (lane & 15)) * 68 + ((lane >> 4) << 2));
    const unsigned abase1 = s2u(As2 + (m0 + (lane & 15)) * 68 + ((lane >> 4) << 2));
    const unsigned b1base4 = s2u(W1s + (n0 + pl8 + (lane & 7)) * 68 + hk4);
    const unsigned b2base4 = s2u(W2s + (n02 + pl8 + (lane & 7)) * 260 + hk4);

    for (int b = blockIdx.x; b < NBATCH; b += PGRID) {
        const long row0 = (long)b * 128;
        __syncthreads();   // protect As reuse across iterations

        // ---- LN2 -> As (tf32) ----------------------------------------------
#pragma unroll
        for (int rr = 0; rr < 4; rr++) {
            int r = wid + rr * 32;
            float o0, o1;
            warp_ln(x + (row0 + r) * 64, lane, gg0, gg1, bbl0, bbl1, o0, o1);
            As[r * 68 + lane] = f2tf(o0);
            As[r * 68 + lane + 32] = f2tf(o1);
        }
        __syncthreads();

        // ---- GEMM1 (16x64, paired B) -----------------------------------------
        float acc[8][4];
#pragma unroll
        for (int ni = 0; ni < 8; ni++)
#pragma unroll
            for (int e = 0; e < 4; e++) acc[ni][e] = 0.0f;
#pragma unroll
        for (int k0 = 0; k0 < 64; k0 += 8) {
            unsigned a[4];
            ldsm4(a, abase0 + k0 * 4);
#pragma unroll
            for (int p = 0; p < 4; p++) {
                unsigned bp[4];
                ldsm4(bp, b1base4 + (p * 16 * 68 + k0) * 4);
                mma_tf32(acc[2 * p], a, bp);
                mma_tf32(acc[2 * p + 1], a, bp + 2);
            }
        }

        // ---- GEMM2 (16x16, paired B), relu(h1) staged -------------------------
        float acc2[2][4];
#pragma unroll
        for (int ni = 0; ni < 2; ni++)
#pragma unroll
            for (int e = 0; e < 4; e++) acc2[ni][e] = 0.0f;

        if (MODE == 0) {
            // double-buffered: stage chunk kc+1 while computing chunk kc
            __syncthreads();                     // GEMM1 reads of As complete
            if (wn == 0) stage_relu(As, acc, b1, n0, m0, lr, lc);
            __syncthreads();
#pragma unroll
            for (int kc = 0; kc < 4; kc++) {
                if (kc < 3 && wn == kc + 1)
                    stage_relu((kc & 1) ? As : As2, acc, b1, n0, m0, lr, lc);
                unsigned ab = (kc & 1) ? abase1 : abase0;
#pragma unroll
                for (int k0 = 0; k0 < 64; k0 += 8) {
                    unsigned a[4];
                    ldsm4(a, ab + k0 * 4);
                    unsigned bp[4];
                    ldsm4(bp, b2base4 + (kc * 64 + k0) * 4);
                    mma_tf32(acc2[0], a, bp);
                    mma_tf32(acc2[1], a, bp + 2);
                }
                if (kc < 3) __syncthreads();
            }
        } else {
            // single buffer (lm_head weights occupy As2 region)
#pragma unroll
            for (int kc = 0; kc < 4; kc++) {
                __syncthreads();
                if (wn == kc) stage_relu(As, acc, b1, n0, m0, lr, lc);
                __syncthreads();
#pragma unroll
                for (int k0 = 0; k0 < 64; k0 += 8) {
                    unsigned a[4];
                    ldsm4(a, abase0 + k0 * 4);
                    unsigned bp[4];
                    ldsm4(bp, b2base4 + (kc * 64 + k0) * 4);
                    mma_tf32(acc2[0], a, bp);
                    mma_tf32(acc2[1], a, bp + 2);
                }
            }
        }

        // ---- epilogue: + bias + residual rmw on x ---------------------------
#pragma unroll
        for (int ni = 0; ni < 2; ni++) {
            int col = n02 + ni * 8 + 2 * lc;
            float2 bb = *(const float2*)(b2 + col);
            float2* p0 = (float2*)(x + (row0 + m0 + lr) * 64 + col);
            float2* p1 = (float2*)(x + (row0 + m0 + lr + 8) * 64 + col);
            float2 r0v = *p0, r1v = *p1;
            r0v.x += acc2[ni][0] + bb.x;
            r0v.y += acc2[ni][1] + bb.y;
            r1v.x += acc2[ni][2] + bb.x;
            r1v.y += acc2[ni][3] + bb.y;
            *p0 = r0v;
            *p1 = r1v;
        }

        // ---- MODE 2: LNf + lm_head + logits + loss --------------------------
        if (MODE == 2) {
            __syncthreads();   // x writes visible block-wide
            {
                float fg0 = lnfg[lane], fg1 = lnfg[lane + 32];
                float fb0 = lnfb[lane], fb1 = lnfb[lane + 32];
#pragma unroll
                for (int rr = 0; rr < 4; rr++) {
                    int r = wid + rr * 32;
                    float o0, o1;
                    warp_ln(x + (row0 + r) * 64, lane, fg0, fg1, fb0, fb1, o0, o1);
                    As[r * 68 + lane] = f2tf(o0);
                    As[r * 68 + lane + 32] = f2tf(o1);
                }
            }
            __syncthreads();

            const int mh = (wid >> 2) * 16;
            const int nq = wid & 3;
            const int nt0 = (nq == 0) ? 0 : (nq == 1) ? 3 : (nq == 2) ? 5 : 7;
            const int ntn = (nq == 0) ? 3 : 2;
            float lacc[3][4];
#pragma unroll
            for (int ni = 0; ni < 3; ni++)
#pragma unroll
                for (int e = 0; e < 4; e++) lacc[ni][e] = 0.0f;
            unsigned la = s2u(As + (mh + (lane & 15)) * 68 + ((lane >> 4) << 2));
            unsigned lb = s2u(lmws + (nt0 * 8 + (lane & 7)) * 68 + (((lane >> 3) & 1) << 2));
#pragma unroll
            for (int k0 = 0; k0 < 64; k0 += 8) {
                unsigned a[4];
                ldsm4(a, la + k0 * 4);
#pragma unroll
                for (int ni = 0; ni < 3; ni++) {
                    if (ni < ntn) {
                        unsigned bfr[2];
                        ldsm2(bfr, lb + (ni * 8 * 68 + k0) * 4);
                        mma_tf32(lacc[ni], a, bfr);
                    }
                }
            }
#pragma unroll
            for (int ni = 0; ni < 3; ni++) {
                if (ni < ntn) {
                    int col = (nt0 + ni) * 8 + 2 * lc;
                    if (col < 65) {
                        float bb = lmb[col];
                        ls[(mh + lr) * 66 + col] = lacc[ni][0] + bb;
                        ls[(mh + lr + 8) * 66 + col] = lacc[ni][2] + bb;
                    }
                    if (col + 1 < 65) {
                        float bb = lmb[col + 1];
                        ls[(mh + lr) * 66 + col + 1] = lacc[ni][1] + bb;
                        ls[(mh + lr + 8) * 66 + col + 1] = lacc[ni][3] + bb;
                    }
                }
            }
            __syncthreads();

            for (int i = tid; i < 128 * 65; i += 1024) {
                int r = i / 65, c = i - r * 65;
                logits[row0 * 65 + i] = ls[r * 66 + c];
            }
#pragma unroll
            for (int rr = 0; rr < 4; rr++) {
                int t = wid * 4 + rr;
                float v0 = ls[t * 66 + lane];
                float v1 = ls[t * 66 + lane + 32];
                float v2 = (lane == 0) ? ls[t * 66 + 64] : -1e30f;
                float mx = fmaxf(fmaxf(v0, v1), v2);
#pragma unroll
                for (int o = 16; o; o >>= 1)
                    mx = fmaxf(mx, __shfl_xor_sync(0xffffffffu, mx, o));
                float se = __expf(v0 - mx) + __expf(v1 - mx) + __expf(v2 - mx);
#pragma unroll
                for (int o = 16; o; o >>= 1)
                    se += __shfl_xor_sync(0xffffffffu, se, o);
                if (lane == 0) {
                    int tg = tgt[row0 + t];
                    tokloss[row0 + t] = -(ls[t * 66 + tg] - mx - __logf(se));
                }
            }
        }
    }
}

// ---------------------------------------------------------------------------
__global__ void reduce1_kernel(const float* __restrict__ tl,
                               double* __restrict__ part) {
    __shared__ double smd[256];
    long base = (long)blockIdx.x * (NTOK / 512);
    double s = 0.0;
    for (int i = threadIdx.x; i < NTOK / 512; i += 256) s += (double)tl[base + i];
    smd[threadIdx.x] = s;
    __syncthreads();
    for (int o = 128; o; o >>= 1) {
        if (threadIdx.x < o) smd[threadIdx.x] += smd[threadIdx.x + o];
        __syncthreads();
    }
    if (threadIdx.x == 0) part[blockIdx.x] = smd[0];
}

__global__ void reduce2_kernel(const double* __restrict__ part,
                               float* __restrict__ out) {
    __shared__ double smd[512];
    smd[threadIdx.x] = part[threadIdx.x];
    __syncthreads();
    for (int o = 256; o; o >>= 1) {
        if (threadIdx.x < o) smd[threadIdx.x] += smd[threadIdx.x + o];
        __syncthreads();
    }
    if (threadIdx.x == 0) out[0] = (float)(smd[0] / (double)NTOK);
}

// ---------------------------------------------------------------------------
extern "C" void kernel_launch(void* const* d_in, const int* in_sizes, int n_in,
                              void* d_out, int out_size) {
    const float* tok_emb = (const float*)d_in[0];
    const float* pos_emb = (const float*)d_in[1];
    const float* ln1_g   = (const float*)d_in[2];
    const float* ln1_b   = (const float*)d_in[3];
    const float* wq      = (const float*)d_in[4];
    const float* wk      = (const float*)d_in[5];
    const float* wv      = (const float*)d_in[6];
    const float* wo      = (const float*)d_in[7];
    const float* bo      = (const float*)d_in[8];
    const float* ln2_g   = (const float*)d_in[9];
    const float* ln2_b   = (const float*)d_in[10];
    const float* w1      = (const float*)d_in[11];
    const float* b1      = (const float*)d_in[12];
    const float* w2      = (const float*)d_in[13];
    const float* b2      = (const float*)d_in[14];
    const float* lnf_g   = (const float*)d_in[15];
    const float* lnf_b   = (const float*)d_in[16];
    const float* lm_w    = (const float*)d_in[17];
    const float* lm_b    = (const float*)d_in[18];
    const int*   idx     = (const int*)d_in[19];
    const int*   targets = (const int*)d_in[20];

    float *x, *lg, *tl;
    double* part;
    cudaGetSymbolAddress((void**)&x,  g_x);
    cudaGetSymbolAddress((void**)&lg, g_logits);
    cudaGetSymbolAddress((void**)&tl, g_tokloss);
    cudaGetSymbolAddress((void**)&part, g_partial);

    float* outp = (float*)d_out;
    const long LSZ = (long)NTOK * NVOCAB;
    float* logits = ((long)out_size >= LSZ) ? outp : lg;
    float* lossp;
    if ((long)out_size >= LSZ + 1)      lossp = outp + LSZ;
    else if (out_size == 1)             lossp = outp;
    else                                lossp = tl;

    const int ATTN_SMEM = 51968 * 4;   // 207872 B
    const int FFN_SMEM  = 51456 * 4;   // 205824 B (incl. As2)
    const int FFN2_SMEM = 56096 * 4;   // 224384 B
    cudaFuncSetAttribute(attn_p,    cudaFuncAttributeMaxDynamicSharedMemorySize, ATTN_SMEM);
    cudaFuncSetAttribute(ffn_p<0>,  cudaFuncAttributeMaxDynamicSharedMemorySize, FFN_SMEM);
    cudaFuncSetAttribute(ffn_p<2>,  cudaFuncAttributeMaxDynamicSharedMemorySize, FFN2_SMEM);

    embed_kernel<<<(NTOK * 16) / 256, 256>>>(
        idx, (const float4*)tok_emb, (const float4*)pos_emb, (float4*)x);

    for (int l = 0; l < NLAYER; l++) {
        attn_p<<<PGRID, 1024, ATTN_SMEM>>>(
            x, ln1_g + l * 64, ln1_b + l * 64,
            wq + (long)l * 4096, wk + (long)l * 4096, wv + (long)l * 4096,
            wo + (long)l * 4096, bo + l * 64);
        if (l < NLAYER - 1) {
            ffn_p<0><<<PGRID, 1024, FFN_SMEM>>>(
                x, ln2_g + l * 64, ln2_b + l * 64,
                w1 + (long)l * 64 * 256, b1 + l * 256,
                w2 + (long)l * 256 * 64, b2 + l * 64,
                lnf_g, lnf_b, lm_w, lm_b, targets, logits, tl);
        } else {
            ffn_p<2><<<PGRID, 1024, FFN2_SMEM>>>(
                x, ln2_g + l * 64, ln2_b + l * 64,
                w1 + (long)l * 64 * 256, b1 + l * 256,
                w2 + (long)l * 256 * 64, b2 + l * 64,
                lnf_g, lnf_b, lm_w, lm_b, targets, logits, tl);
        }
    }
    reduce1_kernel<<<512, 256>>>(tl, part);
    reduce2_kernel<<<1, 512>>>(part, lossp);
}

// round 12
// speedup vs baseline: 3.1601x; 1.0302x over previous
#include <cuda_runtime.h>
#include <cstdint>

// ---------------------------------------------------------------------------
// 3-layer transformer forward. B=4096, T=128, D=64, H=8, HD=8, DF=256, V=65.
// Round 12: embed fused into layer-0 attention, log2e folded into q scale
// (direct ex2.approx), rcp.approx softmax normalization. Persistent kernels.
// ---------------------------------------------------------------------------

#define NTOK (4096 * 128)
#define NBATCH 4096
#define TSEQ 128
#define DMODEL 64
#define NVOCAB 65
#define NHEAD 8
#define DFF 256
#define NLAYER 3
#define PGRID 152

__device__ float g_x[(size_t)NTOK * DMODEL];
__device__ float g_logits[(size_t)NTOK * NVOCAB];
__device__ float g_tokloss[NTOK];
__device__ double g_partial[512];

// ---------------------------------------------------------------------------
__device__ __forceinline__ unsigned f2tf(float f) {
    unsigned r;
    asm("cvt.rna.tf32.f32 %0, %1;" : "=r"(r) : "f"(f));
    return r;
}

__device__ __forceinline__ float ex2f(float f) {
    float r;
    asm("ex2.approx.f32 %0, %1;" : "=f"(r) : "f"(f));
    return r;
}

__device__ __forceinline__ float rcpf(float f) {
    float r;
    asm("rcp.approx.f32 %0, %1;" : "=f"(r) : "f"(f));
    return r;
}

__device__ __forceinline__ unsigned s2u(const void* p) {
    return (unsigned)__cvta_generic_to_shared(p);
}

__device__ __forceinline__ void ldsm4(unsigned* d, unsigned addr) {
    asm volatile(
        "ldmatrix.sync.aligned.m8n8.x4.shared.b16 {%0,%1,%2,%3}, [%4];"
        : "=r"(d[0]), "=r"(d[1]), "=r"(d[2]), "=r"(d[3]) : "r"(addr));
}

__device__ __forceinline__ void ldsm2(unsigned* d, unsigned addr) {
    asm volatile(
        "ldmatrix.sync.aligned.m8n8.x2.shared.b16 {%0,%1}, [%2];"
        : "=r"(d[0]), "=r"(d[1]) : "r"(addr));
}

__device__ __forceinline__ void mma_tf32(float* c, const unsigned* a,
                                         const unsigned* b) {
    asm volatile(
        "mma.sync.aligned.m16n8k8.row.col.f32.tf32.tf32.f32 "
        "{%0,%1,%2,%3},{%4,%5,%6,%7},{%8,%9},{%0,%1,%2,%3};"
        : "+f"(c[0]), "+f"(c[1]), "+f"(c[2]), "+f"(c[3])
        : "r"(a[0]), "r"(a[1]), "r"(a[2]), "r"(a[3]), "r"(b[0]), "r"(b[1]));
}

// LN on two register-resident values per lane (row distributed over a warp).
__device__ __forceinline__ void warp_ln_vals(float a0, float a1,
                                             float gg0, float gg1,
                                             float bb0, float bb1,
                                             float& o0, float& o1) {
    float s = a0 + a1;
#pragma unroll
    for (int o = 16; o; o >>= 1) s += __shfl_xor_sync(0xffffffffu, s, o);
    float mu = s * (1.0f / 64.0f);
    float d0 = a0 - mu, d1 = a1 - mu;
    float vs = d0 * d0 + d1 * d1;
#pragma unroll
    for (int o = 16; o; o >>= 1) vs += __shfl_xor_sync(0xffffffffu, vs, o);
    float inv = rsqrtf(vs * (1.0f / 64.0f) + 1e-5f);
    o0 = d0 * inv * gg0 + bb0;
    o1 = d1 * inv * gg1 + bb1;
}

// One attention k-tile: S-MMA (scores pre-scaled by log2e), ex2 in fragments,
// rowsum, shuffle P->A frag (raw fp32 bits as tf32: HW truncation), PV-MMA.
__device__ __forceinline__ void attn_tile_proc(
    float* out, float& rs0, float& rs1,
    const unsigned* aS, const unsigned* bK, const unsigned* bV,
    int ni, int m, int r0, int lc, int src1, int src2, int par) {
    float c[4] = {0.f, 0.f, 0.f, 0.f};
    mma_tf32(c, aS, bK);
    if (8 * ni + 7 <= 16 * m) {
        c[0] = ex2f(c[0]); c[1] = ex2f(c[1]);
        c[2] = ex2f(c[2]); c[3] = ex2f(c[3]);
    } else {
        int j0 = 8 * ni + 2 * lc, j1 = j0 + 1;
        c[0] = (j0 <= r0) ? ex2f(c[0]) : 0.f;
        c[1] = (j1 <= r0) ? ex2f(c[1]) : 0.f;
        c[2] = (j0 <= r0 + 8) ? ex2f(c[2]) : 0.f;
        c[3] = (j1 <= r0 + 8) ? ex2f(c[3]) : 0.f;
    }
    rs0 += c[0] + c[1];
    rs1 += c[2] + c[3];
    float t0 = __shfl_sync(0xffffffffu, c[0], src1);
    float t1 = __shfl_sync(0xffffffffu, c[1], src1);
    float t2 = __shfl_sync(0xffffffffu, c[2], src1);
    float t3 = __shfl_sync(0xffffffffu, c[3], src1);
    float u0 = __shfl_sync(0xffffffffu, c[0], src2);
    float u1 = __shfl_sync(0xffffffffu, c[1], src2);
    float u2 = __shfl_sync(0xffffffffu, c[2], src2);
    float u3 = __shfl_sync(0xffffffffu, c[3], src2);
    unsigned aP[4];
    aP[0] = __float_as_uint(par ? t1 : t0);
    aP[1] = __float_as_uint(par ? t3 : t2);
    aP[2] = __float_as_uint(par ? u1 : u0);
    aP[3] = __float_as_uint(par ? u3 : u2);
    mma_tf32(out, aP, bV);
}

// ---------------------------------------------------------------------------
// Persistent attention kernel. EMB=1: layer 0, embed computed inline
// (x = te[idx]+pe written for residual; LN fed from registers).
// smem (words): As[128][68] | qs[128][68] | ks[128][68] | vsT[64][132] |
//               Ws[192][68] | Wos[64][68]  = 51968 words = 207872 B.
// ---------------------------------------------------------------------------
template <int EMB>
__global__ __launch_bounds__(1024) void attn_p(
    float* __restrict__ x,
    const int* __restrict__ idx, const float* __restrict__ te,
    const float* __restrict__ pe,
    const float* __restrict__ lng, const float* __restrict__ lnb,
    const float* __restrict__ wq, const float* __restrict__ wk,
    const float* __restrict__ wv, const float* __restrict__ wo,
    const float* __restrict__ bo) {
    extern __shared__ unsigned sm[];
    unsigned* As = sm;                   // [128][68]
    unsigned* qs = As + 8704;            // [128][68]
    unsigned* ks = qs + 8704;            // [128][68]
    unsigned* vsT = ks + 8704;           // [64][132]
    unsigned* Ws = vsT + 8448;           // [192][68]
    unsigned* Wos = Ws + 13056;          // [64][68]

    const int tid = threadIdx.x;
    const int wid = tid >> 5, lane = tid & 31;
    const int lr = lane >> 2, lc = lane & 3;
    const int pl8 = ((lane >> 4) & 1) * 8;
    const int hk4 = ((lane >> 3) & 1) << 2;

    // ---- stage weights ONCE ------------------------------------------------
    {
        const float* wsrc[3] = {wq, wk, wv};
#pragma unroll
        for (int s = 0; s < 3; s++) {
            const float* W = wsrc[s];
#pragma unroll
            for (int j = 0; j < 4; j++) {
                int e = tid + j * 1024;
                Ws[(s * 64 + (e & 63)) * 68 + (e >> 6)] = f2tf(W[e]);
            }
        }
#pragma unroll
        for (int j = 0; j < 4; j++) {
            int e = tid + j * 1024;          // e = k*64 + n
            Wos[(e & 63) * 68 + (e >> 6)] = f2tf(wo[e]);
        }
    }
    const float gg0 = lng[lane], gg1 = lng[lane + 32];
    const float bbl0 = lnb[lane], bbl1 = lnb[lane + 32];

    // hoisted fragment base addresses
    const int wm = wid >> 2, wn = wid & 3;
    const int m0q = wm * 16, n0q = wn * 48;
    const unsigned qkv_a = s2u(As + (m0q + (lane & 15)) * 68 + ((lane >> 4) << 2));
    const unsigned qkv_b4 = s2u(Ws + (n0q + pl8 + (lane & 7)) * 68 + hk4);
    const int h = wid & 7;
    const int mb = wid >> 3;
    const int m1 = mb, m2 = 7 - mb;
    const int nt1 = 2 * m1 + 2, nt2 = 2 * m2 + 2;
    const int r01 = 16 * m1 + lr, r02 = 16 * m2 + lr;
    const int src1 = (lane & 28) | (lc >> 1);
    const int src2 = src1 + 2;
    const int par = lc & 1;
    const unsigned aS1a = s2u(qs + (16 * m1 + (lane & 15)) * 68 + 8 * h + ((lane >> 4) << 2));
    const unsigned aS2a = s2u(qs + (16 * m2 + (lane & 15)) * 68 + 8 * h + ((lane >> 4) << 2));
    const unsigned kb4 = s2u(ks + (pl8 + (lane & 7)) * 68 + 8 * h + hk4);
    const unsigned vb4 = s2u(vsT + (8 * h + (lane & 7)) * 132 + hk4 + pl8);
    const int n0o = wn * 16;
    const unsigned wo_b4 = s2u(Wos + (n0o + pl8 + (lane & 7)) * 68 + hk4);

    for (int b = blockIdx.x; b < NBATCH; b += PGRID) {
        const long row0 = (long)b * 128;
        __syncthreads();   // protect As/qs/ks/vsT reuse across iterations

        // ---- LN1 -> As (tf32); EMB: compute embed + write residual x -------
#pragma unroll
        for (int rr = 0; rr < 4; rr++) {
            int r = wid + rr * 32;
            float a0, a1;
            if (EMB) {
                int id = idx[row0 + r];
                a0 = te[id * 64 + lane] + pe[r * 64 + lane];
                a1 = te[id * 64 + lane + 32] + pe[r * 64 + lane + 32];
                x[(row0 + r) * 64 + lane] = a0;
                x[(row0 + r) * 64 + lane + 32] = a1;
            } else {
                a0 = x[(row0 + r) * 64 + lane];
                a1 = x[(row0 + r) * 64 + lane + 32];
            }
            float o0, o1;
            warp_ln_vals(a0, a1, gg0, gg1, bbl0, bbl1, o0, o1);
            As[r * 68 + lane] = f2tf(o0);
            As[r * 68 + lane + 32] = f2tf(o1);
        }
        __syncthreads();

        // ---- QKV MMA (16x48, paired B loads) -> qs, ks, vsT -----------------
        {
            float acc[6][4];
#pragma unroll
            for (int ni = 0; ni < 6; ni++)
#pragma unroll
                for (int e = 0; e < 4; e++) acc[ni][e] = 0.0f;
#pragma unroll
            for (int k0 = 0; k0 < 64; k0 += 8) {
                unsigned a[4];
                ldsm4(a, qkv_a + k0 * 4);
#pragma unroll
                for (int p = 0; p < 3; p++) {
                    unsigned bp[4];
                    ldsm4(bp, qkv_b4 + (p * 16 * 68 + k0) * 4);
                    mma_tf32(acc[2 * p], a, bp);
                    mma_tf32(acc[2 * p + 1], a, bp + 2);
                }
            }
#pragma unroll
            for (int ni = 0; ni < 6; ni++) {
                int cg = n0q + ni * 8;
                if (cg < 64) {     // q, pre-scaled by log2e/sqrt(8) for ex2
                    const float sc = 0.35355339059327373f * 1.4426950408889634f;
                    int col = cg + 2 * lc;
                    *(uint2*)(qs + (m0q + lr) * 68 + col) =
                        make_uint2(f2tf(acc[ni][0] * sc), f2tf(acc[ni][1] * sc));
                    *(uint2*)(qs + (m0q + lr + 8) * 68 + col) =
                        make_uint2(f2tf(acc[ni][2] * sc), f2tf(acc[ni][3] * sc));
                } else if (cg < 128) {               // k
                    int col = cg - 64 + 2 * lc;
                    *(uint2*)(ks + (m0q + lr) * 68 + col) =
                        make_uint2(f2tf(acc[ni][0]), f2tf(acc[ni][1]));
                    *(uint2*)(ks + (m0q + lr + 8) * 68 + col) =
                        make_uint2(f2tf(acc[ni][2]), f2tf(acc[ni][3]));
                } else {                             // v, transposed
                    int hd = cg - 128 + 2 * lc;
                    vsT[hd * 132 + m0q + lr]           = f2tf(acc[ni][0]);
                    vsT[(hd + 1) * 132 + m0q + lr]     = f2tf(acc[ni][1]);
                    vsT[hd * 132 + m0q + lr + 8]       = f2tf(acc[ni][2]);
                    vsT[(hd + 1) * 132 + m0q + lr + 8] = f2tf(acc[ni][3]);
                }
            }
        }
        __syncthreads();

        // ---- fused-pair MMA attention (paired K/V loads) -> As --------------
        {
            unsigned aS1[4], aS2[4];
            ldsm4(aS1, aS1a);
            ldsm4(aS2, aS2a);
            float out1[4] = {0.f, 0.f, 0.f, 0.f}, out2[4] = {0.f, 0.f, 0.f, 0.f};
            float rs10 = 0.f, rs11 = 0.f, rs20 = 0.f, rs21 = 0.f;
            unsigned kaddr = kb4, vaddr = vb4;
            for (int ni = 0; ni < nt2; ni += 2) {
                unsigned bK[4], bV[4];
                ldsm4(bK, kaddr);
                ldsm4(bV, vaddr);
                kaddr += 2 * 8 * 68 * 4;
                vaddr += 64;
                attn_tile_proc(out2, rs20, rs21, aS2, bK, bV, ni, m2, r02,
                               lc, src1, src2, par);
                attn_tile_proc(out2, rs20, rs21, aS2, bK + 2, bV + 2, ni + 1,
                               m2, r02, lc, src1, src2, par);
                if (ni < nt1) {
                    attn_tile_proc(out1, rs10, rs11, aS1, bK, bV, ni, m1, r01,
                                   lc, src1, src2, par);
                    attn_tile_proc(out1, rs10, rs11, aS1, bK + 2, bV + 2,
                                   ni + 1, m1, r01, lc, src1, src2, par);
                }
            }
#pragma unroll
            for (int t = 0; t < 2; t++) {
                float a0 = t ? rs20 : rs10, a1 = t ? rs21 : rs11;
                const float* ov = t ? out2 : out1;
                int r0 = t ? r02 : r01;
                a0 += __shfl_xor_sync(0xffffffffu, a0, 1);
                a0 += __shfl_xor_sync(0xffffffffu, a0, 2);
                a1 += __shfl_xor_sync(0xffffffffu, a1, 1);
                a1 += __shfl_xor_sync(0xffffffffu, a1, 2);
                float inv0 = rcpf(a0), inv1 = rcpf(a1);
                unsigned* d0 = As + r0 * 68 + 8 * h + 2 * lc;
                unsigned* d1 = As + (r0 + 8) * 68 + 8 * h + 2 * lc;
                d0[0] = f2tf(ov[0] * inv0); d0[1] = f2tf(ov[1] * inv0);
                d1[0] = f2tf(ov[2] * inv1); d1[1] = f2tf(ov[3] * inv1);
            }
        }
        __syncthreads();

        // ---- Wo MMA (16x16, paired B) + bias + residual rmw on x ------------
        {
            float acc[2][4];
#pragma unroll
            for (int ni = 0; ni < 2; ni++)
#pragma unroll
                for (int e = 0; e < 4; e++) acc[ni][e] = 0.0f;
#pragma unroll
            for (int k0 = 0; k0 < 64; k0 += 8) {
                unsigned a[4];
                ldsm4(a, qkv_a + k0 * 4);   // As, same m-tile as QKV
                unsigned bp[4];
                ldsm4(bp, wo_b4 + k0 * 4);
                mma_tf32(acc[0], a, bp);
                mma_tf32(acc[1], a, bp + 2);
            }
#pragma unroll
            for (int ni = 0; ni < 2; ni++) {
                int col = n0o + ni * 8 + 2 * lc;
                float2 bb = *(const float2*)(bo + col);
                float2* p0 = (float2*)(x + (row0 + m0q + lr) * 64 + col);
                float2* p1 = (float2*)(x + (row0 + m0q + lr + 8) * 64 + col);
                float2 r0v = *p0, r1v = *p1;
                r0v.x += acc[ni][0] + bb.x;
                r0v.y += acc[ni][1] + bb.y;
                r1v.x += acc[ni][2] + bb.x;
                r1v.y += acc[ni][3] + bb.y;
                *p0 = r0v;
                *p1 = r1v;
            }
        }
    }
}

// stage relu(h1 chunk) into a buffer (warp-local, from GEMM1 accumulators)
__device__ __forceinline__ void stage_relu(
    unsigned* buf, const float acc[8][4], const float* __restrict__ b1,
    int n0, int m0, int lr, int lc) {
#pragma unroll
    for (int ni = 0; ni < 8; ni++) {
        int coll = ni * 8 + 2 * lc;
        float2 bb = *(const float2*)(b1 + n0 + coll);
        int r = m0 + lr;
        buf[r * 68 + coll]           = f2tf(fmaxf(acc[ni][0] + bb.x, 0.f));
        buf[r * 68 + coll + 1]       = f2tf(fmaxf(acc[ni][1] + bb.y, 0.f));
        buf[(r + 8) * 68 + coll]     = f2tf(fmaxf(acc[ni][2] + bb.x, 0.f));
        buf[(r + 8) * 68 + coll + 1] = f2tf(fmaxf(acc[ni][3] + bb.y, 0.f));
    }
}

// ---------------------------------------------------------------------------
// Persistent FFN kernel: LN2 + W1+ReLU MMA + W2 MMA + residual.
// MODE 0: double-buffered GEMM2 staging. MODE 2: + LNf + lm_head + loss.
// ---------------------------------------------------------------------------
template <int MODE>
__global__ __launch_bounds__(1024) void ffn_p(
    float* __restrict__ x,
    const float* __restrict__ lng, const float* __restrict__ lnb,
    const float* __restrict__ w1, const float* __restrict__ b1,
    const float* __restrict__ w2, const float* __restrict__ b2,
    const float* __restrict__ lnfg, const float* __restrict__ lnfb,
    const float* __restrict__ lmw, const float* __restrict__ lmb,
    const int* __restrict__ tgt,
    float* __restrict__ logits, float* __restrict__ tokloss) {
    extern __shared__ unsigned sm[];
    unsigned* As = sm;                   // [128][68]
    unsigned* W1s = As + 8704;           // [256][68]
    unsigned* W2s = W1s + 17408;         // [64][260]
    unsigned* As2 = W2s + 16640;         // [128][68]  (MODE 0 second buffer)
    unsigned* lmws = W2s + 16640;        // [72][68]   (MODE 2)
    float* ls = (float*)(lmws + 4896);   // [128][66]  (MODE 2)

    const int tid = threadIdx.x;
    const int wid = tid >> 5, lane = tid & 31;
    const int lr = lane >> 2, lc = lane & 3;
    const int pl8 = ((lane >> 4) & 1) * 8;
    const int hk4 = ((lane >> 3) & 1) << 2;

    // ---- stage weights ONCE ------------------------------------------------
#pragma unroll
    for (int j = 0; j < 16; j++) {
        int e = tid + j * 1024;
        W1s[(e & 255) * 68 + (e >> 8)] = f2tf(w1[e]);
    }
#pragma unroll
    for (int j = 0; j < 16; j++) {
        int e = tid + j * 1024;
        W2s[(e & 63) * 260 + (e >> 6)] = f2tf(w2[e]);
    }
    if (MODE == 2) {
        if (tid < 7 * 68) lmws[65 * 68 + tid] = 0u;
#pragma unroll
        for (int j = 0; j < 5; j++) {
            int e = tid + j * 1024;
            if (e < 65 * 64) {
                int n = e >> 6, k = e & 63;
                lmws[n * 68 + k] = f2tf(lmw[k * 65 + n]);
            }
        }
    }
    const float gg0 = lng[lane], gg1 = lng[lane + 32];
    const float bbl0 = lnb[lane], bbl1 = lnb[lane + 32];

    const int wm = wid >> 2, wn = wid & 3;
    const int m0 = wm * 16;
    const int n0 = wn * 64;
    const int n02 = wn * 16;
    const unsigned abase0 = s2u(As + (m0 + (lane & 15)) * 68 + ((lane >> 4) << 2));
    const unsigned abase1 = s2u(As2 + (m0 + (lane & 15)) * 68 + ((lane >> 4) << 2));
    const unsigned b1base4 = s2u(W1s + (n0 + pl8 + (lane & 7)) * 68 + hk4);
    const unsigned b2base4 = s2u(W2s + (n02 + pl8 + (lane & 7)) * 260 + hk4);

    for (int b = blockIdx.x; b < NBATCH; b += PGRID) {
        const long row0 = (long)b * 128;
        __syncthreads();   // protect As reuse across iterations

        // ---- LN2 -> As (tf32) ----------------------------------------------
#pragma unroll
        for (int rr = 0; rr < 4; rr++) {
            int r = wid + rr * 32;
            float a0 = x[(row0 + r) * 64 + lane];
            float a1 = x[(row0 + r) * 64 + lane + 32];
            float o0, o1;
            warp_ln_vals(a0, a1, gg0, gg1, bbl0, bbl1, o0, o1);
            As[r * 68 + lane] = f2tf(o0);
            As[r * 68 + lane + 32] = f2tf(o1);
        }
        __syncthreads();

        // ---- GEMM1 (16x64, paired B) -----------------------------------------
        float acc[8][4];
#pragma unroll
        for (int ni = 0; ni < 8; ni++)
#pragma unroll
            for (int e = 0; e < 4; e++) acc[ni][e] = 0.0f;
#pragma unroll
        for (int k0 = 0; k0 < 64; k0 += 8) {
            unsigned a[4];
            ldsm4(a, abase0 + k0 * 4);
#pragma unroll
            for (int p = 0; p < 4; p++) {
                unsigned bp[4];
                ldsm4(bp, b1base4 + (p * 16 * 68 + k0) * 4);
                mma_tf32(acc[2 * p], a, bp);
                mma_tf32(acc[2 * p + 1], a, bp + 2);
            }
        }

        // ---- GEMM2 (16x16, paired B), relu(h1) staged -------------------------
        float acc2[2][4];
#pragma unroll
        for (int ni = 0; ni < 2; ni++)
#pragma unroll
            for (int e = 0; e < 4; e++) acc2[ni][e] = 0.0f;

        if (MODE == 0) {
            __syncthreads();                     // GEMM1 reads of As complete
            if (wn == 0) stage_relu(As, acc, b1, n0, m0, lr, lc);
            __syncthreads();
#pragma unroll
            for (int kc = 0; kc < 4; kc++) {
                if (kc < 3 && wn == kc + 1)
                    stage_relu((kc & 1) ? As : As2, acc, b1, n0, m0, lr, lc);
                unsigned ab = (kc & 1) ? abase1 : abase0;
#pragma unroll
                for (int k0 = 0; k0 < 64; k0 += 8) {
                    unsigned a[4];
                    ldsm4(a, ab + k0 * 4);
                    unsigned bp[4];
                    ldsm4(bp, b2base4 + (kc * 64 + k0) * 4);
                    mma_tf32(acc2[0], a, bp);
                    mma_tf32(acc2[1], a, bp + 2);
                }
                if (kc < 3) __syncthreads();
            }
        } else {
#pragma unroll
            for (int kc = 0; kc < 4; kc++) {
                __syncthreads();
                if (wn == kc) stage_relu(As, acc, b1, n0, m0, lr, lc);
                __syncthreads();
#pragma unroll
                for (int k0 = 0; k0 < 64; k0 += 8) {
                    unsigned a[4];
                    ldsm4(a, abase0 + k0 * 4);
                    unsigned bp[4];
                    ldsm4(bp, b2base4 + (kc * 64 + k0) * 4);
                    mma_tf32(acc2[0], a, bp);
                    mma_tf32(acc2[1], a, bp + 2);
                }
            }
        }

        // ---- epilogue: + bias + residual rmw on x ---------------------------
#pragma unroll
        for (int ni = 0; ni < 2; ni++) {
            int col = n02 + ni * 8 + 2 * lc;
            float2 bb = *(const float2*)(b2 + col);
            float2* p0 = (float2*)(x + (row0 + m0 + lr) * 64 + col);
            float2* p1 = (float2*)(x + (row0 + m0 + lr + 8) * 64 + col);
            float2 r0v = *p0, r1v = *p1;
            r0v.x += acc2[ni][0] + bb.x;
            r0v.y += acc2[ni][1] + bb.y;
            r1v.x += acc2[ni][2] + bb.x;
            r1v.y += acc2[ni][3] + bb.y;
            *p0 = r0v;
            *p1 = r1v;
        }

        // ---- MODE 2: LNf + lm_head + logits + loss --------------------------
        if (MODE == 2) {
            __syncthreads();   // x writes visible block-wide
            {
                float fg0 = lnfg[lane], fg1 = lnfg[lane + 32];
                float fb0 = lnfb[lane], fb1 = lnfb[lane + 32];
#pragma unroll
                for (int rr = 0; rr < 4; rr++) {
                    int r = wid + rr * 32;
                    float a0 = x[(row0 + r) * 64 + lane];
                    float a1 = x[(row0 + r) * 64 + lane + 32];
                    float o0, o1;
                    warp_ln_vals(a0, a1, fg0, fg1, fb0, fb1, o0, o1);
                    As[r * 68 + lane] = f2tf(o0);
                    As[r * 68 + lane + 32] = f2tf(o1);
                }
            }
            __syncthreads();

            const int mh = (wid >> 2) * 16;
            const int nq = wid & 3;
            const int nt0 = (nq == 0) ? 0 : (nq == 1) ? 3 : (nq == 2) ? 5 : 7;
            const int ntn = (nq == 0) ? 3 : 2;
            float lacc[3][4];
#pragma unroll
            for (int ni = 0; ni < 3; ni++)
#pragma unroll
                for (int e = 0; e < 4; e++) lacc[ni][e] = 0.0f;
            unsigned la = s2u(As + (mh + (lane & 15)) * 68 + ((lane >> 4) << 2));
            unsigned lb = s2u(lmws + (nt0 * 8 + (lane & 7)) * 68 + (((lane >> 3) & 1) << 2));
#pragma unroll
            for (int k0 = 0; k0 < 64; k0 += 8) {
                unsigned a[4];
                ldsm4(a, la + k0 * 4);
#pragma unroll
                for (int ni = 0; ni < 3; ni++) {
                    if (ni < ntn) {
                        unsigned bfr[2];
                        ldsm2(bfr, lb + (ni * 8 * 68 + k0) * 4);
                        mma_tf32(lacc[ni], a, bfr);
                    }
                }
            }
#pragma unroll
            for (int ni = 0; ni < 3; ni++) {
                if (ni < ntn) {
                    int col = (nt0 + ni) * 8 + 2 * lc;
                    if (col < 65) {
                        float bb = lmb[col];
                        ls[(mh + lr) * 66 + col] = lacc[ni][0] + bb;
                        ls[(mh + lr + 8) * 66 + col] = lacc[ni][2] + bb;
                    }
                    if (col + 1 < 65) {
                        float bb = lmb[col + 1];
                        ls[(mh + lr) * 66 + col + 1] = lacc[ni][1] + bb;
                        ls[(mh + lr + 8) * 66 + col + 1] = lacc[ni][3] + bb;
                    }
                }
            }
            __syncthreads();

            for (int i = tid; i < 128 * 65; i += 1024) {
                int r = i / 65, c = i - r * 65;
                logits[row0 * 65 + i] = ls[r * 66 + c];
            }
#pragma unroll
            for (int rr = 0; rr < 4; rr++) {
                int t = wid * 4 + rr;
                float v0 = ls[t * 66 + lane];
                float v1 = ls[t * 66 + lane + 32];
                float v2 = (lane == 0) ? ls[t * 66 + 64] : -1e30f;
                float mx = fmaxf(fmaxf(v0, v1), v2);
#pragma unroll
                for (int o = 16; o; o >>= 1)
                    mx = fmaxf(mx, __shfl_xor_sync(0xffffffffu, mx, o));
                float se = __expf(v0 - mx) + __expf(v1 - mx) + __expf(v2 - mx);
#pragma unroll
                for (int o = 16; o; o >>= 1)
                    se += __shfl_xor_sync(0xffffffffu, se, o);
                if (lane == 0) {
                    int tg = tgt[row0 + t];
                    tokloss[row0 + t] = -(ls[t * 66 + tg] - mx - __logf(se));
                }
            }
        }
    }
}

// ---------------------------------------------------------------------------
__global__ void reduce1_kernel(const float* __restrict__ tl,
                               double* __restrict__ part) {
    __shared__ double smd[256];
    long base = (long)blockIdx.x * (NTOK / 512);
    double s = 0.0;
    for (int i = threadIdx.x; i < NTOK / 512; i += 256) s += (double)tl[base + i];
    smd[threadIdx.x] = s;
    __syncthreads();
    for (int o = 128; o; o >>= 1) {
        if (threadIdx.x < o) smd[threadIdx.x] += smd[threadIdx.x + o];
        __syncthreads();
    }
    if (threadIdx.x == 0) part[blockIdx.x] = smd[0];
}

__global__ void reduce2_kernel(const double* __restrict__ part,
                               float* __restrict__ out) {
    __shared__ double smd[512];
    smd[threadIdx.x] = part[threadIdx.x];
    __syncthreads();
    for (int o = 256; o; o >>= 1) {
        if (threadIdx.x < o) smd[threadIdx.x] += smd[threadIdx.x + o];
        __syncthreads();
    }
    if (threadIdx.x == 0) out[0] = (float)(smd[0] / (double)NTOK);
}

// ---------------------------------------------------------------------------
extern "C" void kernel_launch(void* const* d_in, const int* in_sizes, int n_in,
                              void* d_out, int out_size) {
    const float* tok_emb = (const float*)d_in[0];
    const float* pos_emb = (const float*)d_in[1];
    const float* ln1_g   = (const float*)d_in[2];
    const float* ln1_b   = (const float*)d_in[3];
    const float* wq      = (const float*)d_in[4];
    const float* wk      = (const float*)d_in[5];
    const float* wv      = (const float*)d_in[6];
    const float* wo      = (const float*)d_in[7];
    const float* bo      = (const float*)d_in[8];
    const float* ln2_g   = (const float*)d_in[9];
    const float* ln2_b   = (const float*)d_in[10];
    const float* w1      = (const float*)d_in[11];
    const float* b1      = (const float*)d_in[12];
    const float* w2      = (const float*)d_in[13];
    const float* b2      = (const float*)d_in[14];
    const float* lnf_g   = (const float*)d_in[15];
    const float* lnf_b   = (const float*)d_in[16];
    const float* lm_w    = (const float*)d_in[17];
    const float* lm_b    = (const float*)d_in[18];
    const int*   idx     = (const int*)d_in[19];
    const int*   targets = (const int*)d_in[20];

    float *x, *lg, *tl;
    double* part;
    cudaGetSymbolAddress((void**)&x,  g_x);
    cudaGetSymbolAddress((void**)&lg, g_logits);
    cudaGetSymbolAddress((void**)&tl, g_tokloss);
    cudaGetSymbolAddress((void**)&part, g_partial);

    float* outp = (float*)d_out;
    const long LSZ = (long)NTOK * NVOCAB;
    float* logits = ((long)out_size >= LSZ) ? outp : lg;
    float* lossp;
    if ((long)out_size >= LSZ + 1)      lossp = outp + LSZ;
    else if (out_size == 1)             lossp = outp;
    else                                lossp = tl;

    const int ATTN_SMEM = 51968 * 4;   // 207872 B
    const int FFN_SMEM  = 51456 * 4;   // 205824 B (incl. As2)
    const int FFN2_SMEM = 56096 * 4;   // 224384 B
    cudaFuncSetAttribute(attn_p<0>, cudaFuncAttributeMaxDynamicSharedMemorySize, ATTN_SMEM);
    cudaFuncSetAttribute(attn_p<1>, cudaFuncAttributeMaxDynamicSharedMemorySize, ATTN_SMEM);
    cudaFuncSetAttribute(ffn_p<0>,  cudaFuncAttributeMaxDynamicSharedMemorySize, FFN_SMEM);
    cudaFuncSetAttribute(ffn_p<2>,  cudaFuncAttributeMaxDynamicSharedMemorySize, FFN2_SMEM);

    for (int l = 0; l < NLAYER; l++) {
        if (l == 0) {
            attn_p<1><<<PGRID, 1024, ATTN_SMEM>>>(
                x, idx, tok_emb, pos_emb, ln1_g, ln1_b,
                wq, wk, wv, wo, bo);
        } else {
            attn_p<0><<<PGRID, 1024, ATTN_SMEM>>>(
                x, idx, tok_emb, pos_emb,
                ln1_g + l * 64, ln1_b + l * 64,
                wq + (long)l * 4096, wk + (long)l * 4096, wv + (long)l * 4096,
                wo + (long)l * 4096, bo + l * 64);
        }
        if (l < NLAYER - 1) {
            ffn_p<0><<<PGRID, 1024, FFN_SMEM>>>(
                x, ln2_g + l * 64, ln2_b + l * 64,
                w1 + (long)l * 64 * 256, b1 + l * 256,
                w2 + (long)l * 256 * 64, b2 + l * 64,
                lnf_g, lnf_b, lm_w, lm_b, targets, logits, tl);
        } else {
            ffn_p<2><<<PGRID, 1024, FFN2_SMEM>>>(
                x, ln2_g + l * 64, ln2_b + l * 64,
                w1 + (long)l * 64 * 256, b1 + l * 256,
                w2 + (long)l * 256 * 64, b2 + l * 64,
                lnf_g, lnf_b, lm_w, lm_b, targets, logits, tl);
        }
    }
    reduce1_kernel<<<512, 256>>>(tl, part);
    reduce2_kernel<<<1, 512>>>(part, lossp);
}